// round 2
// baseline (speedup 1.0000x reference)
#include <cuda_runtime.h>
#include <math.h>

// ------------------ scratch (__device__ globals; no allocation) ------------------
__device__ float g_a1[4096 * 256 * 64];     // conv1 out NHWC [B,16x16,64]
__device__ float g_a2[4096 * 64 * 128];     // conv2 out NHWC [B,8x8,128]
__device__ float g_fea[4096 * 16 * 256];    // conv3 out NHWC rows (VQ input)
__device__ float g_wt[16 * 256 * 512];      // fc1_w rearranged [pos][c][n]
__device__ float g_P[16 * 1024 * 512];      // P[pos][code][n]
__device__ float g_h[4096 * 512];           // fc1+gelu output
__device__ int   g_eidx[65536];
__device__ float g_cn[1024];
__device__ int   g_hist[1024];
__device__ float g_losspart[256];

__device__ __forceinline__ float gelu_t(float x) {
    float x3 = x * x * x;
    float t = tanhf(0.7978845608028654f * (x + 0.044715f * x3));
    return 0.5f * x * (1.0f + t);
}

// ---------- conv1: x[4096,3,32,32] -> a1 NHWC, stride2 pad1 + ReLU ----------
__global__ __launch_bounds__(256) void conv1_k(const float* __restrict__ x,
                                               const float* __restrict__ w,
                                               const float* __restrict__ bias) {
    __shared__ float sw1[27][64];
    __shared__ float sb1[64];
    int tid = threadIdx.x, b = blockIdx.x;
    for (int i = tid; i < 1728; i += 256) { int co = i & 63, t = i >> 6; sw1[t][co] = w[co * 27 + t]; }
    if (tid < 64) sb1[tid] = bias[tid];
    __syncthreads();
    int oh = tid >> 4, ow = tid & 15;
    const float* xb = x + (size_t)b * 3072;
    float in[27];
#pragma unroll
    for (int c = 0; c < 3; c++)
#pragma unroll
        for (int kh = 0; kh < 3; kh++)
#pragma unroll
            for (int kw = 0; kw < 3; kw++) {
                int ih = oh * 2 + kh - 1, iw = ow * 2 + kw - 1;
                float v = 0.f;
                if ((unsigned)ih < 32u && (unsigned)iw < 32u) v = xb[(c * 32 + ih) * 32 + iw];
                in[(c * 3 + kh) * 3 + kw] = v;
            }
    float* ob = g_a1 + ((size_t)b * 256 + tid) * 64;
    for (int cq = 0; cq < 16; cq++) {
        float a0 = sb1[cq * 4], a1 = sb1[cq * 4 + 1], a2 = sb1[cq * 4 + 2], a3 = sb1[cq * 4 + 3];
#pragma unroll
        for (int t = 0; t < 27; t++) {
            float4 wv = *(float4*)&sw1[t][cq * 4];
            a0 = fmaf(in[t], wv.x, a0); a1 = fmaf(in[t], wv.y, a1);
            a2 = fmaf(in[t], wv.z, a2); a3 = fmaf(in[t], wv.w, a3);
        }
        float4 o; o.x = fmaxf(a0, 0.f); o.y = fmaxf(a1, 0.f); o.z = fmaxf(a2, 0.f); o.w = fmaxf(a3, 0.f);
        *(float4*)&ob[cq * 4] = o;
    }
}

// ---------- conv2: a1 -> a2 NHWC [B,8x8,128]; 2 images/block ----------
__global__ __launch_bounds__(256) void conv2_k(const float* __restrict__ w,
                                               const float* __restrict__ bias) {
    __shared__ float sin2[2312];      // [img][17][17][4ci]
    __shared__ float sw2[36][128];
    int tid = threadIdx.x;
    int b0 = blockIdx.x * 2;
    int cog = tid & 31, ipg = tid >> 5;
    float acc[16][4];
#pragma unroll
    for (int i = 0; i < 16; i++)
#pragma unroll
        for (int j = 0; j < 4; j++) acc[i][j] = 0.f;

    for (int cc = 0; cc < 16; cc++) {
        int cib = cc * 4;
        __syncthreads();
        for (int i = tid; i < 578; i += 256) {
            int img = i / 289, rr = i % 289;
            int r = rr / 17, c = rr % 17;
            int ih = r - 1, iw = c - 1;
            float4 v = make_float4(0.f, 0.f, 0.f, 0.f);
            if ((unsigned)ih < 16u && (unsigned)iw < 16u)
                v = *(const float4*)&g_a1[(((size_t)(b0 + img) * 256) + ih * 16 + iw) * 64 + cib];
            *(float4*)&sin2[((img * 17 + r) * 17 + c) * 4] = v;
        }
        {
            int co = tid & 127, hh = tid >> 7;
            const float* wp = w + (size_t)co * 576 + cib * 9;
#pragma unroll
            for (int t = 0; t < 18; t++) { int kk = hh * 18 + t; sw2[kk][co] = wp[kk]; }
        }
        __syncthreads();
#pragma unroll
        for (int ciL = 0; ciL < 4; ciL++)
#pragma unroll
            for (int kh = 0; kh < 3; kh++)
#pragma unroll
                for (int kw = 0; kw < 3; kw++) {
                    float4 wv = *(float4*)&sw2[ciL * 9 + kh * 3 + kw][cog * 4];
#pragma unroll
                    for (int i2 = 0; i2 < 16; i2++) {
                        int ip = ipg + 8 * i2;
                        int img = ip >> 6, pos = ip & 63;
                        int oh = pos >> 3, ow2 = pos & 7;
                        float iv = sin2[((img * 17 + (oh * 2 + kh)) * 17 + (ow2 * 2 + kw)) * 4 + ciL];
                        acc[i2][0] = fmaf(iv, wv.x, acc[i2][0]);
                        acc[i2][1] = fmaf(iv, wv.y, acc[i2][1]);
                        acc[i2][2] = fmaf(iv, wv.z, acc[i2][2]);
                        acc[i2][3] = fmaf(iv, wv.w, acc[i2][3]);
                    }
                }
    }
    float b4[4];
#pragma unroll
    for (int j = 0; j < 4; j++) b4[j] = bias[cog * 4 + j];
#pragma unroll
    for (int i2 = 0; i2 < 16; i2++) {
        int ip = ipg + 8 * i2; int img = ip >> 6, pos = ip & 63;
        float4 o;
        o.x = fmaxf(acc[i2][0] + b4[0], 0.f);
        o.y = fmaxf(acc[i2][1] + b4[1], 0.f);
        o.z = fmaxf(acc[i2][2] + b4[2], 0.f);
        o.w = fmaxf(acc[i2][3] + b4[3], 0.f);
        *(float4*)&g_a2[(((size_t)(b0 + img) * 64) + pos) * 128 + cog * 4] = o;
    }
}

// ---------- conv3: a2 -> fea NHWC [B,16,256]; 16 images, 64 co per block ----------
__global__ __launch_bounds__(256) void conv3_k(const float* __restrict__ w,
                                               const float* __restrict__ bias) {
    __shared__ float sin3[5184];      // [img16][9][9][4ci]
    __shared__ float sw3[36][64];
    int tid = threadIdx.x;
    int b0 = blockIdx.x * 16;
    int cob = blockIdx.y * 64;
    int cog = tid & 15, ipg = tid >> 4;
    float acc[16][4];
#pragma unroll
    for (int i = 0; i < 16; i++)
#pragma unroll
        for (int j = 0; j < 4; j++) acc[i][j] = 0.f;

    for (int cc = 0; cc < 32; cc++) {
        int cib = cc * 4;
        __syncthreads();
        for (int i = tid; i < 1296; i += 256) {
            int img = i / 81, rr = i % 81;
            int r = rr / 9, c = rr % 9;
            int ih = r - 1, iw = c - 1;
            float4 v = make_float4(0.f, 0.f, 0.f, 0.f);
            if ((unsigned)ih < 8u && (unsigned)iw < 8u)
                v = *(const float4*)&g_a2[(((size_t)(b0 + img) * 64) + ih * 8 + iw) * 128 + cib];
            *(float4*)&sin3[((img * 9 + r) * 9 + c) * 4] = v;
        }
        {
            int co = tid & 63, hh = tid >> 6;
            const float* wp = w + (size_t)(cob + co) * 1152 + cib * 9;
#pragma unroll
            for (int t = 0; t < 9; t++) { int kk = hh * 9 + t; sw3[kk][co] = wp[kk]; }
        }
        __syncthreads();
#pragma unroll
        for (int ciL = 0; ciL < 4; ciL++)
#pragma unroll
            for (int kh = 0; kh < 3; kh++)
#pragma unroll
                for (int kw = 0; kw < 3; kw++) {
                    float4 wv = *(float4*)&sw3[ciL * 9 + kh * 3 + kw][cog * 4];
#pragma unroll
                    for (int i2 = 0; i2 < 16; i2++) {
                        int ip = ipg + 16 * i2;
                        int img = ip >> 4, pos = ip & 15;
                        int oh = pos >> 2, ow2 = pos & 3;
                        float iv = sin3[((img * 9 + (oh * 2 + kh)) * 9 + (ow2 * 2 + kw)) * 4 + ciL];
                        acc[i2][0] = fmaf(iv, wv.x, acc[i2][0]);
                        acc[i2][1] = fmaf(iv, wv.y, acc[i2][1]);
                        acc[i2][2] = fmaf(iv, wv.z, acc[i2][2]);
                        acc[i2][3] = fmaf(iv, wv.w, acc[i2][3]);
                    }
                }
    }
    float b4[4];
#pragma unroll
    for (int j = 0; j < 4; j++) b4[j] = bias[cob + cog * 4 + j];
#pragma unroll
    for (int i2 = 0; i2 < 16; i2++) {
        int ip = ipg + 16 * i2; int img = ip >> 4, pos = ip & 15;
        float4 o;
        o.x = fmaxf(acc[i2][0] + b4[0], 0.f);
        o.y = fmaxf(acc[i2][1] + b4[1], 0.f);
        o.z = fmaxf(acc[i2][2] + b4[2], 0.f);
        o.w = fmaxf(acc[i2][3] + b4[3], 0.f);
        *(float4*)&g_fea[(((size_t)(b0 + img) * 16) + pos) * 256 + cob + cog * 4] = o;
    }
}

// ---------- code norms ----------
__global__ void codenorm_k(const float* __restrict__ c0, const float* __restrict__ c1) {
    int c = blockIdx.x * 256 + threadIdx.x;
    const float* cp = (c < 512) ? c0 + (size_t)c * 256 : c1 + (size_t)(c - 512) * 256;
    float s = 0.f;
    for (int k = 0; k < 256; k += 4) {
        float4 v = *(const float4*)&cp[k];
        s += v.x * v.x + v.y * v.y + v.z * v.z + v.w * v.w;
    }
    g_cn[c] = s;
}

// ---------- VQ argmin: 64 rows/block, 128-code tiles, 32-k chunks ----------
__global__ __launch_bounds__(256) void vq_k(const float* __restrict__ c0,
                                            const float* __restrict__ c1,
                                            const int* __restrict__ idxp) {
    __shared__ float srow[64][33];
    __shared__ float scode[128][33];
    __shared__ float sbv[64][33];
    __shared__ int   sbi[64][33];
    int tid = threadIdx.x;
    int rowbase = blockIdx.x * 64;
    int rowg = tid & 7;      // owns rows rowg + 8*i
    int codeg = tid >> 3;    // owns codes codeg*4 + j within tile
    int Kc = (idxp[0] == 0) ? 512 : 1024;
    int ntiles = Kc >> 7;
    float bv[8]; int bi[8];
#pragma unroll
    for (int i = 0; i < 8; i++) { bv[i] = 1e30f; bi[i] = 0; }

    for (int t = 0; t < ntiles; t++) {
        float acc[8][4];
#pragma unroll
        for (int i = 0; i < 8; i++)
#pragma unroll
            for (int j = 0; j < 4; j++) acc[i][j] = 0.f;
        for (int kc = 0; kc < 8; kc++) {
            __syncthreads();
            for (int i = tid; i < 2048; i += 256) {
                int r = i >> 5, k = i & 31;
                srow[r][k] = g_fea[(size_t)(rowbase + r) * 256 + kc * 32 + k];
            }
            for (int i = tid; i < 4096; i += 256) {
                int cl = i >> 5, k = i & 31;
                int c = t * 128 + cl;
                const float* cp = (c < 512) ? c0 + (size_t)c * 256 : c1 + (size_t)(c - 512) * 256;
                scode[cl][k] = cp[kc * 32 + k];
            }
            __syncthreads();
#pragma unroll 4
            for (int k = 0; k < 32; k++) {
                float a[8], cv[4];
#pragma unroll
                for (int i = 0; i < 8; i++) a[i] = srow[rowg + 8 * i][k];
#pragma unroll
                for (int j = 0; j < 4; j++) cv[j] = scode[codeg * 4 + j][k];
#pragma unroll
                for (int i = 0; i < 8; i++)
#pragma unroll
                    for (int j = 0; j < 4; j++) acc[i][j] = fmaf(a[i], cv[j], acc[i][j]);
            }
        }
#pragma unroll
        for (int j = 0; j < 4; j++) {
            int c = t * 128 + codeg * 4 + j;
            float cn = g_cn[c];
#pragma unroll
            for (int i = 0; i < 8; i++) {
                float d = cn - 2.f * acc[i][j];
                if (d < bv[i]) { bv[i] = d; bi[i] = c; }
            }
        }
    }
    __syncthreads();
#pragma unroll
    for (int i = 0; i < 8; i++) { sbv[rowg + 8 * i][codeg] = bv[i]; sbi[rowg + 8 * i][codeg] = bi[i]; }
    __syncthreads();
    if (tid < 64) {
        float v = sbv[tid][0]; int ii = sbi[tid][0];
        for (int q = 1; q < 32; q++) {
            float v2 = sbv[tid][q]; int i2 = sbi[tid][q];
            if (v2 < v || (v2 == v && i2 < ii)) { v = v2; ii = i2; }
        }
        g_eidx[rowbase + tid] = ii;
    }
}

__global__ void zero_hist_k() { g_hist[threadIdx.x] = 0; }

// ---------- loss partials + histogram ----------
__global__ void loss_hist_k(const float* __restrict__ c0, const float* __restrict__ c1) {
    __shared__ float red[256];
    int row = blockIdx.x * 256 + threadIdx.x;
    int e = g_eidx[row];
    atomicAdd(&g_hist[e], 1);
    const float* cp = (e < 512) ? c0 + (size_t)e * 256 : c1 + (size_t)(e - 512) * 256;
    const float* f = g_fea + (size_t)row * 256;
    float s = 0.f;
    for (int k = 0; k < 256; k += 4) {
        float4 q = *(const float4*)&cp[k];
        float4 fv = *(const float4*)&f[k];
        float a = q.x - fv.x, b = q.y - fv.y, c = q.z - fv.z, d = q.w - fv.w;
        s += a * a + b * b + c * c + d * d;
    }
    red[threadIdx.x] = s;
    __syncthreads();
    for (int st = 128; st; st >>= 1) {
        if (threadIdx.x < st) red[threadIdx.x] += red[threadIdx.x + st];
        __syncthreads();
    }
    if (threadIdx.x == 0) g_losspart[blockIdx.x] = red[0];
}

// ---------- rearrange fc1_w -> g_wt[pos][c][n] ----------
__global__ void wt_k(const float* __restrict__ w) {
    int pc = blockIdx.x;                 // 4096 = 16 pos * 256 c
    int pos = pc >> 8, c = pc & 255;
    int n = threadIdx.x;                 // 512
    g_wt[((size_t)pos * 256 + c) * 512 + n] = w[(size_t)n * 4096 + c * 16 + pos];
}

// ---------- P[pos] = codes @ wt[pos] : [1024,256]x[256,512] ----------
__global__ __launch_bounds__(256) void ptab_k(const float* __restrict__ c0,
                                              const float* __restrict__ c1) {
    __shared__ float sA[16][68];
    __shared__ float sB[16][68];
    int tid = threadIdx.x;
    int cb = blockIdx.x * 64, nb = blockIdx.y * 64, pos = blockIdx.z;
    int tx = tid & 15, ty = tid >> 4;
    float acc[4][4];
#pragma unroll
    for (int i = 0; i < 4; i++)
#pragma unroll
        for (int j = 0; j < 4; j++) acc[i][j] = 0.f;
    for (int kt = 0; kt < 16; kt++) {
        __syncthreads();
        for (int i = tid; i < 1024; i += 256) {
            int c = i >> 4, k = i & 15;
            int cg = cb + c;
            const float* cp = (cg < 512) ? c0 + (size_t)cg * 256 : c1 + (size_t)(cg - 512) * 256;
            sA[k][c] = cp[kt * 16 + k];
        }
        for (int i = tid; i < 1024; i += 256) {
            int k = i >> 6, n = i & 63;
            sB[k][n] = g_wt[((size_t)pos * 256 + kt * 16 + k) * 512 + nb + n];
        }
        __syncthreads();
#pragma unroll
        for (int kk = 0; kk < 16; kk++) {
            float a4[4], b4[4];
            *(float4*)a4 = *(float4*)&sA[kk][ty * 4];
            *(float4*)b4 = *(float4*)&sB[kk][tx * 4];
#pragma unroll
            for (int i = 0; i < 4; i++)
#pragma unroll
                for (int j = 0; j < 4; j++) acc[i][j] = fmaf(a4[i], b4[j], acc[i][j]);
        }
    }
#pragma unroll
    for (int i = 0; i < 4; i++) {
        float4 o = make_float4(acc[i][0], acc[i][1], acc[i][2], acc[i][3]);
        *(float4*)&g_P[((size_t)pos * 1024 + cb + ty * 4 + i) * 512 + nb + tx * 4] = o;
    }
}

// ---------- h[b,n] = gelu(sum_pos P[pos][e][n] + b1[n]) ----------
__global__ __launch_bounds__(512) void hgs_k(const float* __restrict__ fb) {
    __shared__ int se[16];
    int b = blockIdx.x, tid = threadIdx.x;
    if (tid < 16) se[tid] = g_eidx[b * 16 + tid];
    __syncthreads();
    float acc = fb[tid];
#pragma unroll
    for (int p = 0; p < 16; p++) acc += g_P[((size_t)p * 1024 + se[p]) * 512 + tid];
    g_h[(size_t)b * 512 + tid] = gelu_t(acc);
}

// ---------- fc2: out[b,m] = h[b]·fc2_w[m] + b2[m] ----------
__global__ __launch_bounds__(256) void fc2_k(const float* __restrict__ w,
                                             const float* __restrict__ bias,
                                             float* __restrict__ out) {
    __shared__ float sw[10][512];
    __shared__ float sb[10];
    int tid = threadIdx.x;
    for (int i = tid; i < 5120; i += 256) sw[i >> 9][i & 511] = w[i];
    if (tid < 10) sb[tid] = bias[tid];
    __syncthreads();
    int warp = tid >> 5, lane = tid & 31;
    int bimg = blockIdx.x * 8 + warp;
    const float* hr = g_h + (size_t)bimg * 512;
    float acc[10];
#pragma unroll
    for (int m = 0; m < 10; m++) acc[m] = 0.f;
    for (int k = 0; k < 16; k++) {
        float hv = hr[lane + 32 * k];
#pragma unroll
        for (int m = 0; m < 10; m++) acc[m] = fmaf(hv, sw[m][lane + 32 * k], acc[m]);
    }
#pragma unroll
    for (int off = 16; off; off >>= 1)
#pragma unroll
        for (int m = 0; m < 10; m++) acc[m] += __shfl_xor_sync(0xFFFFFFFFu, acc[m], off);
    if (lane < 10) out[(size_t)bimg * 10 + lane] = acc[lane] + sb[lane];
}

// ---------- loss + perplexity ----------
__global__ void losspp_k(float* __restrict__ dout, int osz) {
    __shared__ float red[256];
    int tid = threadIdx.x;
    red[tid] = g_losspart[tid];
    __syncthreads();
    for (int st = 128; st; st >>= 1) {
        if (tid < st) red[tid] += red[tid + st];
        __syncthreads();
    }
    float loss = 1.25f * red[0] / 16777216.0f;
    __syncthreads();
    float s = 0.f;
    for (int i = tid; i < 1024; i += 256) {
        float p = (float)g_hist[i] / 65536.0f;
        if (p > 0.f) s += p * logf(p + 1e-10f);
    }
    red[tid] = s;
    __syncthreads();
    for (int st = 128; st; st >>= 1) {
        if (tid < st) red[tid] += red[tid + st];
        __syncthreads();
    }
    if (tid == 0) { dout[osz - 2] = loss; dout[osz - 1] = expf(-red[0]); }
}

extern "C" void kernel_launch(void* const* d_in, const int* in_sizes, int n_in,
                              void* d_out, int out_size) {
    const float* x     = (const float*)d_in[0];
    const float* w1    = (const float*)d_in[1];
    const float* b1    = (const float*)d_in[2];
    const float* w2    = (const float*)d_in[3];
    const float* b2    = (const float*)d_in[4];
    const float* w3    = (const float*)d_in[5];
    const float* b3    = (const float*)d_in[6];
    const float* code0 = (const float*)d_in[7];
    const float* code1 = (const float*)d_in[8];
    const float* fc1w  = (const float*)d_in[9];
    const float* fc1b  = (const float*)d_in[10];
    const float* fc2w  = (const float*)d_in[11];
    const float* fc2b  = (const float*)d_in[12];
    const int*   idxp  = (const int*)d_in[13];
    float* out = (float*)d_out;

    conv1_k<<<4096, 256>>>(x, w1, b1);
    conv2_k<<<2048, 256>>>(w2, b2);
    conv3_k<<<dim3(256, 4), 256>>>(w3, b3);
    codenorm_k<<<4, 256>>>(code0, code1);
    vq_k<<<1024, 256>>>(code0, code1, idxp);
    zero_hist_k<<<1, 1024>>>();
    loss_hist_k<<<256, 256>>>(code0, code1);
    wt_k<<<4096, 512>>>(fc1w);
    ptab_k<<<dim3(16, 8, 16), 256>>>(code0, code1);
    hgs_k<<<4096, 512>>>(fc1b);
    fc2_k<<<512, 256>>>(fc2w, fc2b, out);
    losspp_k<<<1, 256>>>(out, out_size);
}

// round 3
// speedup vs baseline: 2.2981x; 2.2981x over previous
#include <cuda_runtime.h>
#include <math.h>

// ------------------ scratch (__device__ globals; no allocation) ------------------
__device__ float g_a1[4096 * 256 * 64];     // conv1 out NHWC [B,16x16,64]
__device__ float g_a2[4096 * 64 * 128];     // conv2 out NHWC [B,8x8,128]
__device__ float g_fea[4096 * 16 * 256];    // conv3 out NHWC rows (VQ input)
__device__ float g_wt[16 * 256 * 512];      // fc1_w rearranged [pos][c][n]
__device__ float g_P[16 * 1024 * 512];      // P[pos][code][n]
__device__ float g_h[4096 * 512];           // fc1+gelu output
__device__ int   g_eidx[65536];
__device__ float g_cn[1024];
__device__ int   g_hist[1024];
__device__ float g_losspart[256];

__device__ __forceinline__ float gelu_t(float x) {
    float x3 = x * x * x;
    float t = tanhf(0.7978845608028654f * (x + 0.044715f * x3));
    return 0.5f * x * (1.0f + t);
}

// ---------- conv1: x[4096,3,32,32] -> a1 NHWC, stride2 pad1 + ReLU ----------
__global__ __launch_bounds__(256) void conv1_k(const float* __restrict__ x,
                                               const float* __restrict__ w,
                                               const float* __restrict__ bias) {
    __shared__ float sw1[27][64];
    __shared__ float sb1[64];
    int tid = threadIdx.x, b = blockIdx.x;
    for (int i = tid; i < 1728; i += 256) { int co = i & 63, t = i >> 6; sw1[t][co] = w[co * 27 + t]; }
    if (tid < 64) sb1[tid] = bias[tid];
    __syncthreads();
    int oh = tid >> 4, ow = tid & 15;
    const float* xb = x + (size_t)b * 3072;
    float in[27];
#pragma unroll
    for (int c = 0; c < 3; c++)
#pragma unroll
        for (int kh = 0; kh < 3; kh++)
#pragma unroll
            for (int kw = 0; kw < 3; kw++) {
                int ih = oh * 2 + kh - 1, iw = ow * 2 + kw - 1;
                float v = 0.f;
                if ((unsigned)ih < 32u && (unsigned)iw < 32u) v = xb[(c * 32 + ih) * 32 + iw];
                in[(c * 3 + kh) * 3 + kw] = v;
            }
    float* ob = g_a1 + ((size_t)b * 256 + tid) * 64;
#pragma unroll
    for (int cq = 0; cq < 16; cq++) {
        float a0 = sb1[cq * 4], a1 = sb1[cq * 4 + 1], a2 = sb1[cq * 4 + 2], a3 = sb1[cq * 4 + 3];
#pragma unroll
        for (int t = 0; t < 27; t++) {
            float4 wv = *(float4*)&sw1[t][cq * 4];
            a0 = fmaf(in[t], wv.x, a0); a1 = fmaf(in[t], wv.y, a1);
            a2 = fmaf(in[t], wv.z, a2); a3 = fmaf(in[t], wv.w, a3);
        }
        float4 o; o.x = fmaxf(a0, 0.f); o.y = fmaxf(a1, 0.f); o.z = fmaxf(a2, 0.f); o.w = fmaxf(a3, 0.f);
        *(float4*)&ob[cq * 4] = o;
    }
}

// ---------- conv2: a1 -> a2 NHWC [B,8x8,128]; ONE image/block, acc[8][4] ----------
__global__ __launch_bounds__(256) void conv2_k(const float* __restrict__ w,
                                               const float* __restrict__ bias) {
    __shared__ float sin2[1156];      // [17][17][4ci]
    __shared__ float sw2[36][128];
    int tid = threadIdx.x;
    int b = blockIdx.x;
    int cog = tid & 31;               // lane: co = cog*4
    int ppg = tid >> 5;               // warp: positions ppg + 8*i
    float acc[8][4];
#pragma unroll
    for (int i = 0; i < 8; i++)
#pragma unroll
        for (int j = 0; j < 4; j++) acc[i][j] = 0.f;

    for (int cc = 0; cc < 16; cc++) {
        int cib = cc * 4;
        __syncthreads();
        for (int i = tid; i < 289; i += 256) {
            int r = i / 17, c = i % 17;
            int ih = r - 1, iw = c - 1;
            float4 v = make_float4(0.f, 0.f, 0.f, 0.f);
            if ((unsigned)ih < 16u && (unsigned)iw < 16u)
                v = *(const float4*)&g_a1[(((size_t)b * 256) + ih * 16 + iw) * 64 + cib];
            *(float4*)&sin2[i * 4] = v;
        }
        {
            int co = tid & 127, hh = tid >> 7;
            const float* wp = w + (size_t)co * 576 + cib * 9;
#pragma unroll
            for (int t = 0; t < 18; t++) { int kk = hh * 18 + t; sw2[kk][co] = wp[kk]; }
        }
        __syncthreads();
#pragma unroll
        for (int ciL = 0; ciL < 4; ciL++)
#pragma unroll
            for (int kh = 0; kh < 3; kh++)
#pragma unroll
                for (int kw = 0; kw < 3; kw++) {
                    float4 wv = *(float4*)&sw2[ciL * 9 + kh * 3 + kw][cog * 4];
#pragma unroll
                    for (int i = 0; i < 8; i++) {
                        int p = ppg + 8 * i;            // 0..63
                        int oh = p >> 3, ow = p & 7;
                        float iv = sin2[((oh * 2 + kh) * 17 + (ow * 2 + kw)) * 4 + ciL];
                        acc[i][0] = fmaf(iv, wv.x, acc[i][0]);
                        acc[i][1] = fmaf(iv, wv.y, acc[i][1]);
                        acc[i][2] = fmaf(iv, wv.z, acc[i][2]);
                        acc[i][3] = fmaf(iv, wv.w, acc[i][3]);
                    }
                }
    }
    float b4[4];
#pragma unroll
    for (int j = 0; j < 4; j++) b4[j] = bias[cog * 4 + j];
#pragma unroll
    for (int i = 0; i < 8; i++) {
        int p = ppg + 8 * i;
        float4 o;
        o.x = fmaxf(acc[i][0] + b4[0], 0.f);
        o.y = fmaxf(acc[i][1] + b4[1], 0.f);
        o.z = fmaxf(acc[i][2] + b4[2], 0.f);
        o.w = fmaxf(acc[i][3] + b4[3], 0.f);
        *(float4*)&g_a2[(((size_t)b * 64) + p) * 128 + cog * 4] = o;
    }
}

// ---------- conv3: a2 -> fea NHWC [B,16,256]; 8 images, 64 co per block, acc[8][4] ----------
__global__ __launch_bounds__(256) void conv3_k(const float* __restrict__ w,
                                               const float* __restrict__ bias) {
    __shared__ float sin3[2592];      // [img8][9][9][4ci]
    __shared__ float sw3[36][64];
    int tid = threadIdx.x;
    int b0 = blockIdx.x * 8;
    int cob = blockIdx.y * 64;
    int cog = tid & 15;               // co = cob + cog*4
    int ppg = tid >> 4;               // 16 groups; img-pos p = ppg + 16*i (0..127)
    float acc[8][4];
#pragma unroll
    for (int i = 0; i < 8; i++)
#pragma unroll
        for (int j = 0; j < 4; j++) acc[i][j] = 0.f;

    for (int cc = 0; cc < 32; cc++) {
        int cib = cc * 4;
        __syncthreads();
        for (int i = tid; i < 648; i += 256) {
            int img = i / 81, rr = i % 81;
            int r = rr / 9, c = rr % 9;
            int ih = r - 1, iw = c - 1;
            float4 v = make_float4(0.f, 0.f, 0.f, 0.f);
            if ((unsigned)ih < 8u && (unsigned)iw < 8u)
                v = *(const float4*)&g_a2[(((size_t)(b0 + img) * 64) + ih * 8 + iw) * 128 + cib];
            *(float4*)&sin3[i * 4] = v;
        }
        {
            int co = tid & 63, hh = tid >> 6;
            const float* wp = w + (size_t)(cob + co) * 1152 + cib * 9;
#pragma unroll
            for (int t = 0; t < 9; t++) { int kk = hh * 9 + t; sw3[kk][co] = wp[kk]; }
        }
        __syncthreads();
#pragma unroll
        for (int ciL = 0; ciL < 4; ciL++)
#pragma unroll
            for (int kh = 0; kh < 3; kh++)
#pragma unroll
                for (int kw = 0; kw < 3; kw++) {
                    float4 wv = *(float4*)&sw3[ciL * 9 + kh * 3 + kw][cog * 4];
#pragma unroll
                    for (int i = 0; i < 8; i++) {
                        int p = ppg + 16 * i;           // 0..127
                        int img = p >> 4, pos = p & 15;
                        int oh = pos >> 2, ow = pos & 3;
                        float iv = sin3[((img * 9 + (oh * 2 + kh)) * 9 + (ow * 2 + kw)) * 4 + ciL];
                        acc[i][0] = fmaf(iv, wv.x, acc[i][0]);
                        acc[i][1] = fmaf(iv, wv.y, acc[i][1]);
                        acc[i][2] = fmaf(iv, wv.z, acc[i][2]);
                        acc[i][3] = fmaf(iv, wv.w, acc[i][3]);
                    }
                }
    }
    float b4[4];
#pragma unroll
    for (int j = 0; j < 4; j++) b4[j] = bias[cob + cog * 4 + j];
#pragma unroll
    for (int i = 0; i < 8; i++) {
        int p = ppg + 16 * i;
        int img = p >> 4, pos = p & 15;
        float4 o;
        o.x = fmaxf(acc[i][0] + b4[0], 0.f);
        o.y = fmaxf(acc[i][1] + b4[1], 0.f);
        o.z = fmaxf(acc[i][2] + b4[2], 0.f);
        o.w = fmaxf(acc[i][3] + b4[3], 0.f);
        *(float4*)&g_fea[(((size_t)(b0 + img) * 16) + pos) * 256 + cob + cog * 4] = o;
    }
}

// ---------- code norms ----------
__global__ void codenorm_k(const float* __restrict__ c0, const float* __restrict__ c1) {
    int c = blockIdx.x * 256 + threadIdx.x;
    const float* cp = (c < 512) ? c0 + (size_t)c * 256 : c1 + (size_t)(c - 512) * 256;
    float s = 0.f;
    for (int k = 0; k < 256; k += 4) {
        float4 v = *(const float4*)&cp[k];
        s += v.x * v.x + v.y * v.y + v.z * v.z + v.w * v.w;
    }
    g_cn[c] = s;
}

// ---------- VQ argmin: 64 rows/block, 128-code tiles, 32-k chunks ----------
__global__ __launch_bounds__(256) void vq_k(const float* __restrict__ c0,
                                            const float* __restrict__ c1,
                                            const int* __restrict__ idxp) {
    __shared__ float srow[64][33];
    __shared__ float scode[128][33];
    __shared__ float sbv[64][33];
    __shared__ int   sbi[64][33];
    int tid = threadIdx.x;
    int rowbase = blockIdx.x * 64;
    int rowg = tid & 7;
    int codeg = tid >> 3;
    int Kc = (idxp[0] == 0) ? 512 : 1024;
    int ntiles = Kc >> 7;
    float bv[8]; int bi[8];
#pragma unroll
    for (int i = 0; i < 8; i++) { bv[i] = 1e30f; bi[i] = 0; }

    for (int t = 0; t < ntiles; t++) {
        float acc[8][4];
#pragma unroll
        for (int i = 0; i < 8; i++)
#pragma unroll
            for (int j = 0; j < 4; j++) acc[i][j] = 0.f;
        for (int kc = 0; kc < 8; kc++) {
            __syncthreads();
            for (int i = tid; i < 2048; i += 256) {
                int r = i >> 5, k = i & 31;
                srow[r][k] = g_fea[(size_t)(rowbase + r) * 256 + kc * 32 + k];
            }
            for (int i = tid; i < 4096; i += 256) {
                int cl = i >> 5, k = i & 31;
                int c = t * 128 + cl;
                const float* cp = (c < 512) ? c0 + (size_t)c * 256 : c1 + (size_t)(c - 512) * 256;
                scode[cl][k] = cp[kc * 32 + k];
            }
            __syncthreads();
#pragma unroll 4
            for (int k = 0; k < 32; k++) {
                float a[8], cv[4];
#pragma unroll
                for (int i = 0; i < 8; i++) a[i] = srow[rowg + 8 * i][k];
#pragma unroll
                for (int j = 0; j < 4; j++) cv[j] = scode[codeg * 4 + j][k];
#pragma unroll
                for (int i = 0; i < 8; i++)
#pragma unroll
                    for (int j = 0; j < 4; j++) acc[i][j] = fmaf(a[i], cv[j], acc[i][j]);
            }
        }
#pragma unroll
        for (int j = 0; j < 4; j++) {
            int c = t * 128 + codeg * 4 + j;
            float cn = g_cn[c];
#pragma unroll
            for (int i = 0; i < 8; i++) {
                float d = cn - 2.f * acc[i][j];
                if (d < bv[i]) { bv[i] = d; bi[i] = c; }
            }
        }
    }
    __syncthreads();
#pragma unroll
    for (int i = 0; i < 8; i++) { sbv[rowg + 8 * i][codeg] = bv[i]; sbi[rowg + 8 * i][codeg] = bi[i]; }
    __syncthreads();
    if (tid < 64) {
        float v = sbv[tid][0]; int ii = sbi[tid][0];
        for (int q = 1; q < 32; q++) {
            float v2 = sbv[tid][q]; int i2 = sbi[tid][q];
            if (v2 < v || (v2 == v && i2 < ii)) { v = v2; ii = i2; }
        }
        g_eidx[rowbase + tid] = ii;
    }
}

__global__ void zero_hist_k() { g_hist[threadIdx.x] = 0; }

// ---------- loss partials + histogram ----------
__global__ void loss_hist_k(const float* __restrict__ c0, const float* __restrict__ c1) {
    __shared__ float red[256];
    int row = blockIdx.x * 256 + threadIdx.x;
    int e = g_eidx[row];
    atomicAdd(&g_hist[e], 1);
    const float* cp = (e < 512) ? c0 + (size_t)e * 256 : c1 + (size_t)(e - 512) * 256;
    const float* f = g_fea + (size_t)row * 256;
    float s = 0.f;
    for (int k = 0; k < 256; k += 4) {
        float4 q = *(const float4*)&cp[k];
        float4 fv = *(const float4*)&f[k];
        float a = q.x - fv.x, b = q.y - fv.y, c = q.z - fv.z, d = q.w - fv.w;
        s += a * a + b * b + c * c + d * d;
    }
    red[threadIdx.x] = s;
    __syncthreads();
    for (int st = 128; st; st >>= 1) {
        if (threadIdx.x < st) red[threadIdx.x] += red[threadIdx.x + st];
        __syncthreads();
    }
    if (threadIdx.x == 0) g_losspart[blockIdx.x] = red[0];
}

// ---------- rearrange fc1_w -> g_wt[pos][c][n] ----------
__global__ void wt_k(const float* __restrict__ w) {
    int pc = blockIdx.x;                 // 4096 = 16 pos * 256 c
    int pos = pc >> 8, c = pc & 255;
    int n = threadIdx.x;                 // 512
    g_wt[((size_t)pos * 256 + c) * 512 + n] = w[(size_t)n * 4096 + c * 16 + pos];
}

// ---------- P[pos] = codes @ wt[pos] : [1024,256]x[256,512] ----------
__global__ __launch_bounds__(256) void ptab_k(const float* __restrict__ c0,
                                              const float* __restrict__ c1) {
    __shared__ float sA[16][68];
    __shared__ float sB[16][68];
    int tid = threadIdx.x;
    int cb = blockIdx.x * 64, nb = blockIdx.y * 64, pos = blockIdx.z;
    int tx = tid & 15, ty = tid >> 4;
    float acc[4][4];
#pragma unroll
    for (int i = 0; i < 4; i++)
#pragma unroll
        for (int j = 0; j < 4; j++) acc[i][j] = 0.f;
    for (int kt = 0; kt < 16; kt++) {
        __syncthreads();
        for (int i = tid; i < 1024; i += 256) {
            int c = i >> 4, k = i & 15;
            int cg = cb + c;
            const float* cp = (cg < 512) ? c0 + (size_t)cg * 256 : c1 + (size_t)(cg - 512) * 256;
            sA[k][c] = cp[kt * 16 + k];
        }
        for (int i = tid; i < 1024; i += 256) {
            int k = i >> 6, n = i & 63;
            sB[k][n] = g_wt[((size_t)pos * 256 + kt * 16 + k) * 512 + nb + n];
        }
        __syncthreads();
#pragma unroll
        for (int kk = 0; kk < 16; kk++) {
            float a4[4], b4[4];
            *(float4*)a4 = *(float4*)&sA[kk][ty * 4];
            *(float4*)b4 = *(float4*)&sB[kk][tx * 4];
#pragma unroll
            for (int i = 0; i < 4; i++)
#pragma unroll
                for (int j = 0; j < 4; j++) acc[i][j] = fmaf(a4[i], b4[j], acc[i][j]);
        }
    }
#pragma unroll
    for (int i = 0; i < 4; i++) {
        float4 o = make_float4(acc[i][0], acc[i][1], acc[i][2], acc[i][3]);
        *(float4*)&g_P[((size_t)pos * 1024 + cb + ty * 4 + i) * 512 + nb + tx * 4] = o;
    }
}

// ---------- h[b,n] = gelu(sum_pos P[pos][e][n] + b1[n]) ----------
__global__ __launch_bounds__(512) void hgs_k(const float* __restrict__ fb) {
    __shared__ int se[16];
    int b = blockIdx.x, tid = threadIdx.x;
    if (tid < 16) se[tid] = g_eidx[b * 16 + tid];
    __syncthreads();
    float acc = fb[tid];
#pragma unroll
    for (int p = 0; p < 16; p++) acc += g_P[((size_t)p * 1024 + se[p]) * 512 + tid];
    g_h[(size_t)b * 512 + tid] = gelu_t(acc);
}

// ---------- fc2: out[b,m] = h[b]·fc2_w[m] + b2[m] ----------
__global__ __launch_bounds__(256) void fc2_k(const float* __restrict__ w,
                                             const float* __restrict__ bias,
                                             float* __restrict__ out) {
    __shared__ float sw[10][512];
    __shared__ float sb[10];
    int tid = threadIdx.x;
    for (int i = tid; i < 5120; i += 256) sw[i >> 9][i & 511] = w[i];
    if (tid < 10) sb[tid] = bias[tid];
    __syncthreads();
    int warp = tid >> 5, lane = tid & 31;
    int bimg = blockIdx.x * 8 + warp;
    const float* hr = g_h + (size_t)bimg * 512;
    float acc[10];
#pragma unroll
    for (int m = 0; m < 10; m++) acc[m] = 0.f;
    for (int k = 0; k < 16; k++) {
        float hv = hr[lane + 32 * k];
#pragma unroll
        for (int m = 0; m < 10; m++) acc[m] = fmaf(hv, sw[m][lane + 32 * k], acc[m]);
    }
#pragma unroll
    for (int off = 16; off; off >>= 1)
#pragma unroll
        for (int m = 0; m < 10; m++) acc[m] += __shfl_xor_sync(0xFFFFFFFFu, acc[m], off);
    if (lane < 10) out[(size_t)bimg * 10 + lane] = acc[lane] + sb[lane];
}

// ---------- loss + perplexity ----------
__global__ void losspp_k(float* __restrict__ dout, int osz) {
    __shared__ float red[256];
    int tid = threadIdx.x;
    red[tid] = g_losspart[tid];
    __syncthreads();
    for (int st = 128; st; st >>= 1) {
        if (tid < st) red[tid] += red[tid + st];
        __syncthreads();
    }
    float loss = 1.25f * red[0] / 16777216.0f;
    __syncthreads();
    float s = 0.f;
    for (int i = tid; i < 1024; i += 256) {
        float p = (float)g_hist[i] / 65536.0f;
        if (p > 0.f) s += p * logf(p + 1e-10f);
    }
    red[tid] = s;
    __syncthreads();
    for (int st = 128; st; st >>= 1) {
        if (tid < st) red[tid] += red[tid + st];
        __syncthreads();
    }
    if (tid == 0) { dout[osz - 2] = loss; dout[osz - 1] = expf(-red[0]); }
}

extern "C" void kernel_launch(void* const* d_in, const int* in_sizes, int n_in,
                              void* d_out, int out_size) {
    const float* x     = (const float*)d_in[0];
    const float* w1    = (const float*)d_in[1];
    const float* b1    = (const float*)d_in[2];
    const float* w2    = (const float*)d_in[3];
    const float* b2    = (const float*)d_in[4];
    const float* w3    = (const float*)d_in[5];
    const float* b3    = (const float*)d_in[6];
    const float* code0 = (const float*)d_in[7];
    const float* code1 = (const float*)d_in[8];
    const float* fc1w  = (const float*)d_in[9];
    const float* fc1b  = (const float*)d_in[10];
    const float* fc2w  = (const float*)d_in[11];
    const float* fc2b  = (const float*)d_in[12];
    const int*   idxp  = (const int*)d_in[13];
    float* out = (float*)d_out;

    // Order chosen so conv2_k is our launch #3 (expected to land at ncu -s 5).
    codenorm_k<<<4, 256>>>(code0, code1);                 // 0
    conv1_k<<<4096, 256>>>(x, w1, b1);                    // 1
    wt_k<<<4096, 512>>>(fc1w);                            // 2
    conv2_k<<<4096, 256>>>(w2, b2);                       // 3  <-- profile target
    conv3_k<<<dim3(512, 4), 256>>>(w3, b3);               // 4
    vq_k<<<1024, 256>>>(code0, code1, idxp);              // 5
    zero_hist_k<<<1, 1024>>>();                           // 6
    loss_hist_k<<<256, 256>>>(code0, code1);              // 7
    ptab_k<<<dim3(16, 8, 16), 256>>>(code0, code1);       // 8
    hgs_k<<<4096, 512>>>(fc1b);                           // 9
    fc2_k<<<512, 256>>>(fc2w, fc2b, out);                 // 10
    losspp_k<<<1, 256>>>(out, out_size);                  // 11
}

// round 4
// speedup vs baseline: 9.9093x; 4.3119x over previous
#include <cuda_runtime.h>
#include <math.h>

// ------------------ scratch (__device__ globals; no allocation) ------------------
__device__ float g_a1[4096 * 256 * 64];     // conv1 out NHWC [B,16x16,64]
__device__ float g_a2[4096 * 64 * 128];     // conv2 out NHWC [B,8x8,128]
__device__ float g_fea[4096 * 16 * 256];    // conv3 out NHWC rows (VQ input)
__device__ float g_wt[16 * 256 * 512];      // fc1_w rearranged [pos][c][n]
__device__ float g_P[16 * 1024 * 512];      // P[pos][code][n]
__device__ float g_h[4096 * 512];           // fc1+gelu output
__device__ int   g_eidx[65536];
__device__ float g_cn[1024];
__device__ int   g_hist[1024];
__device__ float g_losspart[256];

__device__ __forceinline__ float gelu_t(float x) {
    float x3 = x * x * x;
    float t = tanhf(0.7978845608028654f * (x + 0.044715f * x3));
    return 0.5f * x * (1.0f + t);
}

// ---------- conv1: x[4096,3,32,32] -> a1 NHWC, stride2 pad1 + ReLU ----------
__global__ __launch_bounds__(256) void conv1_k(const float* __restrict__ x,
                                               const float* __restrict__ w,
                                               const float* __restrict__ bias) {
    __shared__ float sw1[27][64];
    __shared__ float sb1[64];
    int tid = threadIdx.x, b = blockIdx.x;
    for (int i = tid; i < 1728; i += 256) { int co = i & 63, t = i >> 6; sw1[t][co] = w[co * 27 + t]; }
    if (tid < 64) sb1[tid] = bias[tid];
    __syncthreads();
    int oh = tid >> 4, ow = tid & 15;
    const float* xb = x + (size_t)b * 3072;
    float in[27];
#pragma unroll
    for (int c = 0; c < 3; c++)
#pragma unroll
        for (int kh = 0; kh < 3; kh++)
#pragma unroll
            for (int kw = 0; kw < 3; kw++) {
                int ih = oh * 2 + kh - 1, iw = ow * 2 + kw - 1;
                float v = 0.f;
                if ((unsigned)ih < 32u && (unsigned)iw < 32u) v = xb[(c * 32 + ih) * 32 + iw];
                in[(c * 3 + kh) * 3 + kw] = v;
            }
    float* ob = g_a1 + ((size_t)b * 256 + tid) * 64;
#pragma unroll
    for (int cq = 0; cq < 16; cq++) {
        float a0 = sb1[cq * 4], a1 = sb1[cq * 4 + 1], a2 = sb1[cq * 4 + 2], a3 = sb1[cq * 4 + 3];
#pragma unroll
        for (int t = 0; t < 27; t++) {
            float4 wv = *(float4*)&sw1[t][cq * 4];
            a0 = fmaf(in[t], wv.x, a0); a1 = fmaf(in[t], wv.y, a1);
            a2 = fmaf(in[t], wv.z, a2); a3 = fmaf(in[t], wv.w, a3);
        }
        float4 o; o.x = fmaxf(a0, 0.f); o.y = fmaxf(a1, 0.f); o.z = fmaxf(a2, 0.f); o.w = fmaxf(a3, 0.f);
        *(float4*)&ob[cq * 4] = o;
    }
}

// ---------- conv2: GEMM-style. Per image: C[64pos,128co] = A[64,576] x W[576,128] ----------
// Per cc-chunk (4 ci): stage input halo, build im2col sA[36][64], weights sw2[36][128].
// Thread tile: 4 pos x 8 co. Per k: 3x LDS.128 -> 32 FMA.
__global__ __launch_bounds__(256, 2) void conv2_k(const float* __restrict__ w,
                                                  const float* __restrict__ bias) {
    __shared__ float sin2[1156];      // [17][17][4ci]
    __shared__ float sA[36][64];      // k=(ciL*9+kh*3+kw), pos
    __shared__ float sw2[36][128];
    int tid = threadIdx.x;
    int b = blockIdx.x;
    int px = tid & 15;                // pos block: pos4 = px*4
    int cy = tid >> 4;                // co block:  co8 = cy*8
    float acc[4][8];
#pragma unroll
    for (int i = 0; i < 4; i++)
#pragma unroll
        for (int j = 0; j < 8; j++) acc[i][j] = 0.f;

    for (int cc = 0; cc < 16; cc++) {
        int cib = cc * 4;
        __syncthreads();
        // stage halo tile (coalesced float4) + weights
        for (int i = tid; i < 289; i += 256) {
            int r = i / 17, c = i % 17;
            int ih = r - 1, iw = c - 1;
            float4 v = make_float4(0.f, 0.f, 0.f, 0.f);
            if ((unsigned)ih < 16u && (unsigned)iw < 16u)
                v = *(const float4*)&g_a1[(((size_t)b * 256) + ih * 16 + iw) * 64 + cib];
            *(float4*)&sin2[i * 4] = v;
        }
        {
            int co = tid & 127, hh = tid >> 7;
            const float* wp = w + (size_t)co * 576 + cib * 9;
#pragma unroll
            for (int t = 0; t < 18; t++) { int kk = hh * 18 + t; sw2[kk][co] = wp[kk]; }
        }
        __syncthreads();
        // build im2col A (2304 entries, 9 per thread)
#pragma unroll
        for (int i = 0; i < 9; i++) {
            int idx = tid + 256 * i;
            int k = idx >> 6, pos = idx & 63;
            int ciL = k / 9, t = k - ciL * 9;
            int kh = t / 3, kw = t - kh * 3;
            int oh = pos >> 3, ow = pos & 7;
            sA[k][pos] = sin2[((oh * 2 + kh) * 17 + (ow * 2 + kw)) * 4 + ciL];
        }
        __syncthreads();
        // GEMM microkernel
#pragma unroll 4
        for (int k = 0; k < 36; k++) {
            float4 a = *(float4*)&sA[k][px * 4];
            float4 w0 = *(float4*)&sw2[k][cy * 8];
            float4 w1 = *(float4*)&sw2[k][cy * 8 + 4];
            float av[4] = {a.x, a.y, a.z, a.w};
            float bv[8] = {w0.x, w0.y, w0.z, w0.w, w1.x, w1.y, w1.z, w1.w};
#pragma unroll
            for (int i = 0; i < 4; i++)
#pragma unroll
                for (int j = 0; j < 8; j++) acc[i][j] = fmaf(av[i], bv[j], acc[i][j]);
        }
    }
    float bb[8];
    *(float4*)&bb[0] = *(const float4*)&bias[cy * 8];
    *(float4*)&bb[4] = *(const float4*)&bias[cy * 8 + 4];
#pragma unroll
    for (int i = 0; i < 4; i++) {
        int pos = px * 4 + i;
        float4 o0, o1;
        o0.x = fmaxf(acc[i][0] + bb[0], 0.f); o0.y = fmaxf(acc[i][1] + bb[1], 0.f);
        o0.z = fmaxf(acc[i][2] + bb[2], 0.f); o0.w = fmaxf(acc[i][3] + bb[3], 0.f);
        o1.x = fmaxf(acc[i][4] + bb[4], 0.f); o1.y = fmaxf(acc[i][5] + bb[5], 0.f);
        o1.z = fmaxf(acc[i][6] + bb[6], 0.f); o1.w = fmaxf(acc[i][7] + bb[7], 0.f);
        float* op = &g_a2[(((size_t)b * 64) + pos) * 128 + cy * 8];
        *(float4*)&op[0] = o0;
        *(float4*)&op[4] = o1;
    }
}

// ---------- conv3: GEMM-style. 8 images x 64 co per block: C[128col,64co] ----------
__global__ __launch_bounds__(256, 2) void conv3_k(const float* __restrict__ w,
                                                  const float* __restrict__ bias) {
    __shared__ float sin3[2592];      // [img8][9][9][4ci]
    __shared__ float sA[36][128];     // k, col=img*16+pos
    __shared__ float sw3[36][64];
    int tid = threadIdx.x;
    int b0 = blockIdx.x * 8;
    int cob = blockIdx.y * 64;
    int px = tid & 31;                // col4 = px*4
    int cy = tid >> 5;                // co8 = cy*8
    float acc[4][8];
#pragma unroll
    for (int i = 0; i < 4; i++)
#pragma unroll
        for (int j = 0; j < 8; j++) acc[i][j] = 0.f;

    for (int cc = 0; cc < 32; cc++) {
        int cib = cc * 4;
        __syncthreads();
        for (int i = tid; i < 648; i += 256) {
            int img = i / 81, rr = i % 81;
            int r = rr / 9, c = rr % 9;
            int ih = r - 1, iw = c - 1;
            float4 v = make_float4(0.f, 0.f, 0.f, 0.f);
            if ((unsigned)ih < 8u && (unsigned)iw < 8u)
                v = *(const float4*)&g_a2[(((size_t)(b0 + img) * 64) + ih * 8 + iw) * 128 + cib];
            *(float4*)&sin3[i * 4] = v;
        }
        {
            int co = tid & 63, hh = tid >> 6;
            const float* wp = w + (size_t)(cob + co) * 1152 + cib * 9;
#pragma unroll
            for (int t = 0; t < 9; t++) { int kk = hh * 9 + t; sw3[kk][co] = wp[kk]; }
        }
        __syncthreads();
#pragma unroll
        for (int i = 0; i < 18; i++) {
            int idx = tid + 256 * i;
            int k = idx >> 7, col = idx & 127;
            int ciL = k / 9, t = k - ciL * 9;
            int kh = t / 3, kw = t - kh * 3;
            int img = col >> 4, pos = col & 15;
            int oh = pos >> 2, ow = pos & 3;
            sA[k][col] = sin3[((img * 9 + (oh * 2 + kh)) * 9 + (ow * 2 + kw)) * 4 + ciL];
        }
        __syncthreads();
#pragma unroll 4
        for (int k = 0; k < 36; k++) {
            float4 a = *(float4*)&sA[k][px * 4];
            float4 w0 = *(float4*)&sw3[k][cy * 8];
            float4 w1 = *(float4*)&sw3[k][cy * 8 + 4];
            float av[4] = {a.x, a.y, a.z, a.w};
            float bv[8] = {w0.x, w0.y, w0.z, w0.w, w1.x, w1.y, w1.z, w1.w};
#pragma unroll
            for (int i = 0; i < 4; i++)
#pragma unroll
                for (int j = 0; j < 8; j++) acc[i][j] = fmaf(av[i], bv[j], acc[i][j]);
        }
    }
    float bb[8];
    *(float4*)&bb[0] = *(const float4*)&bias[cob + cy * 8];
    *(float4*)&bb[4] = *(const float4*)&bias[cob + cy * 8 + 4];
#pragma unroll
    for (int i = 0; i < 4; i++) {
        int col = px * 4 + i;
        int img = col >> 4, pos = col & 15;
        float4 o0, o1;
        o0.x = fmaxf(acc[i][0] + bb[0], 0.f); o0.y = fmaxf(acc[i][1] + bb[1], 0.f);
        o0.z = fmaxf(acc[i][2] + bb[2], 0.f); o0.w = fmaxf(acc[i][3] + bb[3], 0.f);
        o1.x = fmaxf(acc[i][4] + bb[4], 0.f); o1.y = fmaxf(acc[i][5] + bb[5], 0.f);
        o1.z = fmaxf(acc[i][6] + bb[6], 0.f); o1.w = fmaxf(acc[i][7] + bb[7], 0.f);
        float* op = &g_fea[(((size_t)(b0 + img) * 16) + pos) * 256 + cob + cy * 8];
        *(float4*)&op[0] = o0;
        *(float4*)&op[4] = o1;
    }
}

// ---------- code norms ----------
__global__ void codenorm_k(const float* __restrict__ c0, const float* __restrict__ c1) {
    int c = blockIdx.x * 256 + threadIdx.x;
    const float* cp = (c < 512) ? c0 + (size_t)c * 256 : c1 + (size_t)(c - 512) * 256;
    float s = 0.f;
    for (int k = 0; k < 256; k += 4) {
        float4 v = *(const float4*)&cp[k];
        s += v.x * v.x + v.y * v.y + v.z * v.z + v.w * v.w;
    }
    g_cn[c] = s;
}

// ---------- VQ: GEMM-style. 64 rows x 128-code tiles; thread = 4 rows x 8 codes ----------
__global__ __launch_bounds__(256, 2) void vq_k(const float* __restrict__ c0,
                                               const float* __restrict__ c1,
                                               const int* __restrict__ idxp) {
    __shared__ float sF[32][64];      // k-major rows
    __shared__ float sC[32][128];     // k-major codes
    __shared__ float sbv[64][17];
    __shared__ int   sbi[64][17];
    int tid = threadIdx.x;
    int rowbase = blockIdx.x * 64;
    int rx = tid & 15;                // rows r4 = rx*4
    int cy = tid >> 4;                // codes c8 = cy*8
    int Kc = (idxp[0] == 0) ? 512 : 1024;
    int ntiles = Kc >> 7;
    float bv[4]; int bi[4];
#pragma unroll
    for (int i = 0; i < 4; i++) { bv[i] = 1e30f; bi[i] = 0; }

    for (int t = 0; t < ntiles; t++) {
        float acc[4][8];
#pragma unroll
        for (int i = 0; i < 4; i++)
#pragma unroll
            for (int j = 0; j < 8; j++) acc[i][j] = 0.f;
        for (int kc = 0; kc < 8; kc++) {
            __syncthreads();
#pragma unroll
            for (int i = 0; i < 2; i++) {               // sF: 512 float4 reads
                int idx = tid + 256 * i;
                int r = idx & 63, kq = idx >> 6;
                float4 v = *(const float4*)&g_fea[(size_t)(rowbase + r) * 256 + kc * 32 + kq * 4];
                sF[kq * 4 + 0][r] = v.x; sF[kq * 4 + 1][r] = v.y;
                sF[kq * 4 + 2][r] = v.z; sF[kq * 4 + 3][r] = v.w;
            }
#pragma unroll
            for (int i = 0; i < 4; i++) {               // sC: 1024 float4 reads
                int idx = tid + 256 * i;
                int c = idx & 127, kq = idx >> 7;
                int cg = t * 128 + c;
                const float* cp = (cg < 512) ? c0 + (size_t)cg * 256 : c1 + (size_t)(cg - 512) * 256;
                float4 v = *(const float4*)&cp[kc * 32 + kq * 4];
                sC[kq * 4 + 0][c] = v.x; sC[kq * 4 + 1][c] = v.y;
                sC[kq * 4 + 2][c] = v.z; sC[kq * 4 + 3][c] = v.w;
            }
            __syncthreads();
#pragma unroll 4
            for (int k = 0; k < 32; k++) {
                float4 a = *(float4*)&sF[k][rx * 4];
                float4 b0 = *(float4*)&sC[k][cy * 8];
                float4 b1 = *(float4*)&sC[k][cy * 8 + 4];
                float av[4] = {a.x, a.y, a.z, a.w};
                float cv[8] = {b0.x, b0.y, b0.z, b0.w, b1.x, b1.y, b1.z, b1.w};
#pragma unroll
                for (int i = 0; i < 4; i++)
#pragma unroll
                    for (int j = 0; j < 8; j++) acc[i][j] = fmaf(av[i], cv[j], acc[i][j]);
            }
        }
#pragma unroll
        for (int j = 0; j < 8; j++) {
            int c = t * 128 + cy * 8 + j;
            float cn = g_cn[c];
#pragma unroll
            for (int i = 0; i < 4; i++) {
                float d = cn - 2.f * acc[i][j];
                if (d < bv[i]) { bv[i] = d; bi[i] = c; }
            }
        }
    }
    __syncthreads();
#pragma unroll
    for (int i = 0; i < 4; i++) { sbv[rx * 4 + i][cy] = bv[i]; sbi[rx * 4 + i][cy] = bi[i]; }
    __syncthreads();
    if (tid < 64) {
        float v = sbv[tid][0]; int ii = sbi[tid][0];
#pragma unroll
        for (int q = 1; q < 16; q++) {
            float v2 = sbv[tid][q]; int i2 = sbi[tid][q];
            if (v2 < v || (v2 == v && i2 < ii)) { v = v2; ii = i2; }
        }
        g_eidx[rowbase + tid] = ii;
    }
}

__global__ void zero_hist_k() { g_hist[threadIdx.x] = 0; }

// ---------- loss partials + histogram ----------
__global__ void loss_hist_k(const float* __restrict__ c0, const float* __restrict__ c1) {
    __shared__ float red[256];
    int row = blockIdx.x * 256 + threadIdx.x;
    int e = g_eidx[row];
    atomicAdd(&g_hist[e], 1);
    const float* cp = (e < 512) ? c0 + (size_t)e * 256 : c1 + (size_t)(e - 512) * 256;
    const float* f = g_fea + (size_t)row * 256;
    float s = 0.f;
    for (int k = 0; k < 256; k += 4) {
        float4 q = *(const float4*)&cp[k];
        float4 fv = *(const float4*)&f[k];
        float a = q.x - fv.x, b = q.y - fv.y, c = q.z - fv.z, d = q.w - fv.w;
        s += a * a + b * b + c * c + d * d;
    }
    red[threadIdx.x] = s;
    __syncthreads();
    for (int st = 128; st; st >>= 1) {
        if (threadIdx.x < st) red[threadIdx.x] += red[threadIdx.x + st];
        __syncthreads();
    }
    if (threadIdx.x == 0) g_losspart[blockIdx.x] = red[0];
}

// ---------- rearrange fc1_w -> g_wt[pos][c][n] ----------
__global__ void wt_k(const float* __restrict__ w) {
    int pc = blockIdx.x;                 // 4096 = 16 pos * 256 c
    int pos = pc >> 8, c = pc & 255;
    int n = threadIdx.x;                 // 512
    g_wt[((size_t)pos * 256 + c) * 512 + n] = w[(size_t)n * 4096 + c * 16 + pos];
}

// ---------- P[pos] = codes @ wt[pos] : [1024,256]x[256,512] ----------
__global__ __launch_bounds__(256) void ptab_k(const float* __restrict__ c0,
                                              const float* __restrict__ c1) {
    __shared__ float sA[16][68];
    __shared__ float sB[16][68];
    int tid = threadIdx.x;
    int cb = blockIdx.x * 64, nb = blockIdx.y * 64, pos = blockIdx.z;
    int tx = tid & 15, ty = tid >> 4;
    float acc[4][4];
#pragma unroll
    for (int i = 0; i < 4; i++)
#pragma unroll
        for (int j = 0; j < 4; j++) acc[i][j] = 0.f;
    for (int kt = 0; kt < 16; kt++) {
        __syncthreads();
        for (int i = tid; i < 1024; i += 256) {
            int c = i >> 4, k = i & 15;
            int cg = cb + c;
            const float* cp = (cg < 512) ? c0 + (size_t)cg * 256 : c1 + (size_t)(cg - 512) * 256;
            sA[k][c] = cp[kt * 16 + k];
        }
        for (int i = tid; i < 1024; i += 256) {
            int k = i >> 6, n = i & 63;
            sB[k][n] = g_wt[((size_t)pos * 256 + kt * 16 + k) * 512 + nb + n];
        }
        __syncthreads();
#pragma unroll
        for (int kk = 0; kk < 16; kk++) {
            float a4[4], b4[4];
            *(float4*)a4 = *(float4*)&sA[kk][ty * 4];
            *(float4*)b4 = *(float4*)&sB[kk][tx * 4];
#pragma unroll
            for (int i = 0; i < 4; i++)
#pragma unroll
                for (int j = 0; j < 4; j++) acc[i][j] = fmaf(a4[i], b4[j], acc[i][j]);
        }
    }
#pragma unroll
    for (int i = 0; i < 4; i++) {
        float4 o = make_float4(acc[i][0], acc[i][1], acc[i][2], acc[i][3]);
        *(float4*)&g_P[((size_t)pos * 1024 + cb + ty * 4 + i) * 512 + nb + tx * 4] = o;
    }
}

// ---------- h[b,n] = gelu(sum_pos P[pos][e][n] + b1[n]) ----------
__global__ __launch_bounds__(512) void hgs_k(const float* __restrict__ fb) {
    __shared__ int se[16];
    int b = blockIdx.x, tid = threadIdx.x;
    if (tid < 16) se[tid] = g_eidx[b * 16 + tid];
    __syncthreads();
    float acc = fb[tid];
#pragma unroll
    for (int p = 0; p < 16; p++) acc += g_P[((size_t)p * 1024 + se[p]) * 512 + tid];
    g_h[(size_t)b * 512 + tid] = gelu_t(acc);
}

// ---------- fc2: out[b,m] = h[b]·fc2_w[m] + b2[m] ----------
__global__ __launch_bounds__(256) void fc2_k(const float* __restrict__ w,
                                             const float* __restrict__ bias,
                                             float* __restrict__ out) {
    __shared__ float sw[10][512];
    __shared__ float sb[10];
    int tid = threadIdx.x;
    for (int i = tid; i < 5120; i += 256) sw[i >> 9][i & 511] = w[i];
    if (tid < 10) sb[tid] = bias[tid];
    __syncthreads();
    int warp = tid >> 5, lane = tid & 31;
    int bimg = blockIdx.x * 8 + warp;
    const float* hr = g_h + (size_t)bimg * 512;
    float acc[10];
#pragma unroll
    for (int m = 0; m < 10; m++) acc[m] = 0.f;
    for (int k = 0; k < 16; k++) {
        float hv = hr[lane + 32 * k];
#pragma unroll
        for (int m = 0; m < 10; m++) acc[m] = fmaf(hv, sw[m][lane + 32 * k], acc[m]);
    }
#pragma unroll
    for (int off = 16; off; off >>= 1)
#pragma unroll
        for (int m = 0; m < 10; m++) acc[m] += __shfl_xor_sync(0xFFFFFFFFu, acc[m], off);
    if (lane < 10) out[(size_t)bimg * 10 + lane] = acc[lane] + sb[lane];
}

// ---------- loss + perplexity ----------
__global__ void losspp_k(float* __restrict__ dout, int osz) {
    __shared__ float red[256];
    int tid = threadIdx.x;
    red[tid] = g_losspart[tid];
    __syncthreads();
    for (int st = 128; st; st >>= 1) {
        if (tid < st) red[tid] += red[tid + st];
        __syncthreads();
    }
    float loss = 1.25f * red[0] / 16777216.0f;
    __syncthreads();
    float s = 0.f;
    for (int i = tid; i < 1024; i += 256) {
        float p = (float)g_hist[i] / 65536.0f;
        if (p > 0.f) s += p * logf(p + 1e-10f);
    }
    red[tid] = s;
    __syncthreads();
    for (int st = 128; st; st >>= 1) {
        if (tid < st) red[tid] += red[tid + st];
        __syncthreads();
    }
    if (tid == 0) { dout[osz - 2] = loss; dout[osz - 1] = expf(-red[0]); }
}

extern "C" void kernel_launch(void* const* d_in, const int* in_sizes, int n_in,
                              void* d_out, int out_size) {
    const float* x     = (const float*)d_in[0];
    const float* w1    = (const float*)d_in[1];
    const float* b1    = (const float*)d_in[2];
    const float* w2    = (const float*)d_in[3];
    const float* b2    = (const float*)d_in[4];
    const float* w3    = (const float*)d_in[5];
    const float* b3    = (const float*)d_in[6];
    const float* code0 = (const float*)d_in[7];
    const float* code1 = (const float*)d_in[8];
    const float* fc1w  = (const float*)d_in[9];
    const float* fc1b  = (const float*)d_in[10];
    const float* fc2w  = (const float*)d_in[11];
    const float* fc2b  = (const float*)d_in[12];
    const int*   idxp  = (const int*)d_in[13];
    float* out = (float*)d_out;

    // Order keeps conv2_k at our launch #3 (ncu -s 5 lands there after 2 harness launches).
    codenorm_k<<<4, 256>>>(code0, code1);                 // 0
    conv1_k<<<4096, 256>>>(x, w1, b1);                    // 1
    wt_k<<<4096, 512>>>(fc1w);                            // 2
    conv2_k<<<4096, 256>>>(w2, b2);                       // 3  <-- profile target
    conv3_k<<<dim3(512, 4), 256>>>(w3, b3);               // 4
    vq_k<<<1024, 256>>>(code0, code1, idxp);              // 5
    zero_hist_k<<<1, 1024>>>();                           // 6
    loss_hist_k<<<256, 256>>>(code0, code1);              // 7
    ptab_k<<<dim3(16, 8, 16), 256>>>(code0, code1);       // 8
    hgs_k<<<4096, 512>>>(fc1b);                           // 9
    fc2_k<<<512, 256>>>(fc2w, fc2b, out);                 // 10
    losspp_k<<<1, 256>>>(out, out_size);                  // 11
}

// round 5
// speedup vs baseline: 11.4885x; 1.1594x over previous
#include <cuda_runtime.h>
#include <math.h>

typedef unsigned long long u64;

// ------------------ scratch (__device__ globals; no allocation) ------------------
__device__ float g_a1[4096 * 256 * 64];     // conv1 out NHWC [B,16x16,64]
__device__ float g_a2[4096 * 64 * 128];     // conv2 out NHWC [B,8x8,128]
__device__ float g_fea[4096 * 16 * 256];    // conv3 out NHWC rows (VQ input)
__device__ float g_wt[16 * 256 * 512];      // fc1_w rearranged [pos][c][n]
__device__ float g_P[16 * 1024 * 512];      // P[pos][code][n]
__device__ float g_h[4096 * 512];           // fc1+gelu output
__device__ int   g_eidx[65536];
__device__ float g_cn[1024];
__device__ int   g_hist[1024];
__device__ float g_losspart[256];

__device__ __forceinline__ float gelu_t(float x) {
    float x3 = x * x * x;
    float t = tanhf(0.7978845608028654f * (x + 0.044715f * x3));
    return 0.5f * x * (1.0f + t);
}

// ---- packed f32x2 helpers (FFMA2: 2 fp32 FMA per instruction) ----
__device__ __forceinline__ u64 pk2(float lo, float hi) {
    u64 r; asm("mov.b64 %0, {%1, %2};" : "=l"(r) : "f"(lo), "f"(hi)); return r;
}
__device__ __forceinline__ void ffma2(u64& d, u64 a, u64 b) {
    asm("fma.rn.f32x2 %0, %1, %2, %0;" : "+l"(d) : "l"(a), "l"(b));
}
__device__ __forceinline__ float2 upk(u64 v) {
    float2 r; asm("mov.b64 {%0, %1}, %2;" : "=f"(r.x), "=f"(r.y) : "l"(v)); return r;
}

// ---------- conv1: x[4096,3,32,32] -> a1 NHWC, stride2 pad1 + ReLU ----------
__global__ __launch_bounds__(256) void conv1_k(const float* __restrict__ x,
                                               const float* __restrict__ w,
                                               const float* __restrict__ bias) {
    __shared__ float sw1[27][64];
    __shared__ float sb1[64];
    int tid = threadIdx.x, b = blockIdx.x;
    for (int i = tid; i < 1728; i += 256) { int co = i & 63, t = i >> 6; sw1[t][co] = w[co * 27 + t]; }
    if (tid < 64) sb1[tid] = bias[tid];
    __syncthreads();
    int oh = tid >> 4, ow = tid & 15;
    const float* xb = x + (size_t)b * 3072;
    float in[27];
#pragma unroll
    for (int c = 0; c < 3; c++)
#pragma unroll
        for (int kh = 0; kh < 3; kh++)
#pragma unroll
            for (int kw = 0; kw < 3; kw++) {
                int ih = oh * 2 + kh - 1, iw = ow * 2 + kw - 1;
                float v = 0.f;
                if ((unsigned)ih < 32u && (unsigned)iw < 32u) v = xb[(c * 32 + ih) * 32 + iw];
                in[(c * 3 + kh) * 3 + kw] = v;
            }
    float* ob = g_a1 + ((size_t)b * 256 + tid) * 64;
#pragma unroll
    for (int cq = 0; cq < 16; cq++) {
        float a0 = sb1[cq * 4], a1 = sb1[cq * 4 + 1], a2 = sb1[cq * 4 + 2], a3 = sb1[cq * 4 + 3];
#pragma unroll
        for (int t = 0; t < 27; t++) {
            float4 wv = *(float4*)&sw1[t][cq * 4];
            a0 = fmaf(in[t], wv.x, a0); a1 = fmaf(in[t], wv.y, a1);
            a2 = fmaf(in[t], wv.z, a2); a3 = fmaf(in[t], wv.w, a3);
        }
        float4 o; o.x = fmaxf(a0, 0.f); o.y = fmaxf(a1, 0.f); o.z = fmaxf(a2, 0.f); o.w = fmaxf(a3, 0.f);
        *(float4*)&ob[cq * 4] = o;
    }
}

// ---------- conv2: 2 images/block, C[128col,128co], 8x8 thread tile, FFMA2 ----------
__global__ __launch_bounds__(256, 2) void conv2_k(const float* __restrict__ w,
                                                  const float* __restrict__ bias) {
    __shared__ float sin2[2 * 1156];   // [img][17][17][4ci]
    __shared__ float sA[36][128];      // k, col=img*64+pos
    __shared__ float sw2[36][128];
    int tid = threadIdx.x;
    int b0 = blockIdx.x * 2;
    int px = tid & 15;                 // cols px*8..px*8+7
    int cy = tid >> 4;                 // cos  cy*8..cy*8+7
    u64 acc[4][8];
#pragma unroll
    for (int i = 0; i < 4; i++)
#pragma unroll
        for (int j = 0; j < 8; j++) acc[i][j] = 0ull;

    for (int cc = 0; cc < 16; cc++) {
        int cib = cc * 4;
        __syncthreads();
        for (int i = tid; i < 578; i += 256) {
            int img = i / 289, rr = i % 289;
            int r = rr / 17, c = rr % 17;
            int ih = r - 1, iw = c - 1;
            float4 v = make_float4(0.f, 0.f, 0.f, 0.f);
            if ((unsigned)ih < 16u && (unsigned)iw < 16u)
                v = *(const float4*)&g_a1[(((size_t)(b0 + img) * 256) + ih * 16 + iw) * 64 + cib];
            *(float4*)&sin2[i * 4] = v;
        }
        {
            int co = tid & 127, hh = tid >> 7;
            const float* wp = w + (size_t)co * 576 + cib * 9;
#pragma unroll
            for (int t = 0; t < 18; t++) { int kk = hh * 18 + t; sw2[kk][co] = wp[kk]; }
        }
        __syncthreads();
#pragma unroll
        for (int i = 0; i < 18; i++) {
            int idx = tid + 256 * i;
            int k = idx >> 7, col = idx & 127;
            int img = col >> 6, pos = col & 63;
            int ciL = k / 9, t = k - ciL * 9;
            int kh = t / 3, kw = t - kh * 3;
            int oh = pos >> 3, ow = pos & 7;
            sA[k][col] = sin2[((img * 17 + (oh * 2 + kh)) * 17 + (ow * 2 + kw)) * 4 + ciL];
        }
        __syncthreads();
#pragma unroll 6
        for (int k = 0; k < 36; k++) {
            float4 a0 = *(float4*)&sA[k][px * 8];
            float4 a1 = *(float4*)&sA[k][px * 8 + 4];
            float4 w0 = *(float4*)&sw2[k][cy * 8];
            float4 w1 = *(float4*)&sw2[k][cy * 8 + 4];
            u64 ap[4] = {pk2(a0.x, a0.y), pk2(a0.z, a0.w), pk2(a1.x, a1.y), pk2(a1.z, a1.w)};
            u64 bd[8] = {pk2(w0.x, w0.x), pk2(w0.y, w0.y), pk2(w0.z, w0.z), pk2(w0.w, w0.w),
                         pk2(w1.x, w1.x), pk2(w1.y, w1.y), pk2(w1.z, w1.z), pk2(w1.w, w1.w)};
#pragma unroll
            for (int ip = 0; ip < 4; ip++)
#pragma unroll
                for (int j = 0; j < 8; j++) ffma2(acc[ip][j], ap[ip], bd[j]);
        }
    }
    float bb[8];
    *(float4*)&bb[0] = *(const float4*)&bias[cy * 8];
    *(float4*)&bb[4] = *(const float4*)&bias[cy * 8 + 4];
#pragma unroll
    for (int ip = 0; ip < 4; ip++) {
        float2 v[8];
#pragma unroll
        for (int j = 0; j < 8; j++) v[j] = upk(acc[ip][j]);
        int col0 = px * 8 + 2 * ip;
#pragma unroll
        for (int e = 0; e < 2; e++) {
            int col = col0 + e;
            int img = col >> 6, pos = col & 63;
            float4 o0, o1;
            o0.x = fmaxf((e ? v[0].y : v[0].x) + bb[0], 0.f);
            o0.y = fmaxf((e ? v[1].y : v[1].x) + bb[1], 0.f);
            o0.z = fmaxf((e ? v[2].y : v[2].x) + bb[2], 0.f);
            o0.w = fmaxf((e ? v[3].y : v[3].x) + bb[3], 0.f);
            o1.x = fmaxf((e ? v[4].y : v[4].x) + bb[4], 0.f);
            o1.y = fmaxf((e ? v[5].y : v[5].x) + bb[5], 0.f);
            o1.z = fmaxf((e ? v[6].y : v[6].x) + bb[6], 0.f);
            o1.w = fmaxf((e ? v[7].y : v[7].x) + bb[7], 0.f);
            float* op = &g_a2[(((size_t)(b0 + img) * 64) + pos) * 128 + cy * 8];
            *(float4*)&op[0] = o0;
            *(float4*)&op[4] = o1;
        }
    }
}

// ---------- conv3: 8 images x 128 co per block, C[128col,128co], FFMA2 ----------
__global__ __launch_bounds__(256, 2) void conv3_k(const float* __restrict__ w,
                                                  const float* __restrict__ bias) {
    __shared__ float sin3[2592];       // [img8][9][9][4ci]
    __shared__ float sA[36][128];      // k, col=img*16+pos
    __shared__ float sw3[36][128];
    int tid = threadIdx.x;
    int b0 = blockIdx.x * 8;
    int cob = blockIdx.y * 128;
    int px = tid & 15;
    int cy = tid >> 4;
    u64 acc[4][8];
#pragma unroll
    for (int i = 0; i < 4; i++)
#pragma unroll
        for (int j = 0; j < 8; j++) acc[i][j] = 0ull;

    for (int cc = 0; cc < 32; cc++) {
        int cib = cc * 4;
        __syncthreads();
        for (int i = tid; i < 648; i += 256) {
            int img = i / 81, rr = i % 81;
            int r = rr / 9, c = rr % 9;
            int ih = r - 1, iw = c - 1;
            float4 v = make_float4(0.f, 0.f, 0.f, 0.f);
            if ((unsigned)ih < 8u && (unsigned)iw < 8u)
                v = *(const float4*)&g_a2[(((size_t)(b0 + img) * 64) + ih * 8 + iw) * 128 + cib];
            *(float4*)&sin3[i * 4] = v;
        }
        {
            int co = tid & 127, hh = tid >> 7;
            const float* wp = w + (size_t)(cob + co) * 1152 + cib * 9;
#pragma unroll
            for (int t = 0; t < 18; t++) { int kk = hh * 18 + t; sw3[kk][co] = wp[kk]; }
        }
        __syncthreads();
#pragma unroll
        for (int i = 0; i < 18; i++) {
            int idx = tid + 256 * i;
            int k = idx >> 7, col = idx & 127;
            int img = col >> 4, pos = col & 15;
            int ciL = k / 9, t = k - ciL * 9;
            int kh = t / 3, kw = t - kh * 3;
            int oh = pos >> 2, ow = pos & 3;
            sA[k][col] = sin3[((img * 9 + (oh * 2 + kh)) * 9 + (ow * 2 + kw)) * 4 + ciL];
        }
        __syncthreads();
#pragma unroll 6
        for (int k = 0; k < 36; k++) {
            float4 a0 = *(float4*)&sA[k][px * 8];
            float4 a1 = *(float4*)&sA[k][px * 8 + 4];
            float4 w0 = *(float4*)&sw3[k][cy * 8];
            float4 w1 = *(float4*)&sw3[k][cy * 8 + 4];
            u64 ap[4] = {pk2(a0.x, a0.y), pk2(a0.z, a0.w), pk2(a1.x, a1.y), pk2(a1.z, a1.w)};
            u64 bd[8] = {pk2(w0.x, w0.x), pk2(w0.y, w0.y), pk2(w0.z, w0.z), pk2(w0.w, w0.w),
                         pk2(w1.x, w1.x), pk2(w1.y, w1.y), pk2(w1.z, w1.z), pk2(w1.w, w1.w)};
#pragma unroll
            for (int ip = 0; ip < 4; ip++)
#pragma unroll
                for (int j = 0; j < 8; j++) ffma2(acc[ip][j], ap[ip], bd[j]);
        }
    }
    float bb[8];
    *(float4*)&bb[0] = *(const float4*)&bias[cob + cy * 8];
    *(float4*)&bb[4] = *(const float4*)&bias[cob + cy * 8 + 4];
#pragma unroll
    for (int ip = 0; ip < 4; ip++) {
        float2 v[8];
#pragma unroll
        for (int j = 0; j < 8; j++) v[j] = upk(acc[ip][j]);
        int col0 = px * 8 + 2 * ip;
#pragma unroll
        for (int e = 0; e < 2; e++) {
            int col = col0 + e;
            int img = col >> 4, pos = col & 15;
            float4 o0, o1;
            o0.x = fmaxf((e ? v[0].y : v[0].x) + bb[0], 0.f);
            o0.y = fmaxf((e ? v[1].y : v[1].x) + bb[1], 0.f);
            o0.z = fmaxf((e ? v[2].y : v[2].x) + bb[2], 0.f);
            o0.w = fmaxf((e ? v[3].y : v[3].x) + bb[3], 0.f);
            o1.x = fmaxf((e ? v[4].y : v[4].x) + bb[4], 0.f);
            o1.y = fmaxf((e ? v[5].y : v[5].x) + bb[5], 0.f);
            o1.z = fmaxf((e ? v[6].y : v[6].x) + bb[6], 0.f);
            o1.w = fmaxf((e ? v[7].y : v[7].x) + bb[7], 0.f);
            float* op = &g_fea[(((size_t)(b0 + img) * 16) + pos) * 256 + cob + cy * 8];
            *(float4*)&op[0] = o0;
            *(float4*)&op[4] = o1;
        }
    }
}

// ---------- code norms ----------
__global__ void codenorm_k(const float* __restrict__ c0, const float* __restrict__ c1) {
    int c = blockIdx.x * 256 + threadIdx.x;
    const float* cp = (c < 512) ? c0 + (size_t)c * 256 : c1 + (size_t)(c - 512) * 256;
    float s = 0.f;
    for (int k = 0; k < 256; k += 4) {
        float4 v = *(const float4*)&cp[k];
        s += v.x * v.x + v.y * v.y + v.z * v.z + v.w * v.w;
    }
    g_cn[c] = s;
}

// ---------- VQ: 128 rows/block, 128-code tiles, 8x8 tile FFMA2 ----------
__global__ __launch_bounds__(256, 2) void vq_k(const float* __restrict__ c0,
                                               const float* __restrict__ c1,
                                               const int* __restrict__ idxp) {
    __shared__ float sF[32][128];     // k-major rows
    __shared__ float sC[32][128];     // k-major codes
    __shared__ float sbv[128][16];
    __shared__ int   sbi[128][16];
    int tid = threadIdx.x;
    int rowbase = blockIdx.x * 128;
    int px = tid & 15;                // rows px*8..+7
    int cy = tid >> 4;                // codes cy*8..+7
    int Kc = (idxp[0] == 0) ? 512 : 1024;
    int ntiles = Kc >> 7;
    float bv[8]; int bi[8];
#pragma unroll
    for (int i = 0; i < 8; i++) { bv[i] = 1e30f; bi[i] = 0; }

    for (int t = 0; t < ntiles; t++) {
        u64 acc[4][8];
#pragma unroll
        for (int i = 0; i < 4; i++)
#pragma unroll
            for (int j = 0; j < 8; j++) acc[i][j] = 0ull;
        for (int kc = 0; kc < 8; kc++) {
            __syncthreads();
#pragma unroll
            for (int i = 0; i < 4; i++) {
                int idx = tid + 256 * i;
                int r = idx & 127, kq = idx >> 7;
                float4 v = *(const float4*)&g_fea[(size_t)(rowbase + r) * 256 + kc * 32 + kq * 4];
                sF[kq * 4 + 0][r] = v.x; sF[kq * 4 + 1][r] = v.y;
                sF[kq * 4 + 2][r] = v.z; sF[kq * 4 + 3][r] = v.w;
            }
#pragma unroll
            for (int i = 0; i < 4; i++) {
                int idx = tid + 256 * i;
                int c = idx & 127, kq = idx >> 7;
                int cg = t * 128 + c;
                const float* cp = (cg < 512) ? c0 + (size_t)cg * 256 : c1 + (size_t)(cg - 512) * 256;
                float4 v = *(const float4*)&cp[kc * 32 + kq * 4];
                sC[kq * 4 + 0][c] = v.x; sC[kq * 4 + 1][c] = v.y;
                sC[kq * 4 + 2][c] = v.z; sC[kq * 4 + 3][c] = v.w;
            }
            __syncthreads();
#pragma unroll 4
            for (int k = 0; k < 32; k++) {
                float4 a0 = *(float4*)&sF[k][px * 8];
                float4 a1 = *(float4*)&sF[k][px * 8 + 4];
                float4 b0 = *(float4*)&sC[k][cy * 8];
                float4 b1 = *(float4*)&sC[k][cy * 8 + 4];
                u64 ap[4] = {pk2(a0.x, a0.y), pk2(a0.z, a0.w), pk2(a1.x, a1.y), pk2(a1.z, a1.w)};
                u64 bd[8] = {pk2(b0.x, b0.x), pk2(b0.y, b0.y), pk2(b0.z, b0.z), pk2(b0.w, b0.w),
                             pk2(b1.x, b1.x), pk2(b1.y, b1.y), pk2(b1.z, b1.z), pk2(b1.w, b1.w)};
#pragma unroll
                for (int ip = 0; ip < 4; ip++)
#pragma unroll
                    for (int j = 0; j < 8; j++) ffma2(acc[ip][j], ap[ip], bd[j]);
            }
        }
#pragma unroll
        for (int j = 0; j < 8; j++) {
            int c = t * 128 + cy * 8 + j;
            float cn = g_cn[c];
#pragma unroll
            for (int ip = 0; ip < 4; ip++) {
                float2 v = upk(acc[ip][j]);
                float d0 = cn - 2.f * v.x;
                float d1 = cn - 2.f * v.y;
                if (d0 < bv[2 * ip])     { bv[2 * ip] = d0;     bi[2 * ip] = c; }
                if (d1 < bv[2 * ip + 1]) { bv[2 * ip + 1] = d1; bi[2 * ip + 1] = c; }
            }
        }
    }
    __syncthreads();
#pragma unroll
    for (int l = 0; l < 8; l++) { sbv[px * 8 + l][cy] = bv[l]; sbi[px * 8 + l][cy] = bi[l]; }
    __syncthreads();
    if (tid < 128) {
        float v = sbv[tid][0]; int ii = sbi[tid][0];
#pragma unroll
        for (int q = 1; q < 16; q++) {
            float v2 = sbv[tid][q]; int i2 = sbi[tid][q];
            if (v2 < v || (v2 == v && i2 < ii)) { v = v2; ii = i2; }
        }
        g_eidx[rowbase + tid] = ii;
    }
}

__global__ void zero_hist_k() { g_hist[threadIdx.x] = 0; }

// ---------- loss partials + histogram ----------
__global__ void loss_hist_k(const float* __restrict__ c0, const float* __restrict__ c1) {
    __shared__ float red[256];
    int row = blockIdx.x * 256 + threadIdx.x;
    int e = g_eidx[row];
    atomicAdd(&g_hist[e], 1);
    const float* cp = (e < 512) ? c0 + (size_t)e * 256 : c1 + (size_t)(e - 512) * 256;
    const float* f = g_fea + (size_t)row * 256;
    float s = 0.f;
    for (int k = 0; k < 256; k += 4) {
        float4 q = *(const float4*)&cp[k];
        float4 fv = *(const float4*)&f[k];
        float a = q.x - fv.x, b = q.y - fv.y, c = q.z - fv.z, d = q.w - fv.w;
        s += a * a + b * b + c * c + d * d;
    }
    red[threadIdx.x] = s;
    __syncthreads();
    for (int st = 128; st; st >>= 1) {
        if (threadIdx.x < st) red[threadIdx.x] += red[threadIdx.x + st];
        __syncthreads();
    }
    if (threadIdx.x == 0) g_losspart[blockIdx.x] = red[0];
}

// ---------- rearrange fc1_w -> g_wt[pos][c][n] ----------
__global__ void wt_k(const float* __restrict__ w) {
    int pc = blockIdx.x;                 // 4096 = 16 pos * 256 c
    int pos = pc >> 8, c = pc & 255;
    int n = threadIdx.x;                 // 512
    g_wt[((size_t)pos * 256 + c) * 512 + n] = w[(size_t)n * 4096 + c * 16 + pos];
}

// ---------- P[pos] = codes @ wt[pos] : [1024,256]x[256,512] ----------
__global__ __launch_bounds__(256) void ptab_k(const float* __restrict__ c0,
                                              const float* __restrict__ c1) {
    __shared__ float sA[16][68];
    __shared__ float sB[16][68];
    int tid = threadIdx.x;
    int cb = blockIdx.x * 64, nb = blockIdx.y * 64, pos = blockIdx.z;
    int tx = tid & 15, ty = tid >> 4;
    float acc[4][4];
#pragma unroll
    for (int i = 0; i < 4; i++)
#pragma unroll
        for (int j = 0; j < 4; j++) acc[i][j] = 0.f;
    for (int kt = 0; kt < 16; kt++) {
        __syncthreads();
        for (int i = tid; i < 1024; i += 256) {
            int c = i >> 4, k = i & 15;
            int cg = cb + c;
            const float* cp = (cg < 512) ? c0 + (size_t)cg * 256 : c1 + (size_t)(cg - 512) * 256;
            sA[k][c] = cp[kt * 16 + k];
        }
        for (int i = tid; i < 1024; i += 256) {
            int k = i >> 6, n = i & 63;
            sB[k][n] = g_wt[((size_t)pos * 256 + kt * 16 + k) * 512 + nb + n];
        }
        __syncthreads();
#pragma unroll
        for (int kk = 0; kk < 16; kk++) {
            float a4[4], b4[4];
            *(float4*)a4 = *(float4*)&sA[kk][ty * 4];
            *(float4*)b4 = *(float4*)&sB[kk][tx * 4];
#pragma unroll
            for (int i = 0; i < 4; i++)
#pragma unroll
                for (int j = 0; j < 4; j++) acc[i][j] = fmaf(a4[i], b4[j], acc[i][j]);
        }
    }
#pragma unroll
    for (int i = 0; i < 4; i++) {
        float4 o = make_float4(acc[i][0], acc[i][1], acc[i][2], acc[i][3]);
        *(float4*)&g_P[((size_t)pos * 1024 + cb + ty * 4 + i) * 512 + nb + tx * 4] = o;
    }
}

// ---------- h[b,n] = gelu(sum_pos P[pos][e][n] + b1[n]) ----------
__global__ __launch_bounds__(512) void hgs_k(const float* __restrict__ fb) {
    __shared__ int se[16];
    int b = blockIdx.x, tid = threadIdx.x;
    if (tid < 16) se[tid] = g_eidx[b * 16 + tid];
    __syncthreads();
    float acc = fb[tid];
#pragma unroll
    for (int p = 0; p < 16; p++) acc += g_P[((size_t)p * 1024 + se[p]) * 512 + tid];
    g_h[(size_t)b * 512 + tid] = gelu_t(acc);
}

// ---------- fc2: out[b,m] = h[b]·fc2_w[m] + b2[m] ----------
__global__ __launch_bounds__(256) void fc2_k(const float* __restrict__ w,
                                             const float* __restrict__ bias,
                                             float* __restrict__ out) {
    __shared__ float sw[10][512];
    __shared__ float sb[10];
    int tid = threadIdx.x;
    for (int i = tid; i < 5120; i += 256) sw[i >> 9][i & 511] = w[i];
    if (tid < 10) sb[tid] = bias[tid];
    __syncthreads();
    int warp = tid >> 5, lane = tid & 31;
    int bimg = blockIdx.x * 8 + warp;
    const float* hr = g_h + (size_t)bimg * 512;
    float acc[10];
#pragma unroll
    for (int m = 0; m < 10; m++) acc[m] = 0.f;
    for (int k = 0; k < 16; k++) {
        float hv = hr[lane + 32 * k];
#pragma unroll
        for (int m = 0; m < 10; m++) acc[m] = fmaf(hv, sw[m][lane + 32 * k], acc[m]);
    }
#pragma unroll
    for (int off = 16; off; off >>= 1)
#pragma unroll
        for (int m = 0; m < 10; m++) acc[m] += __shfl_xor_sync(0xFFFFFFFFu, acc[m], off);
    if (lane < 10) out[(size_t)bimg * 10 + lane] = acc[lane] + sb[lane];
}

// ---------- loss + perplexity ----------
__global__ void losspp_k(float* __restrict__ dout, int osz) {
    __shared__ float red[256];
    int tid = threadIdx.x;
    red[tid] = g_losspart[tid];
    __syncthreads();
    for (int st = 128; st; st >>= 1) {
        if (tid < st) red[tid] += red[tid + st];
        __syncthreads();
    }
    float loss = 1.25f * red[0] / 16777216.0f;
    __syncthreads();
    float s = 0.f;
    for (int i = tid; i < 1024; i += 256) {
        float p = (float)g_hist[i] / 65536.0f;
        if (p > 0.f) s += p * logf(p + 1e-10f);
    }
    red[tid] = s;
    __syncthreads();
    for (int st = 128; st; st >>= 1) {
        if (tid < st) red[tid] += red[tid + st];
        __syncthreads();
    }
    if (tid == 0) { dout[osz - 2] = loss; dout[osz - 1] = expf(-red[0]); }
}

extern "C" void kernel_launch(void* const* d_in, const int* in_sizes, int n_in,
                              void* d_out, int out_size) {
    const float* x     = (const float*)d_in[0];
    const float* w1    = (const float*)d_in[1];
    const float* b1    = (const float*)d_in[2];
    const float* w2    = (const float*)d_in[3];
    const float* b2    = (const float*)d_in[4];
    const float* w3    = (const float*)d_in[5];
    const float* b3    = (const float*)d_in[6];
    const float* code0 = (const float*)d_in[7];
    const float* code1 = (const float*)d_in[8];
    const float* fc1w  = (const float*)d_in[9];
    const float* fc1b  = (const float*)d_in[10];
    const float* fc2w  = (const float*)d_in[11];
    const float* fc2b  = (const float*)d_in[12];
    const int*   idxp  = (const int*)d_in[13];
    float* out = (float*)d_out;

    // Order keeps conv2_k at our launch #3 (ncu -s 5 lands there after 2 harness launches).
    codenorm_k<<<4, 256>>>(code0, code1);                 // 0
    conv1_k<<<4096, 256>>>(x, w1, b1);                    // 1
    wt_k<<<4096, 512>>>(fc1w);                            // 2
    conv2_k<<<2048, 256>>>(w2, b2);                       // 3  <-- profile target
    conv3_k<<<dim3(512, 2), 256>>>(w3, b3);               // 4
    vq_k<<<512, 256>>>(code0, code1, idxp);               // 5
    zero_hist_k<<<1, 1024>>>();                           // 6
    loss_hist_k<<<256, 256>>>(code0, code1);              // 7
    ptab_k<<<dim3(16, 8, 16), 256>>>(code0, code1);       // 8
    hgs_k<<<4096, 512>>>(fc1b);                           // 9
    fc2_k<<<512, 256>>>(fc2w, fc2b, out);                 // 10
    losspp_k<<<1, 256>>>(out, out_size);                  // 11
}

// round 6
// speedup vs baseline: 15.0516x; 1.3101x over previous
#include <cuda_runtime.h>
#include <math.h>

typedef unsigned long long u64;

// ------------------ scratch (__device__ globals; no allocation) ------------------
__device__ float g_a1[4096 * 256 * 64];       // conv1 out NHWC [B,16x16,64]
__device__ float g_a2[4096 * 64 * 128];       // conv2 out NHWC [B,8x8,128]
__device__ float g_fea[4096 * 16 * 256];      // conv3 out NHWC rows (VQ input)
__device__ float g_A2[4096 * 9 * 64 * 64];    // im2col of a1 for conv2 [b][tap][pos][ci]
__device__ float g_A3[4096 * 9 * 16 * 128];   // im2col of a2 for conv3 [b][tap][pos][ci]
__device__ float g_wT2[576 * 128];            // conv2 weights k-major [tap*64+ci][co]
__device__ float g_wT3[1152 * 256];           // conv3 weights k-major [tap*128+ci][co]
__device__ float g_wt[16 * 256 * 512];        // fc1_w rearranged [pos][c][n]
__device__ float g_P[16 * 1024 * 512];        // P[pos][code][n]
__device__ float g_h[4096 * 512];             // fc1+gelu output
__device__ int   g_eidx[65536];
__device__ float g_cn[1024];
__device__ int   g_hist[1024];
__device__ float g_losspart[256];

__device__ __forceinline__ float gelu_t(float x) {
    float x3 = x * x * x;
    float t = tanhf(0.7978845608028654f * (x + 0.044715f * x3));
    return 0.5f * x * (1.0f + t);
}

// ---- packed f32x2 helpers (FFMA2: 2 fp32 FMA per instruction) ----
__device__ __forceinline__ u64 pk2(float lo, float hi) {
    u64 r; asm("mov.b64 %0, {%1, %2};" : "=l"(r) : "f"(lo), "f"(hi)); return r;
}
__device__ __forceinline__ void ffma2(u64& d, u64 a, u64 b) {
    asm("fma.rn.f32x2 %0, %1, %2, %0;" : "+l"(d) : "l"(a), "l"(b));
}
__device__ __forceinline__ float2 upk(u64 v) {
    float2 r; asm("mov.b64 {%0, %1}, %2;" : "=f"(r.x), "=f"(r.y) : "l"(v)); return r;
}

// ---------- conv1: x[4096,3,32,32] -> a1 NHWC, stride2 pad1 + ReLU ----------
__global__ __launch_bounds__(256) void conv1_k(const float* __restrict__ x,
                                               const float* __restrict__ w,
                                               const float* __restrict__ bias) {
    __shared__ float sw1[27][64];
    __shared__ float sb1[64];
    int tid = threadIdx.x, b = blockIdx.x;
    for (int i = tid; i < 1728; i += 256) { int co = i & 63, t = i >> 6; sw1[t][co] = w[co * 27 + t]; }
    if (tid < 64) sb1[tid] = bias[tid];
    __syncthreads();
    int oh = tid >> 4, ow = tid & 15;
    const float* xb = x + (size_t)b * 3072;
    float in[27];
#pragma unroll
    for (int c = 0; c < 3; c++)
#pragma unroll
        for (int kh = 0; kh < 3; kh++)
#pragma unroll
            for (int kw = 0; kw < 3; kw++) {
                int ih = oh * 2 + kh - 1, iw = ow * 2 + kw - 1;
                float v = 0.f;
                if ((unsigned)ih < 32u && (unsigned)iw < 32u) v = xb[(c * 32 + ih) * 32 + iw];
                in[(c * 3 + kh) * 3 + kw] = v;
            }
    float* ob = g_a1 + ((size_t)b * 256 + tid) * 64;
#pragma unroll
    for (int cq = 0; cq < 16; cq++) {
        float a0 = sb1[cq * 4], a1 = sb1[cq * 4 + 1], a2 = sb1[cq * 4 + 2], a3 = sb1[cq * 4 + 3];
#pragma unroll
        for (int t = 0; t < 27; t++) {
            float4 wv = *(float4*)&sw1[t][cq * 4];
            a0 = fmaf(in[t], wv.x, a0); a1 = fmaf(in[t], wv.y, a1);
            a2 = fmaf(in[t], wv.z, a2); a3 = fmaf(in[t], wv.w, a3);
        }
        float4 o; o.x = fmaxf(a0, 0.f); o.y = fmaxf(a1, 0.f); o.z = fmaxf(a2, 0.f); o.w = fmaxf(a3, 0.f);
        *(float4*)&ob[cq * 4] = o;
    }
}

// ---------- weight transposes to k-major ----------
__global__ void wt2_k(const float* __restrict__ w) {
    int k = blockIdx.x;                  // 576
    int co = threadIdx.x;                // 128
    int tap = k >> 6, ci = k & 63;
    g_wT2[k * 128 + co] = w[co * 576 + ci * 9 + tap];
}
__global__ void wt3_k(const float* __restrict__ w) {
    int k = blockIdx.x;                  // 1152
    int co = threadIdx.x;                // 256
    int tap = k / 128, ci = k % 128;
    g_wT3[k * 256 + co] = w[co * 1152 + ci * 9 + tap];
}

// ---------- im2col for conv2: a1 -> A2[b][tap9][pos64][ci64] ----------
__global__ __launch_bounds__(256) void im2col2_k() {
    int b = blockIdx.x, tid = threadIdx.x;
    const float* ab = g_a1 + (size_t)b * 256 * 64;
    float* ob = g_A2 + (size_t)b * 9 * 64 * 64;
#pragma unroll
    for (int l = 0; l < 36; l++) {
        int i = tid + 256 * l;           // < 9216 float4 slots
        int slot = i >> 4, q = i & 15;
        int tap = slot >> 6, pos = slot & 63;
        int kh = tap / 3, kw = tap - kh * 3;
        int oh = pos >> 3, ow = pos & 7;
        int ih = oh * 2 + kh - 1, iw = ow * 2 + kw - 1;
        float4 v = make_float4(0.f, 0.f, 0.f, 0.f);
        if ((unsigned)ih < 16u && (unsigned)iw < 16u)
            v = *(const float4*)&ab[(ih * 16 + iw) * 64 + q * 4];
        *(float4*)&ob[(size_t)slot * 64 + q * 4] = v;
    }
}

// ---------- im2col for conv3: a2 -> A3[b][tap9][pos16][ci128] ----------
__global__ __launch_bounds__(256) void im2col3_k() {
    int b = blockIdx.x, tid = threadIdx.x;
    const float* ab = g_a2 + (size_t)b * 64 * 128;
    float* ob = g_A3 + (size_t)b * 9 * 16 * 128;
#pragma unroll
    for (int l = 0; l < 18; l++) {
        int i = tid + 256 * l;           // < 4608 float4 slots
        int slot = i >> 5, q = i & 31;
        int tap = slot >> 4, pos = slot & 15;
        int kh = tap / 3, kw = tap - kh * 3;
        int oh = pos >> 2, ow = pos & 3;
        int ih = oh * 2 + kh - 1, iw = ow * 2 + kw - 1;
        float4 v = make_float4(0.f, 0.f, 0.f, 0.f);
        if ((unsigned)ih < 8u && (unsigned)iw < 8u)
            v = *(const float4*)&ab[(ih * 8 + iw) * 128 + q * 4];
        *(float4*)&ob[(size_t)slot * 128 + q * 4] = v;
    }
}

// ---------- conv2 GEMM: 2 images/block, C[128col,128co], K=576 ----------
__global__ __launch_bounds__(256, 2) void conv2_k(const float* __restrict__ bias) {
    __shared__ float sA[32][132];
    __shared__ float sB[32][128];
    int tid = threadIdx.x;
    int b0 = blockIdx.x * 2;
    int px = tid & 15;                 // cols px*8..+7
    int cy = tid >> 4;                 // cos  cy*8..+7
    u64 acc[4][8];
#pragma unroll
    for (int i = 0; i < 4; i++)
#pragma unroll
        for (int j = 0; j < 8; j++) acc[i][j] = 0ull;

    for (int ch = 0; ch < 18; ch++) {
        int tap = ch >> 1, ci0 = (ch & 1) * 32;
        __syncthreads();
#pragma unroll
        for (int l = 0; l < 4; l++) {                  // sA: 32k x 128col (transpose)
            int idx = tid + 256 * l;
            int q = idx & 7, c = idx >> 3;             // c 0..127
            int img = c >> 6, pos = c & 63;
            float4 v = *(const float4*)&g_A2[((((size_t)(b0 + img) * 9 + tap) * 64 + pos) * 64) + ci0 + q * 4];
            sA[q * 4 + 0][c] = v.x; sA[q * 4 + 1][c] = v.y;
            sA[q * 4 + 2][c] = v.z; sA[q * 4 + 3][c] = v.w;
        }
#pragma unroll
        for (int l = 0; l < 4; l++) {                  // sB: 32k x 128co (direct)
            int idx = tid + 256 * l;
            int k = idx >> 5, cq = idx & 31;
            *(float4*)&sB[k][cq * 4] = *(const float4*)&g_wT2[(size_t)(tap * 64 + ci0 + k) * 128 + cq * 4];
        }
        __syncthreads();
#pragma unroll 4
        for (int k = 0; k < 32; k++) {
            float4 a0 = *(float4*)&sA[k][px * 8];
            float4 a1 = *(float4*)&sA[k][px * 8 + 4];
            float4 w0 = *(float4*)&sB[k][cy * 8];
            float4 w1 = *(float4*)&sB[k][cy * 8 + 4];
            u64 ap[4] = {pk2(a0.x, a0.y), pk2(a0.z, a0.w), pk2(a1.x, a1.y), pk2(a1.z, a1.w)};
            u64 bd[8] = {pk2(w0.x, w0.x), pk2(w0.y, w0.y), pk2(w0.z, w0.z), pk2(w0.w, w0.w),
                         pk2(w1.x, w1.x), pk2(w1.y, w1.y), pk2(w1.z, w1.z), pk2(w1.w, w1.w)};
#pragma unroll
            for (int ip = 0; ip < 4; ip++)
#pragma unroll
                for (int j = 0; j < 8; j++) ffma2(acc[ip][j], ap[ip], bd[j]);
        }
    }
    float bb[8];
    *(float4*)&bb[0] = *(const float4*)&bias[cy * 8];
    *(float4*)&bb[4] = *(const float4*)&bias[cy * 8 + 4];
#pragma unroll
    for (int ip = 0; ip < 4; ip++) {
        float2 v[8];
#pragma unroll
        for (int j = 0; j < 8; j++) v[j] = upk(acc[ip][j]);
        int col0 = px * 8 + 2 * ip;
#pragma unroll
        for (int e = 0; e < 2; e++) {
            int col = col0 + e;
            int img = col >> 6, pos = col & 63;
            float4 o0, o1;
            o0.x = fmaxf((e ? v[0].y : v[0].x) + bb[0], 0.f);
            o0.y = fmaxf((e ? v[1].y : v[1].x) + bb[1], 0.f);
            o0.z = fmaxf((e ? v[2].y : v[2].x) + bb[2], 0.f);
            o0.w = fmaxf((e ? v[3].y : v[3].x) + bb[3], 0.f);
            o1.x = fmaxf((e ? v[4].y : v[4].x) + bb[4], 0.f);
            o1.y = fmaxf((e ? v[5].y : v[5].x) + bb[5], 0.f);
            o1.z = fmaxf((e ? v[6].y : v[6].x) + bb[6], 0.f);
            o1.w = fmaxf((e ? v[7].y : v[7].x) + bb[7], 0.f);
            float* op = &g_a2[(((size_t)(b0 + img) * 64) + pos) * 128 + cy * 8];
            *(float4*)&op[0] = o0;
            *(float4*)&op[4] = o1;
        }
    }
}

// ---------- conv3 GEMM: 8 images x 128 co per block, K=1152 ----------
__global__ __launch_bounds__(256, 2) void conv3_k(const float* __restrict__ bias) {
    __shared__ float sA[32][132];
    __shared__ float sB[32][128];
    int tid = threadIdx.x;
    int b0 = blockIdx.x * 8;
    int cob = blockIdx.y * 128;
    int px = tid & 15;
    int cy = tid >> 4;
    u64 acc[4][8];
#pragma unroll
    for (int i = 0; i < 4; i++)
#pragma unroll
        for (int j = 0; j < 8; j++) acc[i][j] = 0ull;

    for (int ch = 0; ch < 36; ch++) {
        int tap = ch >> 2, ci0 = (ch & 3) * 32;
        __syncthreads();
#pragma unroll
        for (int l = 0; l < 4; l++) {
            int idx = tid + 256 * l;
            int q = idx & 7, c = idx >> 3;
            int img = c >> 4, pos = c & 15;
            float4 v = *(const float4*)&g_A3[((((size_t)(b0 + img) * 9 + tap) * 16 + pos) * 128) + ci0 + q * 4];
            sA[q * 4 + 0][c] = v.x; sA[q * 4 + 1][c] = v.y;
            sA[q * 4 + 2][c] = v.z; sA[q * 4 + 3][c] = v.w;
        }
#pragma unroll
        for (int l = 0; l < 4; l++) {
            int idx = tid + 256 * l;
            int k = idx >> 5, cq = idx & 31;
            *(float4*)&sB[k][cq * 4] = *(const float4*)&g_wT3[(size_t)(tap * 128 + ci0 + k) * 256 + cob + cq * 4];
        }
        __syncthreads();
#pragma unroll 4
        for (int k = 0; k < 32; k++) {
            float4 a0 = *(float4*)&sA[k][px * 8];
            float4 a1 = *(float4*)&sA[k][px * 8 + 4];
            float4 w0 = *(float4*)&sB[k][cy * 8];
            float4 w1 = *(float4*)&sB[k][cy * 8 + 4];
            u64 ap[4] = {pk2(a0.x, a0.y), pk2(a0.z, a0.w), pk2(a1.x, a1.y), pk2(a1.z, a1.w)};
            u64 bd[8] = {pk2(w0.x, w0.x), pk2(w0.y, w0.y), pk2(w0.z, w0.z), pk2(w0.w, w0.w),
                         pk2(w1.x, w1.x), pk2(w1.y, w1.y), pk2(w1.z, w1.z), pk2(w1.w, w1.w)};
#pragma unroll
            for (int ip = 0; ip < 4; ip++)
#pragma unroll
                for (int j = 0; j < 8; j++) ffma2(acc[ip][j], ap[ip], bd[j]);
        }
    }
    float bb[8];
    *(float4*)&bb[0] = *(const float4*)&bias[cob + cy * 8];
    *(float4*)&bb[4] = *(const float4*)&bias[cob + cy * 8 + 4];
#pragma unroll
    for (int ip = 0; ip < 4; ip++) {
        float2 v[8];
#pragma unroll
        for (int j = 0; j < 8; j++) v[j] = upk(acc[ip][j]);
        int col0 = px * 8 + 2 * ip;
#pragma unroll
        for (int e = 0; e < 2; e++) {
            int col = col0 + e;
            int img = col >> 4, pos = col & 15;
            float4 o0, o1;
            o0.x = fmaxf((e ? v[0].y : v[0].x) + bb[0], 0.f);
            o0.y = fmaxf((e ? v[1].y : v[1].x) + bb[1], 0.f);
            o0.z = fmaxf((e ? v[2].y : v[2].x) + bb[2], 0.f);
            o0.w = fmaxf((e ? v[3].y : v[3].x) + bb[3], 0.f);
            o1.x = fmaxf((e ? v[4].y : v[4].x) + bb[4], 0.f);
            o1.y = fmaxf((e ? v[5].y : v[5].x) + bb[5], 0.f);
            o1.z = fmaxf((e ? v[6].y : v[6].x) + bb[6], 0.f);
            o1.w = fmaxf((e ? v[7].y : v[7].x) + bb[7], 0.f);
            float* op = &g_fea[(((size_t)(b0 + img) * 16) + pos) * 256 + cob + cy * 8];
            *(float4*)&op[0] = o0;
            *(float4*)&op[4] = o1;
        }
    }
}

// ---------- code norms ----------
__global__ void codenorm_k(const float* __restrict__ c0, const float* __restrict__ c1) {
    int c = blockIdx.x * 256 + threadIdx.x;
    const float* cp = (c < 512) ? c0 + (size_t)c * 256 : c1 + (size_t)(c - 512) * 256;
    float s = 0.f;
    for (int k = 0; k < 256; k += 4) {
        float4 v = *(const float4*)&cp[k];
        s += v.x * v.x + v.y * v.y + v.z * v.z + v.w * v.w;
    }
    g_cn[c] = s;
}

// ---------- VQ: 128 rows/block, 128-code tiles, 8x8 tile FFMA2 ----------
__global__ __launch_bounds__(256, 2) void vq_k(const float* __restrict__ c0,
                                               const float* __restrict__ c1,
                                               const int* __restrict__ idxp) {
    __shared__ float sF[32][128];
    __shared__ float sC[32][128];
    __shared__ float sbv[128][16];
    __shared__ int   sbi[128][16];
    int tid = threadIdx.x;
    int rowbase = blockIdx.x * 128;
    int px = tid & 15;
    int cy = tid >> 4;
    int Kc = (idxp[0] == 0) ? 512 : 1024;
    int ntiles = Kc >> 7;
    float bv[8]; int bi[8];
#pragma unroll
    for (int i = 0; i < 8; i++) { bv[i] = 1e30f; bi[i] = 0; }

    for (int t = 0; t < ntiles; t++) {
        u64 acc[4][8];
#pragma unroll
        for (int i = 0; i < 4; i++)
#pragma unroll
            for (int j = 0; j < 8; j++) acc[i][j] = 0ull;
        for (int kc = 0; kc < 8; kc++) {
            __syncthreads();
#pragma unroll
            for (int i = 0; i < 4; i++) {
                int idx = tid + 256 * i;
                int r = idx & 127, kq = idx >> 7;
                float4 v = *(const float4*)&g_fea[(size_t)(rowbase + r) * 256 + kc * 32 + kq * 4];
                sF[kq * 4 + 0][r] = v.x; sF[kq * 4 + 1][r] = v.y;
                sF[kq * 4 + 2][r] = v.z; sF[kq * 4 + 3][r] = v.w;
            }
#pragma unroll
            for (int i = 0; i < 4; i++) {
                int idx = tid + 256 * i;
                int c = idx & 127, kq = idx >> 7;
                int cg = t * 128 + c;
                const float* cp = (cg < 512) ? c0 + (size_t)cg * 256 : c1 + (size_t)(cg - 512) * 256;
                float4 v = *(const float4*)&cp[kc * 32 + kq * 4];
                sC[kq * 4 + 0][c] = v.x; sC[kq * 4 + 1][c] = v.y;
                sC[kq * 4 + 2][c] = v.z; sC[kq * 4 + 3][c] = v.w;
            }
            __syncthreads();
#pragma unroll 4
            for (int k = 0; k < 32; k++) {
                float4 a0 = *(float4*)&sF[k][px * 8];
                float4 a1 = *(float4*)&sF[k][px * 8 + 4];
                float4 b0 = *(float4*)&sC[k][cy * 8];
                float4 b1 = *(float4*)&sC[k][cy * 8 + 4];
                u64 ap[4] = {pk2(a0.x, a0.y), pk2(a0.z, a0.w), pk2(a1.x, a1.y), pk2(a1.z, a1.w)};
                u64 bd[8] = {pk2(b0.x, b0.x), pk2(b0.y, b0.y), pk2(b0.z, b0.z), pk2(b0.w, b0.w),
                             pk2(b1.x, b1.x), pk2(b1.y, b1.y), pk2(b1.z, b1.z), pk2(b1.w, b1.w)};
#pragma unroll
                for (int ip = 0; ip < 4; ip++)
#pragma unroll
                    for (int j = 0; j < 8; j++) ffma2(acc[ip][j], ap[ip], bd[j]);
            }
        }
#pragma unroll
        for (int j = 0; j < 8; j++) {
            int c = t * 128 + cy * 8 + j;
            float cn = g_cn[c];
#pragma unroll
            for (int ip = 0; ip < 4; ip++) {
                float2 v = upk(acc[ip][j]);
                float d0 = cn - 2.f * v.x;
                float d1 = cn - 2.f * v.y;
                if (d0 < bv[2 * ip])     { bv[2 * ip] = d0;     bi[2 * ip] = c; }
                if (d1 < bv[2 * ip + 1]) { bv[2 * ip + 1] = d1; bi[2 * ip + 1] = c; }
            }
        }
    }
    __syncthreads();
#pragma unroll
    for (int l = 0; l < 8; l++) { sbv[px * 8 + l][cy] = bv[l]; sbi[px * 8 + l][cy] = bi[l]; }
    __syncthreads();
    if (tid < 128) {
        float v = sbv[tid][0]; int ii = sbi[tid][0];
#pragma unroll
        for (int q = 1; q < 16; q++) {
            float v2 = sbv[tid][q]; int i2 = sbi[tid][q];
            if (v2 < v || (v2 == v && i2 < ii)) { v = v2; ii = i2; }
        }
        g_eidx[rowbase + tid] = ii;
    }
}

__global__ void zero_hist_k() { g_hist[threadIdx.x] = 0; }

// ---------- loss partials + histogram ----------
__global__ void loss_hist_k(const float* __restrict__ c0, const float* __restrict__ c1) {
    __shared__ float red[256];
    int row = blockIdx.x * 256 + threadIdx.x;
    int e = g_eidx[row];
    atomicAdd(&g_hist[e], 1);
    const float* cp = (e < 512) ? c0 + (size_t)e * 256 : c1 + (size_t)(e - 512) * 256;
    const float* f = g_fea + (size_t)row * 256;
    float s = 0.f;
    for (int k = 0; k < 256; k += 4) {
        float4 q = *(const float4*)&cp[k];
        float4 fv = *(const float4*)&f[k];
        float a = q.x - fv.x, b = q.y - fv.y, c = q.z - fv.z, d = q.w - fv.w;
        s += a * a + b * b + c * c + d * d;
    }
    red[threadIdx.x] = s;
    __syncthreads();
    for (int st = 128; st; st >>= 1) {
        if (threadIdx.x < st) red[threadIdx.x] += red[threadIdx.x + st];
        __syncthreads();
    }
    if (threadIdx.x == 0) g_losspart[blockIdx.x] = red[0];
}

// ---------- rearrange fc1_w -> g_wt[pos][c][n] ----------
__global__ void wt_k(const float* __restrict__ w) {
    int pc = blockIdx.x;                 // 4096 = 16 pos * 256 c
    int pos = pc >> 8, c = pc & 255;
    int n = threadIdx.x;                 // 512
    g_wt[((size_t)pos * 256 + c) * 512 + n] = w[(size_t)n * 4096 + c * 16 + pos];
}

// ---------- P[pos] = codes @ wt[pos] : [1024,256]x[256,512] ----------
__global__ __launch_bounds__(256) void ptab_k(const float* __restrict__ c0,
                                              const float* __restrict__ c1) {
    __shared__ float sA[16][68];
    __shared__ float sB[16][68];
    int tid = threadIdx.x;
    int cb = blockIdx.x * 64, nb = blockIdx.y * 64, pos = blockIdx.z;
    int tx = tid & 15, ty = tid >> 4;
    float acc[4][4];
#pragma unroll
    for (int i = 0; i < 4; i++)
#pragma unroll
        for (int j = 0; j < 4; j++) acc[i][j] = 0.f;
    for (int kt = 0; kt < 16; kt++) {
        __syncthreads();
        for (int i = tid; i < 1024; i += 256) {
            int c = i >> 4, k = i & 15;
            int cg = cb + c;
            const float* cp = (cg < 512) ? c0 + (size_t)cg * 256 : c1 + (size_t)(cg - 512) * 256;
            sA[k][c] = cp[kt * 16 + k];
        }
        for (int i = tid; i < 1024; i += 256) {
            int k = i >> 6, n = i & 63;
            sB[k][n] = g_wt[((size_t)pos * 256 + kt * 16 + k) * 512 + nb + n];
        }
        __syncthreads();
#pragma unroll
        for (int kk = 0; kk < 16; kk++) {
            float a4[4], b4[4];
            *(float4*)a4 = *(float4*)&sA[kk][ty * 4];
            *(float4*)b4 = *(float4*)&sB[kk][tx * 4];
#pragma unroll
            for (int i = 0; i < 4; i++)
#pragma unroll
                for (int j = 0; j < 4; j++) acc[i][j] = fmaf(a4[i], b4[j], acc[i][j]);
        }
    }
#pragma unroll
    for (int i = 0; i < 4; i++) {
        float4 o = make_float4(acc[i][0], acc[i][1], acc[i][2], acc[i][3]);
        *(float4*)&g_P[((size_t)pos * 1024 + cb + ty * 4 + i) * 512 + nb + tx * 4] = o;
    }
}

// ---------- h[b,n] = gelu(sum_pos P[pos][e][n] + b1[n]) ----------
__global__ __launch_bounds__(512) void hgs_k(const float* __restrict__ fb) {
    __shared__ int se[16];
    int b = blockIdx.x, tid = threadIdx.x;
    if (tid < 16) se[tid] = g_eidx[b * 16 + tid];
    __syncthreads();
    float acc = fb[tid];
#pragma unroll
    for (int p = 0; p < 16; p++) acc += g_P[((size_t)p * 1024 + se[p]) * 512 + tid];
    g_h[(size_t)b * 512 + tid] = gelu_t(acc);
}

// ---------- fc2: out[b,m] = h[b]·fc2_w[m] + b2[m] ----------
__global__ __launch_bounds__(256) void fc2_k(const float* __restrict__ w,
                                             const float* __restrict__ bias,
                                             float* __restrict__ out) {
    __shared__ float sw[10][512];
    __shared__ float sb[10];
    int tid = threadIdx.x;
    for (int i = tid; i < 5120; i += 256) sw[i >> 9][i & 511] = w[i];
    if (tid < 10) sb[tid] = bias[tid];
    __syncthreads();
    int warp = tid >> 5, lane = tid & 31;
    int bimg = blockIdx.x * 8 + warp;
    const float* hr = g_h + (size_t)bimg * 512;
    float acc[10];
#pragma unroll
    for (int m = 0; m < 10; m++) acc[m] = 0.f;
    for (int k = 0; k < 16; k++) {
        float hv = hr[lane + 32 * k];
#pragma unroll
        for (int m = 0; m < 10; m++) acc[m] = fmaf(hv, sw[m][lane + 32 * k], acc[m]);
    }
#pragma unroll
    for (int off = 16; off; off >>= 1)
#pragma unroll
        for (int m = 0; m < 10; m++) acc[m] += __shfl_xor_sync(0xFFFFFFFFu, acc[m], off);
    if (lane < 10) out[(size_t)bimg * 10 + lane] = acc[lane] + sb[lane];
}

// ---------- loss + perplexity ----------
__global__ void losspp_k(float* __restrict__ dout, int osz) {
    __shared__ float red[256];
    int tid = threadIdx.x;
    red[tid] = g_losspart[tid];
    __syncthreads();
    for (int st = 128; st; st >>= 1) {
        if (tid < st) red[tid] += red[tid + st];
        __syncthreads();
    }
    float loss = 1.25f * red[0] / 16777216.0f;
    __syncthreads();
    float s = 0.f;
    for (int i = tid; i < 1024; i += 256) {
        float p = (float)g_hist[i] / 65536.0f;
        if (p > 0.f) s += p * logf(p + 1e-10f);
    }
    red[tid] = s;
    __syncthreads();
    for (int st = 128; st; st >>= 1) {
        if (tid < st) red[tid] += red[tid + st];
        __syncthreads();
    }
    if (tid == 0) { dout[osz - 2] = loss; dout[osz - 1] = expf(-red[0]); }
}

extern "C" void kernel_launch(void* const* d_in, const int* in_sizes, int n_in,
                              void* d_out, int out_size) {
    const float* x     = (const float*)d_in[0];
    const float* w1    = (const float*)d_in[1];
    const float* b1    = (const float*)d_in[2];
    const float* w2    = (const float*)d_in[3];
    const float* b2    = (const float*)d_in[4];
    const float* w3    = (const float*)d_in[5];
    const float* b3    = (const float*)d_in[6];
    const float* code0 = (const float*)d_in[7];
    const float* code1 = (const float*)d_in[8];
    const float* fc1w  = (const float*)d_in[9];
    const float* fc1b  = (const float*)d_in[10];
    const float* fc2w  = (const float*)d_in[11];
    const float* fc2b  = (const float*)d_in[12];
    const int*   idxp  = (const int*)d_in[13];
    float* out = (float*)d_out;

    // conv2_k stays at our launch #3 (ncu -s 5 lands there after 2 harness launches).
    conv1_k<<<4096, 256>>>(x, w1, b1);                    // 0
    wt2_k<<<576, 128>>>(w2);                              // 1
    im2col2_k<<<4096, 256>>>();                           // 2
    conv2_k<<<2048, 256>>>(b2);                           // 3  <-- profile target
    wt3_k<<<1152, 256>>>(w3);                             // 4
    im2col3_k<<<4096, 256>>>();                           // 5
    conv3_k<<<dim3(512, 2), 256>>>(b3);                   // 6
    codenorm_k<<<4, 256>>>(code0, code1);                 // 7
    vq_k<<<512, 256>>>(code0, code1, idxp);               // 8
    zero_hist_k<<<1, 1024>>>();                           // 9
    loss_hist_k<<<256, 256>>>(code0, code1);              // 10
    wt_k<<<4096, 512>>>(fc1w);                            // 11
    ptab_k<<<dim3(16, 8, 16), 256>>>(code0, code1);       // 12
    hgs_k<<<4096, 512>>>(fc1b);                           // 13
    fc2_k<<<512, 256>>>(fc2w, fc2b, out);                 // 14
    losspp_k<<<1, 256>>>(out, out_size);                  // 15
}

// round 7
// speedup vs baseline: 17.1350x; 1.1384x over previous
#include <cuda_runtime.h>
#include <math.h>

typedef unsigned long long u64;

// ------------------ scratch (__device__ globals; no allocation) ------------------
__device__ float g_a1[4096 * 256 * 64];       // conv1 out NHWC [B,16x16,64]
__device__ float g_a2[4096 * 64 * 128];       // conv2 out NHWC [B,8x8,128]
__device__ float g_fea[4096 * 16 * 256];      // conv3 out NHWC rows (VQ input)
__device__ float g_A2[4096 * 9 * 64 * 64];    // im2col of a1 for conv2 [b][tap][pos][ci]
__device__ float g_A3[4096 * 9 * 16 * 128];   // im2col of a2 for conv3 [b][tap][pos][ci]
__device__ float g_wT2[576 * 128];            // conv2 weights k-major [tap*64+ci][co]
__device__ float g_wT3[1152 * 256];           // conv3 weights k-major [tap*128+ci][co]
__device__ float g_cT[256 * 1024];            // codes k-major [k][code]
__device__ float g_wt[16 * 256 * 512];        // fc1_w rearranged [pos][c][n]
__device__ float g_P[16 * 1024 * 512];        // P[pos][code][n]
__device__ float g_h[4096 * 512];             // fc1+gelu output
__device__ int   g_eidx[65536];
__device__ float g_cn[1024];
__device__ int   g_hist[1024];
__device__ float g_losspart[256];

__device__ __forceinline__ float gelu_t(float x) {
    float x3 = x * x * x;
    float t = tanhf(0.7978845608028654f * (x + 0.044715f * x3));
    return 0.5f * x * (1.0f + t);
}

// ---- packed f32x2 helpers ----
__device__ __forceinline__ u64 pk2(float lo, float hi) {
    u64 r; asm("mov.b64 %0, {%1, %2};" : "=l"(r) : "f"(lo), "f"(hi)); return r;
}
__device__ __forceinline__ void ffma2(u64& d, u64 a, u64 b) {
    asm("fma.rn.f32x2 %0, %1, %2, %0;" : "+l"(d) : "l"(a), "l"(b));
}
__device__ __forceinline__ float2 upk(u64 v) {
    float2 r; asm("mov.b64 {%0, %1}, %2;" : "=f"(r.x), "=f"(r.y) : "l"(v)); return r;
}

// ---- cp.async helpers ----
__device__ __forceinline__ void cpa16(void* smem_dst, const void* gmem_src) {
    unsigned d = (unsigned)__cvta_generic_to_shared(smem_dst);
    asm volatile("cp.async.ca.shared.global [%0], [%1], 16;" :: "r"(d), "l"(gmem_src));
}
__device__ __forceinline__ void cpa_commit() { asm volatile("cp.async.commit_group;"); }
__device__ __forceinline__ void cpa_wait0()  { asm volatile("cp.async.wait_group 0;" ::: "memory"); }

// ---------- conv1 ----------
__global__ __launch_bounds__(256) void conv1_k(const float* __restrict__ x,
                                               const float* __restrict__ w,
                                               const float* __restrict__ bias) {
    __shared__ float sw1[27][64];
    __shared__ float sb1[64];
    int tid = threadIdx.x, b = blockIdx.x;
    for (int i = tid; i < 1728; i += 256) { int co = i & 63, t = i >> 6; sw1[t][co] = w[co * 27 + t]; }
    if (tid < 64) sb1[tid] = bias[tid];
    __syncthreads();
    int oh = tid >> 4, ow = tid & 15;
    const float* xb = x + (size_t)b * 3072;
    float in[27];
#pragma unroll
    for (int c = 0; c < 3; c++)
#pragma unroll
        for (int kh = 0; kh < 3; kh++)
#pragma unroll
            for (int kw = 0; kw < 3; kw++) {
                int ih = oh * 2 + kh - 1, iw = ow * 2 + kw - 1;
                float v = 0.f;
                if ((unsigned)ih < 32u && (unsigned)iw < 32u) v = xb[(c * 32 + ih) * 32 + iw];
                in[(c * 3 + kh) * 3 + kw] = v;
            }
    float* ob = g_a1 + ((size_t)b * 256 + tid) * 64;
#pragma unroll
    for (int cq = 0; cq < 16; cq++) {
        float a0 = sb1[cq * 4], a1 = sb1[cq * 4 + 1], a2 = sb1[cq * 4 + 2], a3 = sb1[cq * 4 + 3];
#pragma unroll
        for (int t = 0; t < 27; t++) {
            float4 wv = *(float4*)&sw1[t][cq * 4];
            a0 = fmaf(in[t], wv.x, a0); a1 = fmaf(in[t], wv.y, a1);
            a2 = fmaf(in[t], wv.z, a2); a3 = fmaf(in[t], wv.w, a3);
        }
        float4 o; o.x = fmaxf(a0, 0.f); o.y = fmaxf(a1, 0.f); o.z = fmaxf(a2, 0.f); o.w = fmaxf(a3, 0.f);
        *(float4*)&ob[cq * 4] = o;
    }
}

// ---------- weight/code transposes ----------
__global__ void wt2_k(const float* __restrict__ w) {
    int k = blockIdx.x, co = threadIdx.x;
    int tap = k >> 6, ci = k & 63;
    g_wT2[k * 128 + co] = w[co * 576 + ci * 9 + tap];
}
__global__ void wt3_k(const float* __restrict__ w) {
    int k = blockIdx.x, co = threadIdx.x;
    int tap = k / 128, ci = k % 128;
    g_wT3[k * 256 + co] = w[co * 1152 + ci * 9 + tap];
}
__global__ void ct_k(const float* __restrict__ c0, const float* __restrict__ c1) {
    int k = blockIdx.x;
    for (int c = threadIdx.x; c < 1024; c += 256)
        g_cT[k * 1024 + c] = (c < 512) ? c0[(size_t)c * 256 + k] : c1[(size_t)(c - 512) * 256 + k];
}

// ---------- im2col ----------
__global__ __launch_bounds__(256) void im2col2_k() {
    int b = blockIdx.x, tid = threadIdx.x;
    const float* ab = g_a1 + (size_t)b * 256 * 64;
    float* ob = g_A2 + (size_t)b * 9 * 64 * 64;
#pragma unroll
    for (int l = 0; l < 36; l++) {
        int i = tid + 256 * l;
        int slot = i >> 4, q = i & 15;
        int tap = slot >> 6, pos = slot & 63;
        int kh = tap / 3, kw = tap - kh * 3;
        int oh = pos >> 3, ow = pos & 7;
        int ih = oh * 2 + kh - 1, iw = ow * 2 + kw - 1;
        float4 v = make_float4(0.f, 0.f, 0.f, 0.f);
        if ((unsigned)ih < 16u && (unsigned)iw < 16u)
            v = *(const float4*)&ab[(ih * 16 + iw) * 64 + q * 4];
        *(float4*)&ob[(size_t)slot * 64 + q * 4] = v;
    }
}
__global__ __launch_bounds__(256) void im2col3_k() {
    int b = blockIdx.x, tid = threadIdx.x;
    const float* ab = g_a2 + (size_t)b * 64 * 128;
    float* ob = g_A3 + (size_t)b * 9 * 16 * 128;
#pragma unroll
    for (int l = 0; l < 18; l++) {
        int i = tid + 256 * l;
        int slot = i >> 5, q = i & 31;
        int tap = slot >> 4, pos = slot & 15;
        int kh = tap / 3, kw = tap - kh * 3;
        int oh = pos >> 2, ow = pos & 3;
        int ih = oh * 2 + kh - 1, iw = ow * 2 + kw - 1;
        float4 v = make_float4(0.f, 0.f, 0.f, 0.f);
        if ((unsigned)ih < 8u && (unsigned)iw < 8u)
            v = *(const float4*)&ab[(ih * 8 + iw) * 128 + q * 4];
        *(float4*)&ob[(size_t)slot * 128 + q * 4] = v;
    }
}

// ---- shared 16-k FFMA2 microkernel ----
#define MICRO16(SA, SB)                                                          \
    _Pragma("unroll")                                                            \
    for (int k = 0; k < 16; k++) {                                               \
        float4 a0 = *(float4*)&SA[k][px * 8];                                    \
        float4 a1 = *(float4*)&SA[k][px * 8 + 4];                                \
        float4 w0 = *(float4*)&SB[k][cy * 8];                                    \
        float4 w1 = *(float4*)&SB[k][cy * 8 + 4];                                \
        u64 ap[4] = {pk2(a0.x, a0.y), pk2(a0.z, a0.w), pk2(a1.x, a1.y), pk2(a1.z, a1.w)}; \
        u64 bd[8] = {pk2(w0.x, w0.x), pk2(w0.y, w0.y), pk2(w0.z, w0.z), pk2(w0.w, w0.w),  \
                     pk2(w1.x, w1.x), pk2(w1.y, w1.y), pk2(w1.z, w1.z), pk2(w1.w, w1.w)}; \
        _Pragma("unroll")                                                        \
        for (int ip = 0; ip < 4; ip++)                                           \
            _Pragma("unroll")                                                    \
            for (int j = 0; j < 8; j++) ffma2(acc[ip][j], ap[ip], bd[j]);        \
    }

// ---------- conv2 GEMM: 2 images/block, C[128col,128co], K=576, pipelined ----------
__global__ __launch_bounds__(256, 2) void conv2_k(const float* __restrict__ bias) {
    __shared__ float sA[16][132];
    __shared__ float sB[2][16][128];
    int tid = threadIdx.x;
    int b0 = blockIdx.x * 2;
    int px = tid & 15, cy = tid >> 4;
    int qa = tid & 3, ca = tid >> 2;        // A prefetch: col = ca + 64*l, ci word = qa*4
    u64 acc[4][8];
#pragma unroll
    for (int i = 0; i < 4; i++)
#pragma unroll
        for (int j = 0; j < 8; j++) acc[i][j] = 0ull;
    float4 pva[2];

    // prologue: chunk 0
    {
#pragma unroll
        for (int l = 0; l < 2; l++) {
            int c = ca + 64 * l; int img = c >> 6, pos = c & 63;
            pva[l] = *(const float4*)&g_A2[(((size_t)(b0 + img) * 9 + 0) * 64 + pos) * 64 + qa * 4];
        }
#pragma unroll
        for (int l = 0; l < 2; l++) {
            int slot = tid + 256 * l;
            int k = slot >> 5, q = slot & 31;
            cpa16(&sB[0][k][q * 4], &g_wT2[(size_t)k * 128 + q * 4]);
        }
        cpa_commit();
    }
    for (int ch = 0; ch < 36; ch++) {
        cpa_wait0();
        __syncthreads();
#pragma unroll
        for (int l = 0; l < 2; l++) {
            int c = ca + 64 * l;
            sA[qa * 4 + 0][c] = pva[l].x; sA[qa * 4 + 1][c] = pva[l].y;
            sA[qa * 4 + 2][c] = pva[l].z; sA[qa * 4 + 3][c] = pva[l].w;
        }
        if (ch + 1 < 36) {
            int tap = (ch + 1) >> 2, ci0 = ((ch + 1) & 3) * 16;
#pragma unroll
            for (int l = 0; l < 2; l++) {
                int c = ca + 64 * l; int img = c >> 6, pos = c & 63;
                pva[l] = *(const float4*)&g_A2[(((size_t)(b0 + img) * 9 + tap) * 64 + pos) * 64 + ci0 + qa * 4];
            }
            int nb = (ch + 1) & 1;
#pragma unroll
            for (int l = 0; l < 2; l++) {
                int slot = tid + 256 * l;
                int k = slot >> 5, q = slot & 31;
                cpa16(&sB[nb][k][q * 4], &g_wT2[(size_t)(tap * 64 + ci0 + k) * 128 + q * 4]);
            }
            cpa_commit();
        }
        __syncthreads();
        int cb = ch & 1;
        MICRO16(sA, sB[cb])
    }
    float bb[8];
    *(float4*)&bb[0] = *(const float4*)&bias[cy * 8];
    *(float4*)&bb[4] = *(const float4*)&bias[cy * 8 + 4];
#pragma unroll
    for (int ip = 0; ip < 4; ip++) {
        float2 v[8];
#pragma unroll
        for (int j = 0; j < 8; j++) v[j] = upk(acc[ip][j]);
        int col0 = px * 8 + 2 * ip;
#pragma unroll
        for (int e = 0; e < 2; e++) {
            int col = col0 + e;
            int img = col >> 6, pos = col & 63;
            float4 o0, o1;
            o0.x = fmaxf((e ? v[0].y : v[0].x) + bb[0], 0.f);
            o0.y = fmaxf((e ? v[1].y : v[1].x) + bb[1], 0.f);
            o0.z = fmaxf((e ? v[2].y : v[2].x) + bb[2], 0.f);
            o0.w = fmaxf((e ? v[3].y : v[3].x) + bb[3], 0.f);
            o1.x = fmaxf((e ? v[4].y : v[4].x) + bb[4], 0.f);
            o1.y = fmaxf((e ? v[5].y : v[5].x) + bb[5], 0.f);
            o1.z = fmaxf((e ? v[6].y : v[6].x) + bb[6], 0.f);
            o1.w = fmaxf((e ? v[7].y : v[7].x) + bb[7], 0.f);
            float* op = &g_a2[(((size_t)(b0 + img) * 64) + pos) * 128 + cy * 8];
            *(float4*)&op[0] = o0;
            *(float4*)&op[4] = o1;
        }
    }
}

// ---------- conv3 GEMM: 8 images x 128 co, K=1152, pipelined ----------
__global__ __launch_bounds__(256, 2) void conv3_k(const float* __restrict__ bias) {
    __shared__ float sA[16][132];
    __shared__ float sB[2][16][128];
    int tid = threadIdx.x;
    int b0 = blockIdx.x * 8;
    int cob = blockIdx.y * 128;
    int px = tid & 15, cy = tid >> 4;
    int qa = tid & 3, ca = tid >> 2;
    u64 acc[4][8];
#pragma unroll
    for (int i = 0; i < 4; i++)
#pragma unroll
        for (int j = 0; j < 8; j++) acc[i][j] = 0ull;
    float4 pva[2];

    {
#pragma unroll
        for (int l = 0; l < 2; l++) {
            int c = ca + 64 * l; int img = c >> 4, pos = c & 15;
            pva[l] = *(const float4*)&g_A3[(((size_t)(b0 + img) * 9 + 0) * 16 + pos) * 128 + qa * 4];
        }
#pragma unroll
        for (int l = 0; l < 2; l++) {
            int slot = tid + 256 * l;
            int k = slot >> 5, q = slot & 31;
            cpa16(&sB[0][k][q * 4], &g_wT3[(size_t)k * 256 + cob + q * 4]);
        }
        cpa_commit();
    }
    for (int ch = 0; ch < 72; ch++) {
        cpa_wait0();
        __syncthreads();
#pragma unroll
        for (int l = 0; l < 2; l++) {
            int c = ca + 64 * l;
            sA[qa * 4 + 0][c] = pva[l].x; sA[qa * 4 + 1][c] = pva[l].y;
            sA[qa * 4 + 2][c] = pva[l].z; sA[qa * 4 + 3][c] = pva[l].w;
        }
        if (ch + 1 < 72) {
            int tap = (ch + 1) >> 3, ci0 = ((ch + 1) & 7) * 16;
#pragma unroll
            for (int l = 0; l < 2; l++) {
                int c = ca + 64 * l; int img = c >> 4, pos = c & 15;
                pva[l] = *(const float4*)&g_A3[(((size_t)(b0 + img) * 9 + tap) * 16 + pos) * 128 + ci0 + qa * 4];
            }
            int nb = (ch + 1) & 1;
#pragma unroll
            for (int l = 0; l < 2; l++) {
                int slot = tid + 256 * l;
                int k = slot >> 5, q = slot & 31;
                cpa16(&sB[nb][k][q * 4], &g_wT3[(size_t)(tap * 128 + ci0 + k) * 256 + cob + q * 4]);
            }
            cpa_commit();
        }
        __syncthreads();
        int cb = ch & 1;
        MICRO16(sA, sB[cb])
    }
    float bb[8];
    *(float4*)&bb[0] = *(const float4*)&bias[cob + cy * 8];
    *(float4*)&bb[4] = *(const float4*)&bias[cob + cy * 8 + 4];
#pragma unroll
    for (int ip = 0; ip < 4; ip++) {
        float2 v[8];
#pragma unroll
        for (int j = 0; j < 8; j++) v[j] = upk(acc[ip][j]);
        int col0 = px * 8 + 2 * ip;
#pragma unroll
        for (int e = 0; e < 2; e++) {
            int col = col0 + e;
            int img = col >> 4, pos = col & 15;
            float4 o0, o1;
            o0.x = fmaxf((e ? v[0].y : v[0].x) + bb[0], 0.f);
            o0.y = fmaxf((e ? v[1].y : v[1].x) + bb[1], 0.f);
            o0.z = fmaxf((e ? v[2].y : v[2].x) + bb[2], 0.f);
            o0.w = fmaxf((e ? v[3].y : v[3].x) + bb[3], 0.f);
            o1.x = fmaxf((e ? v[4].y : v[4].x) + bb[4], 0.f);
            o1.y = fmaxf((e ? v[5].y : v[5].x) + bb[5], 0.f);
            o1.z = fmaxf((e ? v[6].y : v[6].x) + bb[6], 0.f);
            o1.w = fmaxf((e ? v[7].y : v[7].x) + bb[7], 0.f);
            float* op = &g_fea[(((size_t)(b0 + img) * 16) + pos) * 256 + cob + cy * 8];
            *(float4*)&op[0] = o0;
            *(float4*)&op[4] = o1;
        }
    }
}

// ---------- code norms ----------
__global__ void codenorm_k(const float* __restrict__ c0, const float* __restrict__ c1) {
    int c = blockIdx.x * 256 + threadIdx.x;
    const float* cp = (c < 512) ? c0 + (size_t)c * 256 : c1 + (size_t)(c - 512) * 256;
    float s = 0.f;
    for (int k = 0; k < 256; k += 4) {
        float4 v = *(const float4*)&cp[k];
        s += v.x * v.x + v.y * v.y + v.z * v.z + v.w * v.w;
    }
    g_cn[c] = s;
}

// ---------- VQ: 128 rows/block x 128-code tiles, pipelined ----------
__global__ __launch_bounds__(256, 2) void vq_k(const int* __restrict__ idxp) {
    __shared__ float sA[16][132];
    __shared__ float sB[2][16][128];
    __shared__ float sbv[128][16];
    __shared__ int   sbi[128][16];
    int tid = threadIdx.x;
    int rowbase = blockIdx.x * 128;
    int px = tid & 15, cy = tid >> 4;
    int qa = tid & 3, ca = tid >> 2;
    int Kc = (idxp[0] == 0) ? 512 : 1024;
    int total = (Kc >> 7) * 16;               // chunks: t = cc>>4, kc = cc&15
    float bv[8]; int bi[8];
#pragma unroll
    for (int i = 0; i < 8; i++) { bv[i] = 1e30f; bi[i] = 0; }
    u64 acc[4][8];
#pragma unroll
    for (int i = 0; i < 4; i++)
#pragma unroll
        for (int j = 0; j < 8; j++) acc[i][j] = 0ull;
    float4 pva[2];

    {
#pragma unroll
        for (int l = 0; l < 2; l++) {
            int r = ca + 64 * l;
            pva[l] = *(const float4*)&g_fea[(size_t)(rowbase + r) * 256 + qa * 4];
        }
#pragma unroll
        for (int l = 0; l < 2; l++) {
            int slot = tid + 256 * l;
            int k = slot >> 5, q = slot & 31;
            cpa16(&sB[0][k][q * 4], &g_cT[(size_t)k * 1024 + q * 4]);
        }
        cpa_commit();
    }
    for (int cc = 0; cc < total; cc++) {
        cpa_wait0();
        __syncthreads();
#pragma unroll
        for (int l = 0; l < 2; l++) {
            int r = ca + 64 * l;
            sA[qa * 4 + 0][r] = pva[l].x; sA[qa * 4 + 1][r] = pva[l].y;
            sA[qa * 4 + 2][r] = pva[l].z; sA[qa * 4 + 3][r] = pva[l].w;
        }
        if (cc + 1 < total) {
            int t = (cc + 1) >> 4, kc = (cc + 1) & 15;
#pragma unroll
            for (int l = 0; l < 2; l++) {
                int r = ca + 64 * l;
                pva[l] = *(const float4*)&g_fea[(size_t)(rowbase + r) * 256 + kc * 16 + qa * 4];
            }
            int nb = (cc + 1) & 1;
#pragma unroll
            for (int l = 0; l < 2; l++) {
                int slot = tid + 256 * l;
                int k = slot >> 5, q = slot & 31;
                cpa16(&sB[nb][k][q * 4], &g_cT[(size_t)(kc * 16 + k) * 1024 + t * 128 + q * 4]);
            }
            cpa_commit();
        }
        __syncthreads();
        int cb = cc & 1;
        MICRO16(sA, sB[cb])
        if ((cc & 15) == 15) {
            int t = cc >> 4;
#pragma unroll
            for (int j = 0; j < 8; j++) {
                int c = t * 128 + cy * 8 + j;
                float cn = g_cn[c];
#pragma unroll
                for (int ip = 0; ip < 4; ip++) {
                    float2 v = upk(acc[ip][j]);
                    float d0 = cn - 2.f * v.x;
                    float d1 = cn - 2.f * v.y;
                    if (d0 < bv[2 * ip])     { bv[2 * ip] = d0;     bi[2 * ip] = c; }
                    if (d1 < bv[2 * ip + 1]) { bv[2 * ip + 1] = d1; bi[2 * ip + 1] = c; }
                }
            }
#pragma unroll
            for (int i = 0; i < 4; i++)
#pragma unroll
                for (int j = 0; j < 8; j++) acc[i][j] = 0ull;
        }
    }
    __syncthreads();
#pragma unroll
    for (int l = 0; l < 8; l++) { sbv[px * 8 + l][cy] = bv[l]; sbi[px * 8 + l][cy] = bi[l]; }
    __syncthreads();
    if (tid < 128) {
        float v = sbv[tid][0]; int ii = sbi[tid][0];
#pragma unroll
        for (int q = 1; q < 16; q++) {
            float v2 = sbv[tid][q]; int i2 = sbi[tid][q];
            if (v2 < v || (v2 == v && i2 < ii)) { v = v2; ii = i2; }
        }
        g_eidx[rowbase + tid] = ii;
    }
}

__global__ void zero_hist_k() { g_hist[threadIdx.x] = 0; }

// ---------- loss partials + histogram ----------
__global__ void loss_hist_k(const float* __restrict__ c0, const float* __restrict__ c1) {
    __shared__ float red[256];
    int row = blockIdx.x * 256 + threadIdx.x;
    int e = g_eidx[row];
    atomicAdd(&g_hist[e], 1);
    const float* cp = (e < 512) ? c0 + (size_t)e * 256 : c1 + (size_t)(e - 512) * 256;
    const float* f = g_fea + (size_t)row * 256;
    float s = 0.f;
    for (int k = 0; k < 256; k += 4) {
        float4 q = *(const float4*)&cp[k];
        float4 fv = *(const float4*)&f[k];
        float a = q.x - fv.x, b = q.y - fv.y, c = q.z - fv.z, d = q.w - fv.w;
        s += a * a + b * b + c * c + d * d;
    }
    red[threadIdx.x] = s;
    __syncthreads();
    for (int st = 128; st; st >>= 1) {
        if (threadIdx.x < st) red[threadIdx.x] += red[threadIdx.x + st];
        __syncthreads();
    }
    if (threadIdx.x == 0) g_losspart[blockIdx.x] = red[0];
}

// ---------- rearrange fc1_w ----------
__global__ void wt_k(const float* __restrict__ w) {
    int pc = blockIdx.x;
    int pos = pc >> 8, c = pc & 255;
    int n = threadIdx.x;
    g_wt[((size_t)pos * 256 + c) * 512 + n] = w[(size_t)n * 4096 + c * 16 + pos];
}

// ---------- P[pos] = codes @ wt[pos] ----------
__global__ __launch_bounds__(256) void ptab_k(const float* __restrict__ c0,
                                              const float* __restrict__ c1) {
    __shared__ float sA[16][68];
    __shared__ float sB[16][68];
    int tid = threadIdx.x;
    int cb = blockIdx.x * 64, nb = blockIdx.y * 64, pos = blockIdx.z;
    int tx = tid & 15, ty = tid >> 4;
    float acc[4][4];
#pragma unroll
    for (int i = 0; i < 4; i++)
#pragma unroll
        for (int j = 0; j < 4; j++) acc[i][j] = 0.f;
    for (int kt = 0; kt < 16; kt++) {
        __syncthreads();
        for (int i = tid; i < 1024; i += 256) {
            int c = i >> 4, k = i & 15;
            int cg = cb + c;
            const float* cp = (cg < 512) ? c0 + (size_t)cg * 256 : c1 + (size_t)(cg - 512) * 256;
            sA[k][c] = cp[kt * 16 + k];
        }
        for (int i = tid; i < 1024; i += 256) {
            int k = i >> 6, n = i & 63;
            sB[k][n] = g_wt[((size_t)pos * 256 + kt * 16 + k) * 512 + nb + n];
        }
        __syncthreads();
#pragma unroll
        for (int kk = 0; kk < 16; kk++) {
            float a4[4], b4[4];
            *(float4*)a4 = *(float4*)&sA[kk][ty * 4];
            *(float4*)b4 = *(float4*)&sB[kk][tx * 4];
#pragma unroll
            for (int i = 0; i < 4; i++)
#pragma unroll
                for (int j = 0; j < 4; j++) acc[i][j] = fmaf(a4[i], b4[j], acc[i][j]);
        }
    }
#pragma unroll
    for (int i = 0; i < 4; i++) {
        float4 o = make_float4(acc[i][0], acc[i][1], acc[i][2], acc[i][3]);
        *(float4*)&g_P[((size_t)pos * 1024 + cb + ty * 4 + i) * 512 + nb + tx * 4] = o;
    }
}

// ---------- h = gelu(sum_pos P + b1) ----------
__global__ __launch_bounds__(512) void hgs_k(const float* __restrict__ fb) {
    __shared__ int se[16];
    int b = blockIdx.x, tid = threadIdx.x;
    if (tid < 16) se[tid] = g_eidx[b * 16 + tid];
    __syncthreads();
    float acc = fb[tid];
#pragma unroll
    for (int p = 0; p < 16; p++) acc += g_P[((size_t)p * 1024 + se[p]) * 512 + tid];
    g_h[(size_t)b * 512 + tid] = gelu_t(acc);
}

// ---------- fc2 ----------
__global__ __launch_bounds__(256) void fc2_k(const float* __restrict__ w,
                                             const float* __restrict__ bias,
                                             float* __restrict__ out) {
    __shared__ float sw[10][512];
    __shared__ float sb[10];
    int tid = threadIdx.x;
    for (int i = tid; i < 5120; i += 256) sw[i >> 9][i & 511] = w[i];
    if (tid < 10) sb[tid] = bias[tid];
    __syncthreads();
    int warp = tid >> 5, lane = tid & 31;
    int bimg = blockIdx.x * 8 + warp;
    const float* hr = g_h + (size_t)bimg * 512;
    float acc[10];
#pragma unroll
    for (int m = 0; m < 10; m++) acc[m] = 0.f;
    for (int k = 0; k < 16; k++) {
        float hv = hr[lane + 32 * k];
#pragma unroll
        for (int m = 0; m < 10; m++) acc[m] = fmaf(hv, sw[m][lane + 32 * k], acc[m]);
    }
#pragma unroll
    for (int off = 16; off; off >>= 1)
#pragma unroll
        for (int m = 0; m < 10; m++) acc[m] += __shfl_xor_sync(0xFFFFFFFFu, acc[m], off);
    if (lane < 10) out[(size_t)bimg * 10 + lane] = acc[lane] + sb[lane];
}

// ---------- loss + perplexity ----------
__global__ void losspp_k(float* __restrict__ dout, int osz) {
    __shared__ float red[256];
    int tid = threadIdx.x;
    red[tid] = g_losspart[tid];
    __syncthreads();
    for (int st = 128; st; st >>= 1) {
        if (tid < st) red[tid] += red[tid + st];
        __syncthreads();
    }
    float loss = 1.25f * red[0] / 16777216.0f;
    __syncthreads();
    float s = 0.f;
    for (int i = tid; i < 1024; i += 256) {
        float p = (float)g_hist[i] / 65536.0f;
        if (p > 0.f) s += p * logf(p + 1e-10f);
    }
    red[tid] = s;
    __syncthreads();
    for (int st = 128; st; st >>= 1) {
        if (tid < st) red[tid] += red[tid + st];
        __syncthreads();
    }
    if (tid == 0) { dout[osz - 2] = loss; dout[osz - 1] = expf(-red[0]); }
}

extern "C" void kernel_launch(void* const* d_in, const int* in_sizes, int n_in,
                              void* d_out, int out_size) {
    const float* x     = (const float*)d_in[0];
    const float* w1    = (const float*)d_in[1];
    const float* b1    = (const float*)d_in[2];
    const float* w2    = (const float*)d_in[3];
    const float* b2    = (const float*)d_in[4];
    const float* w3    = (const float*)d_in[5];
    const float* b3    = (const float*)d_in[6];
    const float* code0 = (const float*)d_in[7];
    const float* code1 = (const float*)d_in[8];
    const float* fc1w  = (const float*)d_in[9];
    const float* fc1b  = (const float*)d_in[10];
    const float* fc2w  = (const float*)d_in[11];
    const float* fc2b  = (const float*)d_in[12];
    const int*   idxp  = (const int*)d_in[13];
    float* out = (float*)d_out;

    // conv2_k stays at our launch #3 (ncu -s 5 lands there after 2 harness launches).
    conv1_k<<<4096, 256>>>(x, w1, b1);                    // 0
    wt2_k<<<576, 128>>>(w2);                              // 1
    im2col2_k<<<4096, 256>>>();                           // 2
    conv2_k<<<2048, 256>>>(b2);                           // 3  <-- profile target
    wt3_k<<<1152, 256>>>(w3);                             // 4
    im2col3_k<<<4096, 256>>>();                           // 5
    conv3_k<<<dim3(512, 2), 256>>>(b3);                   // 6
    ct_k<<<256, 256>>>(code0, code1);                     // 7
    codenorm_k<<<4, 256>>>(code0, code1);                 // 8
    vq_k<<<512, 256>>>(idxp);                             // 9
    zero_hist_k<<<1, 1024>>>();                           // 10
    loss_hist_k<<<256, 256>>>(code0, code1);              // 11
    wt_k<<<4096, 512>>>(fc1w);                            // 12
    ptab_k<<<dim3(16, 8, 16), 256>>>(code0, code1);       // 13
    hgs_k<<<4096, 512>>>(fc1b);                           // 14
    fc2_k<<<512, 256>>>(fc2w, fc2b, out);                 // 15
    losspp_k<<<1, 256>>>(out, out_size);                  // 16
}

// round 8
// speedup vs baseline: 18.7407x; 1.0937x over previous
#include <cuda_runtime.h>
#include <math.h>

typedef unsigned long long u64;

// ------------------ scratch (__device__ globals; no allocation) ------------------
__device__ float g_a1[4096 * 256 * 64];       // conv1 out NHWC [B,16x16,64]
__device__ float g_a2[4096 * 64 * 128];       // conv2 out NHWC [B,8x8,128]
__device__ float g_fea[4096 * 16 * 256];      // conv3 out NHWC rows (VQ input)
__device__ float g_wT2[576 * 128];            // conv2 weights k-major [tap*64+ci][co]
__device__ float g_wT3[1152 * 256];           // conv3 weights k-major [tap*128+ci][co]
__device__ float g_cT[256 * 1024];            // codes k-major [k][code]
__device__ float g_wt[4096 * 512];            // fc1_w transposed [c'][n], c' = c*16+pos
__device__ float g_P[16 * 1024 * 512];        // P[pos][code][n]
__device__ float g_h[4096 * 512];             // fc1+gelu output
__device__ int   g_eidx[65536];
__device__ float g_cn[1024];
__device__ int   g_hist[1024];
__device__ float g_losspart[256];

__device__ __forceinline__ float gelu_t(float x) {
    float x3 = x * x * x;
    float t = tanhf(0.7978845608028654f * (x + 0.044715f * x3));
    return 0.5f * x * (1.0f + t);
}

// ---- packed f32x2 helpers ----
__device__ __forceinline__ u64 pk2(float lo, float hi) {
    u64 r; asm("mov.b64 %0, {%1, %2};" : "=l"(r) : "f"(lo), "f"(hi)); return r;
}
__device__ __forceinline__ void ffma2(u64& d, u64 a, u64 b) {
    asm("fma.rn.f32x2 %0, %1, %2, %0;" : "+l"(d) : "l"(a), "l"(b));
}
__device__ __forceinline__ float2 upk(u64 v) {
    float2 r; asm("mov.b64 {%0, %1}, %2;" : "=f"(r.x), "=f"(r.y) : "l"(v)); return r;
}

// ---- cp.async helpers ----
__device__ __forceinline__ void cpa16(void* smem_dst, const void* gmem_src) {
    unsigned d = (unsigned)__cvta_generic_to_shared(smem_dst);
    asm volatile("cp.async.ca.shared.global [%0], [%1], 16;" :: "r"(d), "l"(gmem_src));
}
__device__ __forceinline__ void cpa_commit() { asm volatile("cp.async.commit_group;"); }
__device__ __forceinline__ void cpa_wait0()  { asm volatile("cp.async.wait_group 0;" ::: "memory"); }

// ---------- conv1 ----------
__global__ __launch_bounds__(256) void conv1_k(const float* __restrict__ x,
                                               const float* __restrict__ w,
                                               const float* __restrict__ bias) {
    __shared__ float sw1[27][64];
    __shared__ float sb1[64];
    int tid = threadIdx.x, b = blockIdx.x;
    for (int i = tid; i < 1728; i += 256) { int co = i & 63, t = i >> 6; sw1[t][co] = w[co * 27 + t]; }
    if (tid < 64) sb1[tid] = bias[tid];
    __syncthreads();
    int oh = tid >> 4, ow = tid & 15;
    const float* xb = x + (size_t)b * 3072;
    float in[27];
#pragma unroll
    for (int c = 0; c < 3; c++)
#pragma unroll
        for (int kh = 0; kh < 3; kh++)
#pragma unroll
            for (int kw = 0; kw < 3; kw++) {
                int ih = oh * 2 + kh - 1, iw = ow * 2 + kw - 1;
                float v = 0.f;
                if ((unsigned)ih < 32u && (unsigned)iw < 32u) v = xb[(c * 32 + ih) * 32 + iw];
                in[(c * 3 + kh) * 3 + kw] = v;
            }
    float* ob = g_a1 + ((size_t)b * 256 + tid) * 64;
#pragma unroll
    for (int cq = 0; cq < 16; cq++) {
        float a0 = sb1[cq * 4], a1 = sb1[cq * 4 + 1], a2 = sb1[cq * 4 + 2], a3 = sb1[cq * 4 + 3];
#pragma unroll
        for (int t = 0; t < 27; t++) {
            float4 wv = *(float4*)&sw1[t][cq * 4];
            a0 = fmaf(in[t], wv.x, a0); a1 = fmaf(in[t], wv.y, a1);
            a2 = fmaf(in[t], wv.z, a2); a3 = fmaf(in[t], wv.w, a3);
        }
        float4 o; o.x = fmaxf(a0, 0.f); o.y = fmaxf(a1, 0.f); o.z = fmaxf(a2, 0.f); o.w = fmaxf(a3, 0.f);
        *(float4*)&ob[cq * 4] = o;
    }
}

// ---------- weight/code transposes ----------
__global__ void wt2_k(const float* __restrict__ w) {
    int k = blockIdx.x, co = threadIdx.x;
    int tap = k >> 6, ci = k & 63;
    g_wT2[k * 128 + co] = w[co * 576 + ci * 9 + tap];
}
__global__ void wt3_k(const float* __restrict__ w) {
    int k = blockIdx.x, co = threadIdx.x;
    int tap = k / 128, ci = k % 128;
    g_wT3[k * 256 + co] = w[co * 1152 + ci * 9 + tap];
}
__global__ void ct_k(const float* __restrict__ c0, const float* __restrict__ c1) {
    int k = blockIdx.x;
    for (int c = threadIdx.x; c < 1024; c += 256)
        g_cT[k * 1024 + c] = (c < 512) ? c0[(size_t)c * 256 + k] : c1[(size_t)(c - 512) * 256 + k];
}
// fc1_w [512n][4096c'] -> g_wt [4096c'][512n], 32x32 smem tile transpose
__global__ __launch_bounds__(256) void wtT_k(const float* __restrict__ w) {
    __shared__ float t[32][33];
    int bx = blockIdx.x, by = blockIdx.y;
    int tx = threadIdx.x & 31, ty = threadIdx.x >> 5;
#pragma unroll
    for (int i = 0; i < 4; i++)
        t[ty + 8 * i][tx] = w[(size_t)(by * 32 + ty + 8 * i) * 4096 + bx * 32 + tx];
    __syncthreads();
#pragma unroll
    for (int i = 0; i < 4; i++)
        g_wt[(size_t)(bx * 32 + ty + 8 * i) * 512 + by * 32 + tx] = t[tx][ty + 8 * i];
}

// ---- shared 16-k FFMA2 microkernel ----
#define MICRO16(SA, SB)                                                          \
    _Pragma("unroll")                                                            \
    for (int k = 0; k < 16; k++) {                                               \
        float4 a0 = *(float4*)&SA[k][px * 8];                                    \
        float4 a1 = *(float4*)&SA[k][px * 8 + 4];                                \
        float4 w0 = *(float4*)&SB[k][cy * 8];                                    \
        float4 w1 = *(float4*)&SB[k][cy * 8 + 4];                                \
        u64 ap[4] = {pk2(a0.x, a0.y), pk2(a0.z, a0.w), pk2(a1.x, a1.y), pk2(a1.z, a1.w)}; \
        u64 bd[8] = {pk2(w0.x, w0.x), pk2(w0.y, w0.y), pk2(w0.z, w0.z), pk2(w0.w, w0.w),  \
                     pk2(w1.x, w1.x), pk2(w1.y, w1.y), pk2(w1.z, w1.z), pk2(w1.w, w1.w)}; \
        _Pragma("unroll")                                                        \
        for (int ip = 0; ip < 4; ip++)                                           \
            _Pragma("unroll")                                                    \
            for (int j = 0; j < 8; j++) ffma2(acc[ip][j], ap[ip], bd[j]);        \
    }

// ---------- conv2 GEMM: 2 images/block, C[128col,128co], K=576, inline im2col ----------
__global__ __launch_bounds__(256, 2) void conv2_k(const float* __restrict__ bias) {
    __shared__ float sA[2][16][132];
    __shared__ float sB[2][16][128];
    int tid = threadIdx.x;
    int b0 = blockIdx.x * 2;
    int px = tid & 15, cy = tid >> 4;
    int qa = tid & 3, ca = tid >> 2;
    u64 acc[4][8];
#pragma unroll
    for (int i = 0; i < 4; i++)
#pragma unroll
        for (int j = 0; j < 8; j++) acc[i][j] = 0ull;
    float4 pva[2];

    // A fetch for chunk ch into pva
    auto fetchA = [&](int ch) {
        int tap = ch >> 2, ci0 = (ch & 3) * 16;
        int kh = tap / 3, kw = tap - kh * 3;
#pragma unroll
        for (int l = 0; l < 2; l++) {
            int c = ca + 64 * l; int img = c >> 6, pos = c & 63;
            int oh = pos >> 3, ow = pos & 7;
            int ih = oh * 2 + kh - 1, iw = ow * 2 + kw - 1;
            float4 v = make_float4(0.f, 0.f, 0.f, 0.f);
            if ((unsigned)ih < 16u && (unsigned)iw < 16u)
                v = *(const float4*)&g_a1[(((size_t)(b0 + img) * 256) + ih * 16 + iw) * 64 + ci0 + qa * 4];
            pva[l] = v;
        }
    };

    fetchA(0);
    {   // prologue cp.async for chunk 0 B
#pragma unroll
        for (int l = 0; l < 2; l++) {
            int slot = tid + 256 * l;
            int k = slot >> 5, q = slot & 31;
            cpa16(&sB[0][k][q * 4], &g_wT2[(size_t)k * 128 + q * 4]);
        }
        cpa_commit();
    }
    for (int ch = 0; ch < 36; ch++) {
        int cb = ch & 1;
#pragma unroll
        for (int l = 0; l < 2; l++) {
            int c = ca + 64 * l;
            sA[cb][qa * 4 + 0][c] = pva[l].x; sA[cb][qa * 4 + 1][c] = pva[l].y;
            sA[cb][qa * 4 + 2][c] = pva[l].z; sA[cb][qa * 4 + 3][c] = pva[l].w;
        }
        if (ch + 1 < 36) fetchA(ch + 1);
        cpa_wait0();
        __syncthreads();
        if (ch + 1 < 36) {
            int tap = (ch + 1) >> 2, ci0 = ((ch + 1) & 3) * 16;
            int nb = (ch + 1) & 1;
#pragma unroll
            for (int l = 0; l < 2; l++) {
                int slot = tid + 256 * l;
                int k = slot >> 5, q = slot & 31;
                cpa16(&sB[nb][k][q * 4], &g_wT2[(size_t)(tap * 64 + ci0 + k) * 128 + q * 4]);
            }
            cpa_commit();
        }
        MICRO16(sA[cb], sB[cb])
    }
    float bb[8];
    *(float4*)&bb[0] = *(const float4*)&bias[cy * 8];
    *(float4*)&bb[4] = *(const float4*)&bias[cy * 8 + 4];
#pragma unroll
    for (int ip = 0; ip < 4; ip++) {
        float2 v[8];
#pragma unroll
        for (int j = 0; j < 8; j++) v[j] = upk(acc[ip][j]);
        int col0 = px * 8 + 2 * ip;
#pragma unroll
        for (int e = 0; e < 2; e++) {
            int col = col0 + e;
            int img = col >> 6, pos = col & 63;
            float4 o0, o1;
            o0.x = fmaxf((e ? v[0].y : v[0].x) + bb[0], 0.f);
            o0.y = fmaxf((e ? v[1].y : v[1].x) + bb[1], 0.f);
            o0.z = fmaxf((e ? v[2].y : v[2].x) + bb[2], 0.f);
            o0.w = fmaxf((e ? v[3].y : v[3].x) + bb[3], 0.f);
            o1.x = fmaxf((e ? v[4].y : v[4].x) + bb[4], 0.f);
            o1.y = fmaxf((e ? v[5].y : v[5].x) + bb[5], 0.f);
            o1.z = fmaxf((e ? v[6].y : v[6].x) + bb[6], 0.f);
            o1.w = fmaxf((e ? v[7].y : v[7].x) + bb[7], 0.f);
            float* op = &g_a2[(((size_t)(b0 + img) * 64) + pos) * 128 + cy * 8];
            *(float4*)&op[0] = o0;
            *(float4*)&op[4] = o1;
        }
    }
}

// ---------- conv3 GEMM: 8 images x 128 co, K=1152, inline im2col ----------
__global__ __launch_bounds__(256, 2) void conv3_k(const float* __restrict__ bias) {
    __shared__ float sA[2][16][132];
    __shared__ float sB[2][16][128];
    int tid = threadIdx.x;
    int b0 = blockIdx.x * 8;
    int cob = blockIdx.y * 128;
    int px = tid & 15, cy = tid >> 4;
    int qa = tid & 3, ca = tid >> 2;
    u64 acc[4][8];
#pragma unroll
    for (int i = 0; i < 4; i++)
#pragma unroll
        for (int j = 0; j < 8; j++) acc[i][j] = 0ull;
    float4 pva[2];

    auto fetchA = [&](int ch) {
        int tap = ch >> 3, ci0 = (ch & 7) * 16;
        int kh = tap / 3, kw = tap - kh * 3;
#pragma unroll
        for (int l = 0; l < 2; l++) {
            int c = ca + 64 * l; int img = c >> 4, pos = c & 15;
            int oh = pos >> 2, ow = pos & 3;
            int ih = oh * 2 + kh - 1, iw = ow * 2 + kw - 1;
            float4 v = make_float4(0.f, 0.f, 0.f, 0.f);
            if ((unsigned)ih < 8u && (unsigned)iw < 8u)
                v = *(const float4*)&g_a2[(((size_t)(b0 + img) * 64) + ih * 8 + iw) * 128 + ci0 + qa * 4];
            pva[l] = v;
        }
    };

    fetchA(0);
    {
#pragma unroll
        for (int l = 0; l < 2; l++) {
            int slot = tid + 256 * l;
            int k = slot >> 5, q = slot & 31;
            cpa16(&sB[0][k][q * 4], &g_wT3[(size_t)k * 256 + cob + q * 4]);
        }
        cpa_commit();
    }
    for (int ch = 0; ch < 72; ch++) {
        int cb = ch & 1;
#pragma unroll
        for (int l = 0; l < 2; l++) {
            int c = ca + 64 * l;
            sA[cb][qa * 4 + 0][c] = pva[l].x; sA[cb][qa * 4 + 1][c] = pva[l].y;
            sA[cb][qa * 4 + 2][c] = pva[l].z; sA[cb][qa * 4 + 3][c] = pva[l].w;
        }
        if (ch + 1 < 72) fetchA(ch + 1);
        cpa_wait0();
        __syncthreads();
        if (ch + 1 < 72) {
            int tap = (ch + 1) >> 3, ci0 = ((ch + 1) & 7) * 16;
            int nb = (ch + 1) & 1;
#pragma unroll
            for (int l = 0; l < 2; l++) {
                int slot = tid + 256 * l;
                int k = slot >> 5, q = slot & 31;
                cpa16(&sB[nb][k][q * 4], &g_wT3[(size_t)(tap * 128 + ci0 + k) * 256 + cob + q * 4]);
            }
            cpa_commit();
        }
        MICRO16(sA[cb], sB[cb])
    }
    float bb[8];
    *(float4*)&bb[0] = *(const float4*)&bias[cob + cy * 8];
    *(float4*)&bb[4] = *(const float4*)&bias[cob + cy * 8 + 4];
#pragma unroll
    for (int ip = 0; ip < 4; ip++) {
        float2 v[8];
#pragma unroll
        for (int j = 0; j < 8; j++) v[j] = upk(acc[ip][j]);
        int col0 = px * 8 + 2 * ip;
#pragma unroll
        for (int e = 0; e < 2; e++) {
            int col = col0 + e;
            int img = col >> 4, pos = col & 15;
            float4 o0, o1;
            o0.x = fmaxf((e ? v[0].y : v[0].x) + bb[0], 0.f);
            o0.y = fmaxf((e ? v[1].y : v[1].x) + bb[1], 0.f);
            o0.z = fmaxf((e ? v[2].y : v[2].x) + bb[2], 0.f);
            o0.w = fmaxf((e ? v[3].y : v[3].x) + bb[3], 0.f);
            o1.x = fmaxf((e ? v[4].y : v[4].x) + bb[4], 0.f);
            o1.y = fmaxf((e ? v[5].y : v[5].x) + bb[5], 0.f);
            o1.z = fmaxf((e ? v[6].y : v[6].x) + bb[6], 0.f);
            o1.w = fmaxf((e ? v[7].y : v[7].x) + bb[7], 0.f);
            float* op = &g_fea[(((size_t)(b0 + img) * 16) + pos) * 256 + cob + cy * 8];
            *(float4*)&op[0] = o0;
            *(float4*)&op[4] = o1;
        }
    }
}

// ---------- code norms ----------
__global__ void codenorm_k(const float* __restrict__ c0, const float* __restrict__ c1) {
    int c = blockIdx.x * 256 + threadIdx.x;
    const float* cp = (c < 512) ? c0 + (size_t)c * 256 : c1 + (size_t)(c - 512) * 256;
    float s = 0.f;
    for (int k = 0; k < 256; k += 4) {
        float4 v = *(const float4*)&cp[k];
        s += v.x * v.x + v.y * v.y + v.z * v.z + v.w * v.w;
    }
    g_cn[c] = s;
}

// ---------- VQ: 128 rows/block x 128-code tiles, pipelined, db sA ----------
__global__ __launch_bounds__(256, 2) void vq_k(const int* __restrict__ idxp) {
    __shared__ float sA[2][16][132];
    __shared__ float sB[2][16][128];
    int tid = threadIdx.x;
    int rowbase = blockIdx.x * 128;
    int px = tid & 15, cy = tid >> 4;
    int qa = tid & 3, ca = tid >> 2;
    int Kc = (idxp[0] == 0) ? 512 : 1024;
    int total = (Kc >> 7) * 16;               // t = cc>>4, kc = cc&15
    float bv[8]; int bi[8];
#pragma unroll
    for (int i = 0; i < 8; i++) { bv[i] = 1e30f; bi[i] = 0; }
    u64 acc[4][8];
#pragma unroll
    for (int i = 0; i < 4; i++)
#pragma unroll
        for (int j = 0; j < 8; j++) acc[i][j] = 0ull;
    float4 pva[2];

    auto fetchA = [&](int cc) {
        int kc = cc & 15;
#pragma unroll
        for (int l = 0; l < 2; l++) {
            int r = ca + 64 * l;
            pva[l] = *(const float4*)&g_fea[(size_t)(rowbase + r) * 256 + kc * 16 + qa * 4];
        }
    };

    fetchA(0);
    {
#pragma unroll
        for (int l = 0; l < 2; l++) {
            int slot = tid + 256 * l;
            int k = slot >> 5, q = slot & 31;
            cpa16(&sB[0][k][q * 4], &g_cT[(size_t)k * 1024 + q * 4]);
        }
        cpa_commit();
    }
    for (int cc = 0; cc < total; cc++) {
        int cb = cc & 1;
#pragma unroll
        for (int l = 0; l < 2; l++) {
            int r = ca + 64 * l;
            sA[cb][qa * 4 + 0][r] = pva[l].x; sA[cb][qa * 4 + 1][r] = pva[l].y;
            sA[cb][qa * 4 + 2][r] = pva[l].z; sA[cb][qa * 4 + 3][r] = pva[l].w;
        }
        if (cc + 1 < total) fetchA(cc + 1);
        cpa_wait0();
        __syncthreads();
        if (cc + 1 < total) {
            int t = (cc + 1) >> 4, kc = (cc + 1) & 15;
            int nb = (cc + 1) & 1;
#pragma unroll
            for (int l = 0; l < 2; l++) {
                int slot = tid + 256 * l;
                int k = slot >> 5, q = slot & 31;
                cpa16(&sB[nb][k][q * 4], &g_cT[(size_t)(kc * 16 + k) * 1024 + t * 128 + q * 4]);
            }
            cpa_commit();
        }
        MICRO16(sA[cb], sB[cb])
        if ((cc & 15) == 15) {
            int t = cc >> 4;
#pragma unroll
            for (int j = 0; j < 8; j++) {
                int c = t * 128 + cy * 8 + j;
                float cn = g_cn[c];
#pragma unroll
                for (int ip = 0; ip < 4; ip++) {
                    float2 v = upk(acc[ip][j]);
                    float d0 = cn - 2.f * v.x;
                    float d1 = cn - 2.f * v.y;
                    if (d0 < bv[2 * ip])     { bv[2 * ip] = d0;     bi[2 * ip] = c; }
                    if (d1 < bv[2 * ip + 1]) { bv[2 * ip + 1] = d1; bi[2 * ip + 1] = c; }
                }
            }
#pragma unroll
            for (int i = 0; i < 4; i++)
#pragma unroll
                for (int j = 0; j < 8; j++) acc[i][j] = 0ull;
        }
    }
    // final cross-thread reduction (reuse sA/sB space)
    __syncthreads();
    float (*sbv)[16] = (float(*)[16])&sA[0][0][0];
    int   (*sbi)[16] = (int(*)[16])&sB[0][0][0];
#pragma unroll
    for (int l = 0; l < 8; l++) { sbv[px * 8 + l][cy] = bv[l]; sbi[px * 8 + l][cy] = bi[l]; }
    __syncthreads();
    if (tid < 128) {
        float v = sbv[tid][0]; int ii = sbi[tid][0];
#pragma unroll
        for (int q = 1; q < 16; q++) {
            float v2 = sbv[tid][q]; int i2 = sbi[tid][q];
            if (v2 < v || (v2 == v && i2 < ii)) { v = v2; ii = i2; }
        }
        g_eidx[rowbase + tid] = ii;
    }
}

__global__ void zero_hist_k() { g_hist[threadIdx.x] = 0; }

// ---------- loss partials + histogram ----------
__global__ void loss_hist_k(const float* __restrict__ c0, const float* __restrict__ c1) {
    __shared__ float red[256];
    int row = blockIdx.x * 256 + threadIdx.x;
    int e = g_eidx[row];
    atomicAdd(&g_hist[e], 1);
    const float* cp = (e < 512) ? c0 + (size_t)e * 256 : c1 + (size_t)(e - 512) * 256;
    const float* f = g_fea + (size_t)row * 256;
    float s = 0.f;
    for (int k = 0; k < 256; k += 4) {
        float4 q = *(const float4*)&cp[k];
        float4 fv = *(const float4*)&f[k];
        float a = q.x - fv.x, b = q.y - fv.y, c = q.z - fv.z, d = q.w - fv.w;
        s += a * a + b * b + c * c + d * d;
    }
    red[threadIdx.x] = s;
    __syncthreads();
    for (int st = 128; st; st >>= 1) {
        if (threadIdx.x < st) red[threadIdx.x] += red[threadIdx.x + st];
        __syncthreads();
    }
    if (threadIdx.x == 0) g_losspart[blockIdx.x] = red[0];
}

// ---------- P[pos] = codes @ wt[pos] ----------
__global__ __launch_bounds__(256) void ptab_k(const float* __restrict__ c0,
                                              const float* __restrict__ c1) {
    __shared__ float sA[16][68];
    __shared__ float sB[16][68];
    int tid = threadIdx.x;
    int cb = blockIdx.x * 64, nb = blockIdx.y * 64, pos = blockIdx.z;
    int tx = tid & 15, ty = tid >> 4;
    float acc[4][4];
#pragma unroll
    for (int i = 0; i < 4; i++)
#pragma unroll
        for (int j = 0; j < 4; j++) acc[i][j] = 0.f;
    for (int kt = 0; kt < 16; kt++) {
        __syncthreads();
        for (int i = tid; i < 1024; i += 256) {
            int c = i >> 4, k = i & 15;
            int cg = cb + c;
            const float* cp = (cg < 512) ? c0 + (size_t)cg * 256 : c1 + (size_t)(cg - 512) * 256;
            sA[k][c] = cp[kt * 16 + k];
        }
        for (int i = tid; i < 1024; i += 256) {
            int k = i >> 6, n = i & 63;
            sB[k][n] = g_wt[(size_t)((kt * 16 + k) * 16 + pos) * 512 + nb + n];
        }
        __syncthreads();
#pragma unroll
        for (int kk = 0; kk < 16; kk++) {
            float a4[4], b4[4];
            *(float4*)a4 = *(float4*)&sA[kk][ty * 4];
            *(float4*)b4 = *(float4*)&sB[kk][tx * 4];
#pragma unroll
            for (int i = 0; i < 4; i++)
#pragma unroll
                for (int j = 0; j < 4; j++) acc[i][j] = fmaf(a4[i], b4[j], acc[i][j]);
        }
    }
#pragma unroll
    for (int i = 0; i < 4; i++) {
        float4 o = make_float4(acc[i][0], acc[i][1], acc[i][2], acc[i][3]);
        *(float4*)&g_P[((size_t)pos * 1024 + cb + ty * 4 + i) * 512 + nb + tx * 4] = o;
    }
}

// ---------- h = gelu(sum_pos P + b1) ----------
__global__ __launch_bounds__(512) void hgs_k(const float* __restrict__ fb) {
    __shared__ int se[16];
    int b = blockIdx.x, tid = threadIdx.x;
    if (tid < 16) se[tid] = g_eidx[b * 16 + tid];
    __syncthreads();
    float acc = fb[tid];
#pragma unroll
    for (int p = 0; p < 16; p++) acc += g_P[((size_t)p * 1024 + se[p]) * 512 + tid];
    g_h[(size_t)b * 512 + tid] = gelu_t(acc);
}

// ---------- fc2 ----------
__global__ __launch_bounds__(256) void fc2_k(const float* __restrict__ w,
                                             const float* __restrict__ bias,
                                             float* __restrict__ out) {
    __shared__ float sw[10][512];
    __shared__ float sb[10];
    int tid = threadIdx.x;
    for (int i = tid; i < 5120; i += 256) sw[i >> 9][i & 511] = w[i];
    if (tid < 10) sb[tid] = bias[tid];
    __syncthreads();
    int warp = tid >> 5, lane = tid & 31;
    int bimg = blockIdx.x * 8 + warp;
    const float* hr = g_h + (size_t)bimg * 512;
    float acc[10];
#pragma unroll
    for (int m = 0; m < 10; m++) acc[m] = 0.f;
    for (int k = 0; k < 16; k++) {
        float hv = hr[lane + 32 * k];
#pragma unroll
        for (int m = 0; m < 10; m++) acc[m] = fmaf(hv, sw[m][lane + 32 * k], acc[m]);
    }
#pragma unroll
    for (int off = 16; off; off >>= 1)
#pragma unroll
        for (int m = 0; m < 10; m++) acc[m] += __shfl_xor_sync(0xFFFFFFFFu, acc[m], off);
    if (lane < 10) out[(size_t)bimg * 10 + lane] = acc[lane] + sb[lane];
}

// ---------- loss + perplexity ----------
__global__ void losspp_k(float* __restrict__ dout, int osz) {
    __shared__ float red[256];
    int tid = threadIdx.x;
    red[tid] = g_losspart[tid];
    __syncthreads();
    for (int st = 128; st; st >>= 1) {
        if (tid < st) red[tid] += red[tid + st];
        __syncthreads();
    }
    float loss = 1.25f * red[0] / 16777216.0f;
    __syncthreads();
    float s = 0.f;
    for (int i = tid; i < 1024; i += 256) {
        float p = (float)g_hist[i] / 65536.0f;
        if (p > 0.f) s += p * logf(p + 1e-10f);
    }
    red[tid] = s;
    __syncthreads();
    for (int st = 128; st; st >>= 1) {
        if (tid < st) red[tid] += red[tid + st];
        __syncthreads();
    }
    if (tid == 0) { dout[osz - 2] = loss; dout[osz - 1] = expf(-red[0]); }
}

extern "C" void kernel_launch(void* const* d_in, const int* in_sizes, int n_in,
                              void* d_out, int out_size) {
    const float* x     = (const float*)d_in[0];
    const float* w1    = (const float*)d_in[1];
    const float* b1    = (const float*)d_in[2];
    const float* w2    = (const float*)d_in[3];
    const float* b2    = (const float*)d_in[4];
    const float* w3    = (const float*)d_in[5];
    const float* b3    = (const float*)d_in[6];
    const float* code0 = (const float*)d_in[7];
    const float* code1 = (const float*)d_in[8];
    const float* fc1w  = (const float*)d_in[9];
    const float* fc1b  = (const float*)d_in[10];
    const float* fc2w  = (const float*)d_in[11];
    const float* fc2b  = (const float*)d_in[12];
    const int*   idxp  = (const int*)d_in[13];
    float* out = (float*)d_out;

    // conv2_k stays at our launch #3 (ncu -s 5 lands there after 2 harness launches).
    conv1_k<<<4096, 256>>>(x, w1, b1);                    // 0
    wt2_k<<<576, 128>>>(w2);                              // 1
    wt3_k<<<1152, 256>>>(w3);                             // 2
    conv2_k<<<2048, 256>>>(b2);                           // 3  <-- profile target
    conv3_k<<<dim3(512, 2), 256>>>(b3);                   // 4
    ct_k<<<256, 256>>>(code0, code1);                     // 5
    codenorm_k<<<4, 256>>>(code0, code1);                 // 6
    vq_k<<<512, 256>>>(idxp);                             // 7
    zero_hist_k<<<1, 1024>>>();                           // 8
    loss_hist_k<<<256, 256>>>(code0, code1);              // 9
    wtT_k<<<dim3(128, 16), 256>>>(fc1w);                  // 10
    ptab_k<<<dim3(16, 8, 16), 256>>>(code0, code1);       // 11
    hgs_k<<<4096, 512>>>(fc1b);                           // 12
    fc2_k<<<512, 256>>>(fc2w, fc2b, out);                 // 13
    losspp_k<<<1, 256>>>(out, out_size);                  // 14
}

// round 9
// speedup vs baseline: 21.2326x; 1.1330x over previous
#include <cuda_runtime.h>
#include <math.h>

typedef unsigned long long u64;

// ------------------ scratch (__device__ globals; no allocation) ------------------
__device__ float g_a1[4096 * 256 * 64];       // conv1 out NHWC [B,16x16,64]
__device__ float g_a2[4096 * 64 * 128];       // conv2 out NHWC [B,8x8,128]
__device__ float g_fea[4096 * 16 * 256];      // conv3 out NHWC rows (VQ input)
__device__ float g_wT2[576 * 128];            // conv2 weights k-major [tap*64+ci][co]
__device__ float g_wT3[1152 * 256];           // conv3 weights k-major [tap*128+ci][co]
__device__ float g_cT[256 * 1024];            // codes k-major [k][code]
__device__ float g_wt[4096 * 512];            // fc1_w transposed [c'][n], c' = c*16+pos
__device__ float g_P[16 * 1024 * 512];        // P[pos][code][n]
__device__ float g_h[4096 * 512];             // fc1+gelu output
__device__ int   g_eidx[65536];
__device__ float g_cn[1024];
__device__ int   g_hist[1024];
__device__ float g_losspart[256];

__device__ __forceinline__ float gelu_t(float x) {
    float x3 = x * x * x;
    float t = tanhf(0.7978845608028654f * (x + 0.044715f * x3));
    return 0.5f * x * (1.0f + t);
}

// ---- packed f32x2 helpers ----
__device__ __forceinline__ u64 pk2(float lo, float hi) {
    u64 r; asm("mov.b64 %0, {%1, %2};" : "=l"(r) : "f"(lo), "f"(hi)); return r;
}
__device__ __forceinline__ void ffma2(u64& d, u64 a, u64 b) {
    asm("fma.rn.f32x2 %0, %1, %2, %0;" : "+l"(d) : "l"(a), "l"(b));
}
__device__ __forceinline__ float2 upk(u64 v) {
    float2 r; asm("mov.b64 {%0, %1}, %2;" : "=f"(r.x), "=f"(r.y) : "l"(v)); return r;
}

// ---- cp.async helpers ----
__device__ __forceinline__ void cpa16(void* smem_dst, const void* gmem_src) {
    unsigned d = (unsigned)__cvta_generic_to_shared(smem_dst);
    asm volatile("cp.async.ca.shared.global [%0], [%1], 16;" :: "r"(d), "l"(gmem_src));
}
__device__ __forceinline__ void cpa_commit() { asm volatile("cp.async.commit_group;"); }
__device__ __forceinline__ void cpa_wait0()  { asm volatile("cp.async.wait_group 0;" ::: "memory"); }

// ---------- conv1 ----------
__global__ __launch_bounds__(256) void conv1_k(const float* __restrict__ x,
                                               const float* __restrict__ w,
                                               const float* __restrict__ bias) {
    __shared__ float sw1[27][64];
    __shared__ float sb1[64];
    int tid = threadIdx.x, b = blockIdx.x;
    for (int i = tid; i < 1728; i += 256) { int co = i & 63, t = i >> 6; sw1[t][co] = w[co * 27 + t]; }
    if (tid < 64) sb1[tid] = bias[tid];
    __syncthreads();
    int oh = tid >> 4, ow = tid & 15;
    const float* xb = x + (size_t)b * 3072;
    float in[27];
#pragma unroll
    for (int c = 0; c < 3; c++)
#pragma unroll
        for (int kh = 0; kh < 3; kh++)
#pragma unroll
            for (int kw = 0; kw < 3; kw++) {
                int ih = oh * 2 + kh - 1, iw = ow * 2 + kw - 1;
                float v = 0.f;
                if ((unsigned)ih < 32u && (unsigned)iw < 32u) v = xb[(c * 32 + ih) * 32 + iw];
                in[(c * 3 + kh) * 3 + kw] = v;
            }
    float* ob = g_a1 + ((size_t)b * 256 + tid) * 64;
#pragma unroll
    for (int cq = 0; cq < 16; cq++) {
        float a0 = sb1[cq * 4], a1 = sb1[cq * 4 + 1], a2 = sb1[cq * 4 + 2], a3 = sb1[cq * 4 + 3];
#pragma unroll
        for (int t = 0; t < 27; t++) {
            float4 wv = *(float4*)&sw1[t][cq * 4];
            a0 = fmaf(in[t], wv.x, a0); a1 = fmaf(in[t], wv.y, a1);
            a2 = fmaf(in[t], wv.z, a2); a3 = fmaf(in[t], wv.w, a3);
        }
        float4 o; o.x = fmaxf(a0, 0.f); o.y = fmaxf(a1, 0.f); o.z = fmaxf(a2, 0.f); o.w = fmaxf(a3, 0.f);
        *(float4*)&ob[cq * 4] = o;
    }
}

// ---------- weight/code transposes ----------
__global__ void wt2_k(const float* __restrict__ w) {
    int k = blockIdx.x, co = threadIdx.x;
    int tap = k >> 6, ci = k & 63;
    g_wT2[k * 128 + co] = w[co * 576 + ci * 9 + tap];
}
__global__ void wt3_k(const float* __restrict__ w) {
    int k = blockIdx.x, co = threadIdx.x;
    int tap = k / 128, ci = k % 128;
    g_wT3[k * 256 + co] = w[co * 1152 + ci * 9 + tap];
}
__global__ void ct_k(const float* __restrict__ c0, const float* __restrict__ c1) {
    int k = blockIdx.x;
    for (int c = threadIdx.x; c < 1024; c += 256)
        g_cT[k * 1024 + c] = (c < 512) ? c0[(size_t)c * 256 + k] : c1[(size_t)(c - 512) * 256 + k];
}
// fc1_w [512n][4096c'] -> g_wt [4096c'][512n]
__global__ __launch_bounds__(256) void wtT_k(const float* __restrict__ w) {
    __shared__ float t[32][33];
    int bx = blockIdx.x, by = blockIdx.y;
    int tx = threadIdx.x & 31, ty = threadIdx.x >> 5;
#pragma unroll
    for (int i = 0; i < 4; i++)
        t[ty + 8 * i][tx] = w[(size_t)(by * 32 + ty + 8 * i) * 4096 + bx * 32 + tx];
    __syncthreads();
#pragma unroll
    for (int i = 0; i < 4; i++)
        g_wt[(size_t)(bx * 32 + ty + 8 * i) * 512 + by * 32 + tx] = t[tx][ty + 8 * i];
}

// ---- 16-k FFMA2 microkernel; A fragment = cols {px*4..+3, 64+px*4..+3} (bank-conflict-free) ----
#define MICRO16(SA, SB)                                                          \
    _Pragma("unroll")                                                            \
    for (int k = 0; k < 16; k++) {                                               \
        float4 a0 = *(float4*)&SA[k][px * 4];                                    \
        float4 a1 = *(float4*)&SA[k][64 + px * 4];                               \
        float4 w0 = *(float4*)&SB[k][cy * 8];                                    \
        float4 w1 = *(float4*)&SB[k][cy * 8 + 4];                                \
        u64 ap[4] = {pk2(a0.x, a0.y), pk2(a0.z, a0.w), pk2(a1.x, a1.y), pk2(a1.z, a1.w)}; \
        u64 bd[8] = {pk2(w0.x, w0.x), pk2(w0.y, w0.y), pk2(w0.z, w0.z), pk2(w0.w, w0.w),  \
                     pk2(w1.x, w1.x), pk2(w1.y, w1.y), pk2(w1.z, w1.z), pk2(w1.w, w1.w)}; \
        _Pragma("unroll")                                                        \
        for (int ip = 0; ip < 4; ip++)                                           \
            _Pragma("unroll")                                                    \
            for (int j = 0; j < 8; j++) ffma2(acc[ip][j], ap[ip], bd[j]);        \
    }
// local column for (ip, e): ip<2 -> px*4 + 2*ip + e ; ip>=2 -> 64 + px*4 + 2*(ip-2) + e
#define COL_OF(ip, e) (((ip) < 2) ? (px * 4 + 2 * (ip) + (e)) : (64 + px * 4 + 2 * ((ip) - 2) + (e)))

// ---------- conv2 GEMM: 2 images/block, C[128col,128co], K=576, inline im2col ----------
__global__ __launch_bounds__(256, 2) void conv2_k(const float* __restrict__ bias) {
    __shared__ float sA[2][16][132];
    __shared__ float sB[2][16][128];
    int tid = threadIdx.x;
    int b0 = blockIdx.x * 2;
    int px = tid & 15, cy = tid >> 4;
    int qa = tid & 3, ca = tid >> 2;
    u64 acc[4][8];
#pragma unroll
    for (int i = 0; i < 4; i++)
#pragma unroll
        for (int j = 0; j < 8; j++) acc[i][j] = 0ull;
    float4 pva[2];

    auto fetchA = [&](int ch) {
        int tap = ch >> 2, ci0 = (ch & 3) * 16;
        int kh = tap / 3, kw = tap - kh * 3;
#pragma unroll
        for (int l = 0; l < 2; l++) {
            int c = ca + 64 * l; int img = c >> 6, pos = c & 63;
            int oh = pos >> 3, ow = pos & 7;
            int ih = oh * 2 + kh - 1, iw = ow * 2 + kw - 1;
            float4 v = make_float4(0.f, 0.f, 0.f, 0.f);
            if ((unsigned)ih < 16u && (unsigned)iw < 16u)
                v = *(const float4*)&g_a1[(((size_t)(b0 + img) * 256) + ih * 16 + iw) * 64 + ci0 + qa * 4];
            pva[l] = v;
        }
    };

    fetchA(0);
    {
#pragma unroll
        for (int l = 0; l < 2; l++) {
            int slot = tid + 256 * l;
            int k = slot >> 5, q = slot & 31;
            cpa16(&sB[0][k][q * 4], &g_wT2[(size_t)k * 128 + q * 4]);
        }
        cpa_commit();
    }
    for (int ch = 0; ch < 36; ch++) {
        int cb = ch & 1;
#pragma unroll
        for (int l = 0; l < 2; l++) {
            int c = ca + 64 * l;
            sA[cb][qa * 4 + 0][c] = pva[l].x; sA[cb][qa * 4 + 1][c] = pva[l].y;
            sA[cb][qa * 4 + 2][c] = pva[l].z; sA[cb][qa * 4 + 3][c] = pva[l].w;
        }
        if (ch + 1 < 36) fetchA(ch + 1);
        cpa_wait0();
        __syncthreads();
        if (ch + 1 < 36) {
            int tap = (ch + 1) >> 2, ci0 = ((ch + 1) & 3) * 16;
            int nb = (ch + 1) & 1;
#pragma unroll
            for (int l = 0; l < 2; l++) {
                int slot = tid + 256 * l;
                int k = slot >> 5, q = slot & 31;
                cpa16(&sB[nb][k][q * 4], &g_wT2[(size_t)(tap * 64 + ci0 + k) * 128 + q * 4]);
            }
            cpa_commit();
        }
        MICRO16(sA[cb], sB[cb])
    }
    float bb[8];
    *(float4*)&bb[0] = *(const float4*)&bias[cy * 8];
    *(float4*)&bb[4] = *(const float4*)&bias[cy * 8 + 4];
#pragma unroll
    for (int ip = 0; ip < 4; ip++) {
        float2 v[8];
#pragma unroll
        for (int j = 0; j < 8; j++) v[j] = upk(acc[ip][j]);
#pragma unroll
        for (int e = 0; e < 2; e++) {
            int col = COL_OF(ip, e);
            int img = col >> 6, pos = col & 63;
            float4 o0, o1;
            o0.x = fmaxf((e ? v[0].y : v[0].x) + bb[0], 0.f);
            o0.y = fmaxf((e ? v[1].y : v[1].x) + bb[1], 0.f);
            o0.z = fmaxf((e ? v[2].y : v[2].x) + bb[2], 0.f);
            o0.w = fmaxf((e ? v[3].y : v[3].x) + bb[3], 0.f);
            o1.x = fmaxf((e ? v[4].y : v[4].x) + bb[4], 0.f);
            o1.y = fmaxf((e ? v[5].y : v[5].x) + bb[5], 0.f);
            o1.z = fmaxf((e ? v[6].y : v[6].x) + bb[6], 0.f);
            o1.w = fmaxf((e ? v[7].y : v[7].x) + bb[7], 0.f);
            float* op = &g_a2[(((size_t)(b0 + img) * 64) + pos) * 128 + cy * 8];
            *(float4*)&op[0] = o0;
            *(float4*)&op[4] = o1;
        }
    }
}

// ---------- conv3 GEMM: 8 images x 128 co, K=1152, inline im2col ----------
__global__ __launch_bounds__(256, 2) void conv3_k(const float* __restrict__ bias) {
    __shared__ float sA[2][16][132];
    __shared__ float sB[2][16][128];
    int tid = threadIdx.x;
    int b0 = blockIdx.x * 8;
    int cob = blockIdx.y * 128;
    int px = tid & 15, cy = tid >> 4;
    int qa = tid & 3, ca = tid >> 2;
    u64 acc[4][8];
#pragma unroll
    for (int i = 0; i < 4; i++)
#pragma unroll
        for (int j = 0; j < 8; j++) acc[i][j] = 0ull;
    float4 pva[2];

    auto fetchA = [&](int ch) {
        int tap = ch >> 3, ci0 = (ch & 7) * 16;
        int kh = tap / 3, kw = tap - kh * 3;
#pragma unroll
        for (int l = 0; l < 2; l++) {
            int c = ca + 64 * l; int img = c >> 4, pos = c & 15;
            int oh = pos >> 2, ow = pos & 3;
            int ih = oh * 2 + kh - 1, iw = ow * 2 + kw - 1;
            float4 v = make_float4(0.f, 0.f, 0.f, 0.f);
            if ((unsigned)ih < 8u && (unsigned)iw < 8u)
                v = *(const float4*)&g_a2[(((size_t)(b0 + img) * 64) + ih * 8 + iw) * 128 + ci0 + qa * 4];
            pva[l] = v;
        }
    };

    fetchA(0);
    {
#pragma unroll
        for (int l = 0; l < 2; l++) {
            int slot = tid + 256 * l;
            int k = slot >> 5, q = slot & 31;
            cpa16(&sB[0][k][q * 4], &g_wT3[(size_t)k * 256 + cob + q * 4]);
        }
        cpa_commit();
    }
    for (int ch = 0; ch < 72; ch++) {
        int cb = ch & 1;
#pragma unroll
        for (int l = 0; l < 2; l++) {
            int c = ca + 64 * l;
            sA[cb][qa * 4 + 0][c] = pva[l].x; sA[cb][qa * 4 + 1][c] = pva[l].y;
            sA[cb][qa * 4 + 2][c] = pva[l].z; sA[cb][qa * 4 + 3][c] = pva[l].w;
        }
        if (ch + 1 < 72) fetchA(ch + 1);
        cpa_wait0();
        __syncthreads();
        if (ch + 1 < 72) {
            int tap = (ch + 1) >> 3, ci0 = ((ch + 1) & 7) * 16;
            int nb = (ch + 1) & 1;
#pragma unroll
            for (int l = 0; l < 2; l++) {
                int slot = tid + 256 * l;
                int k = slot >> 5, q = slot & 31;
                cpa16(&sB[nb][k][q * 4], &g_wT3[(size_t)(tap * 128 + ci0 + k) * 256 + cob + q * 4]);
            }
            cpa_commit();
        }
        MICRO16(sA[cb], sB[cb])
    }
    float bb[8];
    *(float4*)&bb[0] = *(const float4*)&bias[cob + cy * 8];
    *(float4*)&bb[4] = *(const float4*)&bias[cob + cy * 8 + 4];
#pragma unroll
    for (int ip = 0; ip < 4; ip++) {
        float2 v[8];
#pragma unroll
        for (int j = 0; j < 8; j++) v[j] = upk(acc[ip][j]);
#pragma unroll
        for (int e = 0; e < 2; e++) {
            int col = COL_OF(ip, e);
            int img = col >> 4, pos = col & 15;
            float4 o0, o1;
            o0.x = fmaxf((e ? v[0].y : v[0].x) + bb[0], 0.f);
            o0.y = fmaxf((e ? v[1].y : v[1].x) + bb[1], 0.f);
            o0.z = fmaxf((e ? v[2].y : v[2].x) + bb[2], 0.f);
            o0.w = fmaxf((e ? v[3].y : v[3].x) + bb[3], 0.f);
            o1.x = fmaxf((e ? v[4].y : v[4].x) + bb[4], 0.f);
            o1.y = fmaxf((e ? v[5].y : v[5].x) + bb[5], 0.f);
            o1.z = fmaxf((e ? v[6].y : v[6].x) + bb[6], 0.f);
            o1.w = fmaxf((e ? v[7].y : v[7].x) + bb[7], 0.f);
            float* op = &g_fea[(((size_t)(b0 + img) * 16) + pos) * 256 + cob + cy * 8];
            *(float4*)&op[0] = o0;
            *(float4*)&op[4] = o1;
        }
    }
}

// ---------- code norms ----------
__global__ void codenorm_k(const float* __restrict__ c0, const float* __restrict__ c1) {
    int c = blockIdx.x * 256 + threadIdx.x;
    const float* cp = (c < 512) ? c0 + (size_t)c * 256 : c1 + (size_t)(c - 512) * 256;
    float s = 0.f;
    for (int k = 0; k < 256; k += 4) {
        float4 v = *(const float4*)&cp[k];
        s += v.x * v.x + v.y * v.y + v.z * v.z + v.w * v.w;
    }
    g_cn[c] = s;
}

// ---------- VQ: 128 rows/block x 128-code tiles, pipelined ----------
__global__ __launch_bounds__(256, 2) void vq_k(const int* __restrict__ idxp) {
    __shared__ float sA[2][16][132];
    __shared__ float sB[2][16][128];
    int tid = threadIdx.x;
    int rowbase = blockIdx.x * 128;
    int px = tid & 15, cy = tid >> 4;
    int qa = tid & 3, ca = tid >> 2;
    int Kc = (idxp[0] == 0) ? 512 : 1024;
    int total = (Kc >> 7) * 16;               // t = cc>>4, kc = cc&15
    float bv[8]; int bi[8];
#pragma unroll
    for (int i = 0; i < 8; i++) { bv[i] = 1e30f; bi[i] = 0; }
    u64 acc[4][8];
#pragma unroll
    for (int i = 0; i < 4; i++)
#pragma unroll
        for (int j = 0; j < 8; j++) acc[i][j] = 0ull;
    float4 pva[2];

    auto fetchA = [&](int cc) {
        int kc = cc & 15;
#pragma unroll
        for (int l = 0; l < 2; l++) {
            int r = ca + 64 * l;
            pva[l] = *(const float4*)&g_fea[(size_t)(rowbase + r) * 256 + kc * 16 + qa * 4];
        }
    };

    fetchA(0);
    {
#pragma unroll
        for (int l = 0; l < 2; l++) {
            int slot = tid + 256 * l;
            int k = slot >> 5, q = slot & 31;
            cpa16(&sB[0][k][q * 4], &g_cT[(size_t)k * 1024 + q * 4]);
        }
        cpa_commit();
    }
    for (int cc = 0; cc < total; cc++) {
        int cb = cc & 1;
#pragma unroll
        for (int l = 0; l < 2; l++) {
            int r = ca + 64 * l;
            sA[cb][qa * 4 + 0][r] = pva[l].x; sA[cb][qa * 4 + 1][r] = pva[l].y;
            sA[cb][qa * 4 + 2][r] = pva[l].z; sA[cb][qa * 4 + 3][r] = pva[l].w;
        }
        if (cc + 1 < total) fetchA(cc + 1);
        cpa_wait0();
        __syncthreads();
        if (cc + 1 < total) {
            int t = (cc + 1) >> 4, kc = (cc + 1) & 15;
            int nb = (cc + 1) & 1;
#pragma unroll
            for (int l = 0; l < 2; l++) {
                int slot = tid + 256 * l;
                int k = slot >> 5, q = slot & 31;
                cpa16(&sB[nb][k][q * 4], &g_cT[(size_t)(kc * 16 + k) * 1024 + t * 128 + q * 4]);
            }
            cpa_commit();
        }
        MICRO16(sA[cb], sB[cb])
        if ((cc & 15) == 15) {
            int t = cc >> 4;
#pragma unroll
            for (int j = 0; j < 8; j++) {
                int c = t * 128 + cy * 8 + j;
                float cn = g_cn[c];
#pragma unroll
                for (int ip = 0; ip < 4; ip++) {
                    float2 v = upk(acc[ip][j]);
                    float d0 = cn - 2.f * v.x;
                    float d1 = cn - 2.f * v.y;
                    if (d0 < bv[2 * ip])     { bv[2 * ip] = d0;     bi[2 * ip] = c; }
                    if (d1 < bv[2 * ip + 1]) { bv[2 * ip + 1] = d1; bi[2 * ip + 1] = c; }
                }
            }
#pragma unroll
            for (int i = 0; i < 4; i++)
#pragma unroll
                for (int j = 0; j < 8; j++) acc[i][j] = 0ull;
        }
    }
    // final cross-thread reduction (reuse sA/sB space); bv[2*ip+e] <-> row COL_OF(ip,e)
    __syncthreads();
    float (*sbv)[16] = (float(*)[16])&sA[0][0][0];
    int   (*sbi)[16] = (int(*)[16])&sB[0][0][0];
#pragma unroll
    for (int ip = 0; ip < 4; ip++)
#pragma unroll
        for (int e = 0; e < 2; e++) {
            int row = COL_OF(ip, e);
            sbv[row][cy] = bv[2 * ip + e];
            sbi[row][cy] = bi[2 * ip + e];
        }
    __syncthreads();
    if (tid < 128) {
        float v = sbv[tid][0]; int ii = sbi[tid][0];
#pragma unroll
        for (int q = 1; q < 16; q++) {
            float v2 = sbv[tid][q]; int i2 = sbi[tid][q];
            if (v2 < v || (v2 == v && i2 < ii)) { v = v2; ii = i2; }
        }
        g_eidx[rowbase + tid] = ii;
    }
}

__global__ void zero_hist_k() { g_hist[threadIdx.x] = 0; }

// ---------- loss partials + histogram ----------
__global__ void loss_hist_k(const float* __restrict__ c0, const float* __restrict__ c1) {
    __shared__ float red[256];
    int row = blockIdx.x * 256 + threadIdx.x;
    int e = g_eidx[row];
    atomicAdd(&g_hist[e], 1);
    const float* cp = (e < 512) ? c0 + (size_t)e * 256 : c1 + (size_t)(e - 512) * 256;
    const float* f = g_fea + (size_t)row * 256;
    float s = 0.f;
    for (int k = 0; k < 256; k += 4) {
        float4 q = *(const float4*)&cp[k];
        float4 fv = *(const float4*)&f[k];
        float a = q.x - fv.x, b = q.y - fv.y, c = q.z - fv.z, d = q.w - fv.w;
        s += a * a + b * b + c * c + d * d;
    }
    red[threadIdx.x] = s;
    __syncthreads();
    for (int st = 128; st; st >>= 1) {
        if (threadIdx.x < st) red[threadIdx.x] += red[threadIdx.x + st];
        __syncthreads();
    }
    if (threadIdx.x == 0) g_losspart[blockIdx.x] = red[0];
}

// ---------- P[pos] = codes @ wt[pos] ----------
__global__ __launch_bounds__(256) void ptab_k(const float* __restrict__ c0,
                                              const float* __restrict__ c1) {
    __shared__ float sA[16][68];
    __shared__ float sB[16][68];
    int tid = threadIdx.x;
    int cb = blockIdx.x * 64, nb = blockIdx.y * 64, pos = blockIdx.z;
    int tx = tid & 15, ty = tid >> 4;
    float acc[4][4];
#pragma unroll
    for (int i = 0; i < 4; i++)
#pragma unroll
        for (int j = 0; j < 4; j++) acc[i][j] = 0.f;
    for (int kt = 0; kt < 16; kt++) {
        __syncthreads();
        for (int i = tid; i < 1024; i += 256) {
            int c = i >> 4, k = i & 15;
            int cg = cb + c;
            const float* cp = (cg < 512) ? c0 + (size_t)cg * 256 : c1 + (size_t)(cg - 512) * 256;
            sA[k][c] = cp[kt * 16 + k];
        }
        for (int i = tid; i < 1024; i += 256) {
            int k = i >> 6, n = i & 63;
            sB[k][n] = g_wt[(size_t)((kt * 16 + k) * 16 + pos) * 512 + nb + n];
        }
        __syncthreads();
#pragma unroll
        for (int kk = 0; kk < 16; kk++) {
            float a4[4], b4[4];
            *(float4*)a4 = *(float4*)&sA[kk][ty * 4];
            *(float4*)b4 = *(float4*)&sB[kk][tx * 4];
#pragma unroll
            for (int i = 0; i < 4; i++)
#pragma unroll
                for (int j = 0; j < 4; j++) acc[i][j] = fmaf(a4[i], b4[j], acc[i][j]);
        }
    }
#pragma unroll
    for (int i = 0; i < 4; i++) {
        float4 o = make_float4(acc[i][0], acc[i][1], acc[i][2], acc[i][3]);
        *(float4*)&g_P[((size_t)pos * 1024 + cb + ty * 4 + i) * 512 + nb + tx * 4] = o;
    }
}

// ---------- h = gelu(sum_pos P + b1) ----------
__global__ __launch_bounds__(512) void hgs_k(const float* __restrict__ fb) {
    __shared__ int se[16];
    int b = blockIdx.x, tid = threadIdx.x;
    if (tid < 16) se[tid] = g_eidx[b * 16 + tid];
    __syncthreads();
    float acc = fb[tid];
#pragma unroll
    for (int p = 0; p < 16; p++) acc += g_P[((size_t)p * 1024 + se[p]) * 512 + tid];
    g_h[(size_t)b * 512 + tid] = gelu_t(acc);
}

// ---------- fc2 ----------
__global__ __launch_bounds__(256) void fc2_k(const float* __restrict__ w,
                                             const float* __restrict__ bias,
                                             float* __restrict__ out) {
    __shared__ float sw[10][512];
    __shared__ float sb[10];
    int tid = threadIdx.x;
    for (int i = tid; i < 5120; i += 256) sw[i >> 9][i & 511] = w[i];
    if (tid < 10) sb[tid] = bias[tid];
    __syncthreads();
    int warp = tid >> 5, lane = tid & 31;
    int bimg = blockIdx.x * 8 + warp;
    const float* hr = g_h + (size_t)bimg * 512;
    float acc[10];
#pragma unroll
    for (int m = 0; m < 10; m++) acc[m] = 0.f;
    for (int k = 0; k < 16; k++) {
        float hv = hr[lane + 32 * k];
#pragma unroll
        for (int m = 0; m < 10; m++) acc[m] = fmaf(hv, sw[m][lane + 32 * k], acc[m]);
    }
#pragma unroll
    for (int off = 16; off; off >>= 1)
#pragma unroll
        for (int m = 0; m < 10; m++) acc[m] += __shfl_xor_sync(0xFFFFFFFFu, acc[m], off);
    if (lane < 10) out[(size_t)bimg * 10 + lane] = acc[lane] + sb[lane];
}

// ---------- loss + perplexity ----------
__global__ void losspp_k(float* __restrict__ dout, int osz) {
    __shared__ float red[256];
    int tid = threadIdx.x;
    red[tid] = g_losspart[tid];
    __syncthreads();
    for (int st = 128; st; st >>= 1) {
        if (tid < st) red[tid] += red[tid + st];
        __syncthreads();
    }
    float loss = 1.25f * red[0] / 16777216.0f;
    __syncthreads();
    float s = 0.f;
    for (int i = tid; i < 1024; i += 256) {
        float p = (float)g_hist[i] / 65536.0f;
        if (p > 0.f) s += p * logf(p + 1e-10f);
    }
    red[tid] = s;
    __syncthreads();
    for (int st = 128; st; st >>= 1) {
        if (tid < st) red[tid] += red[tid + st];
        __syncthreads();
    }
    if (tid == 0) { dout[osz - 2] = loss; dout[osz - 1] = expf(-red[0]); }
}

extern "C" void kernel_launch(void* const* d_in, const int* in_sizes, int n_in,
                              void* d_out, int out_size) {
    const float* x     = (const float*)d_in[0];
    const float* w1    = (const float*)d_in[1];
    const float* b1    = (const float*)d_in[2];
    const float* w2    = (const float*)d_in[3];
    const float* b2    = (const float*)d_in[4];
    const float* w3    = (const float*)d_in[5];
    const float* b3    = (const float*)d_in[6];
    const float* code0 = (const float*)d_in[7];
    const float* code1 = (const float*)d_in[8];
    const float* fc1w  = (const float*)d_in[9];
    const float* fc1b  = (const float*)d_in[10];
    const float* fc2w  = (const float*)d_in[11];
    const float* fc2b  = (const float*)d_in[12];
    const int*   idxp  = (const int*)d_in[13];
    float* out = (float*)d_out;

    // conv2_k stays at our launch #3 (ncu -s 5 lands there after 2 harness launches).
    conv1_k<<<4096, 256>>>(x, w1, b1);                    // 0
    wt2_k<<<576, 128>>>(w2);                              // 1
    wt3_k<<<1152, 256>>>(w3);                             // 2
    conv2_k<<<2048, 256>>>(b2);                           // 3  <-- profile target
    conv3_k<<<dim3(512, 2), 256>>>(b3);                   // 4
    ct_k<<<256, 256>>>(code0, code1);                     // 5
    codenorm_k<<<4, 256>>>(code0, code1);                 // 6
    vq_k<<<512, 256>>>(idxp);                             // 7
    zero_hist_k<<<1, 1024>>>();                           // 8
    loss_hist_k<<<256, 256>>>(code0, code1);              // 9
    wtT_k<<<dim3(128, 16), 256>>>(fc1w);                  // 10
    ptab_k<<<dim3(16, 8, 16), 256>>>(code0, code1);       // 11
    hgs_k<<<4096, 512>>>(fc1b);                           // 12
    fc2_k<<<512, 256>>>(fc2w, fc2b, out);                 // 13
    losspp_k<<<1, 256>>>(out, out_size);                  // 14
}

// round 11
// speedup vs baseline: 23.1388x; 1.0898x over previous
#include <cuda_runtime.h>
#include <cuda_bf16.h>
#include <math.h>

typedef unsigned long long u64;

// ------------------ scratch (__device__ globals; no allocation) ------------------
__device__ float g_a1[4096 * 256 * 64];       // conv1 out NHWC [B,16x16,64]
__device__ __nv_bfloat16 g_a1h[4096 * 256 * 64];  // a1 hi bf16
__device__ __nv_bfloat16 g_a1l[4096 * 256 * 64];  // a1 lo bf16
__device__ __nv_bfloat16 g_wB2h[9 * 128 * 64];    // conv2 w hi [tap][co][ci]
__device__ __nv_bfloat16 g_wB2l[9 * 128 * 64];    // conv2 w lo
__device__ float g_a2[4096 * 64 * 128];       // conv2 out NHWC [B,8x8,128]
__device__ float g_fea[4096 * 16 * 256];      // conv3 out NHWC rows (VQ input)
__device__ float g_wT3[1152 * 256];           // conv3 weights k-major [tap*128+ci][co]
__device__ float g_cT[256 * 1024];            // codes k-major [k][code]
__device__ float g_wt[4096 * 512];            // fc1_w transposed [c'][n], c' = c*16+pos
__device__ float g_P[16 * 1024 * 512];        // P[pos][code][n]
__device__ float g_h[4096 * 512];             // fc1+gelu output
__device__ int   g_eidx[65536];
__device__ float g_cn[1024];
__device__ int   g_hist[1024];
__device__ float g_losspart[256];

__device__ __forceinline__ float gelu_t(float x) {
    float x3 = x * x * x;
    float t = tanhf(0.7978845608028654f * (x + 0.044715f * x3));
    return 0.5f * x * (1.0f + t);
}

// ---- packed f32x2 helpers ----
__device__ __forceinline__ u64 pk2(float lo, float hi) {
    u64 r; asm("mov.b64 %0, {%1, %2};" : "=l"(r) : "f"(lo), "f"(hi)); return r;
}
__device__ __forceinline__ void ffma2(u64& d, u64 a, u64 b) {
    asm("fma.rn.f32x2 %0, %1, %2, %0;" : "+l"(d) : "l"(a), "l"(b));
}
__device__ __forceinline__ float2 upk(u64 v) {
    float2 r; asm("mov.b64 {%0, %1}, %2;" : "=f"(r.x), "=f"(r.y) : "l"(v)); return r;
}

// ---- cp.async helpers ----
__device__ __forceinline__ void cpa16(void* smem_dst, const void* gmem_src) {
    unsigned d = (unsigned)__cvta_generic_to_shared(smem_dst);
    asm volatile("cp.async.ca.shared.global [%0], [%1], 16;" :: "r"(d), "l"(gmem_src));
}
__device__ __forceinline__ void cpa16z(void* smem_dst, const void* gmem_src, int srcbytes) {
    unsigned d = (unsigned)__cvta_generic_to_shared(smem_dst);
    asm volatile("cp.async.ca.shared.global [%0], [%1], 16, %2;" :: "r"(d), "l"(gmem_src), "r"(srcbytes));
}
__device__ __forceinline__ void cpa_commit() { asm volatile("cp.async.commit_group;"); }
__device__ __forceinline__ void cpa_wait0()  { asm volatile("cp.async.wait_group 0;" ::: "memory"); }

// ---- bf16 HMMA (sm_80+, compiles for plain compute_103) ----
__device__ __forceinline__ void hmma(float* c, const unsigned* a, const unsigned* b) {
    asm volatile(
        "mma.sync.aligned.m16n8k16.row.col.f32.bf16.bf16.f32 "
        "{%0,%1,%2,%3}, {%4,%5,%6,%7}, {%8,%9}, {%0,%1,%2,%3};\n"
        : "+f"(c[0]), "+f"(c[1]), "+f"(c[2]), "+f"(c[3])
        : "r"(a[0]), "r"(a[1]), "r"(a[2]), "r"(a[3]), "r"(b[0]), "r"(b[1]));
}

// ---------- conv1 ----------
__global__ __launch_bounds__(256) void conv1_k(const float* __restrict__ x,
                                               const float* __restrict__ w,
                                               const float* __restrict__ bias) {
    __shared__ float sw1[27][64];
    __shared__ float sb1[64];
    int tid = threadIdx.x, b = blockIdx.x;
    for (int i = tid; i < 1728; i += 256) { int co = i & 63, t = i >> 6; sw1[t][co] = w[co * 27 + t]; }
    if (tid < 64) sb1[tid] = bias[tid];
    __syncthreads();
    int oh = tid >> 4, ow = tid & 15;
    const float* xb = x + (size_t)b * 3072;
    float in[27];
#pragma unroll
    for (int c = 0; c < 3; c++)
#pragma unroll
        for (int kh = 0; kh < 3; kh++)
#pragma unroll
            for (int kw = 0; kw < 3; kw++) {
                int ih = oh * 2 + kh - 1, iw = ow * 2 + kw - 1;
                float v = 0.f;
                if ((unsigned)ih < 32u && (unsigned)iw < 32u) v = xb[(c * 32 + ih) * 32 + iw];
                in[(c * 3 + kh) * 3 + kw] = v;
            }
    float* ob = g_a1 + ((size_t)b * 256 + tid) * 64;
#pragma unroll
    for (int cq = 0; cq < 16; cq++) {
        float a0 = sb1[cq * 4], a1 = sb1[cq * 4 + 1], a2 = sb1[cq * 4 + 2], a3 = sb1[cq * 4 + 3];
#pragma unroll
        for (int t = 0; t < 27; t++) {
            float4 wv = *(float4*)&sw1[t][cq * 4];
            a0 = fmaf(in[t], wv.x, a0); a1 = fmaf(in[t], wv.y, a1);
            a2 = fmaf(in[t], wv.z, a2); a3 = fmaf(in[t], wv.w, a3);
        }
        float4 o; o.x = fmaxf(a0, 0.f); o.y = fmaxf(a1, 0.f); o.z = fmaxf(a2, 0.f); o.w = fmaxf(a3, 0.f);
        *(float4*)&ob[cq * 4] = o;
    }
}

// ---------- a1 -> bf16 hi/lo ----------
__global__ __launch_bounds__(256) void cvt_a1_k() {
    int b = blockIdx.x, tid = threadIdx.x;
    const float* src = g_a1 + (size_t)b * 16384;
    __nv_bfloat16* dh = g_a1h + (size_t)b * 16384;
    __nv_bfloat16* dl = g_a1l + (size_t)b * 16384;
#pragma unroll
    for (int l = 0; l < 16; l++) {
        int idx = tid + 256 * l;
        float4 v = *(const float4*)&src[idx * 4];
        __nv_bfloat16 h[4], lo[4];
        float vv[4] = {v.x, v.y, v.z, v.w};
#pragma unroll
        for (int i = 0; i < 4; i++) {
            h[i] = __float2bfloat16(vv[i]);
            lo[i] = __float2bfloat16(vv[i] - __bfloat162float(h[i]));
        }
        *(uint2*)&dh[idx * 4] = *(uint2*)h;
        *(uint2*)&dl[idx * 4] = *(uint2*)lo;
    }
}

// ---------- conv2 weights -> bf16 hi/lo, [tap][co][ci] ----------
__global__ __launch_bounds__(256) void cvt_w2_k(const float* __restrict__ w) {
    int tap = blockIdx.x, tid = threadIdx.x;
    for (int i = tid; i < 8192; i += 256) {
        int co = i >> 6, ci = i & 63;
        float v = w[(size_t)co * 576 + ci * 9 + tap];
        __nv_bfloat16 h = __float2bfloat16(v);
        g_wB2h[tap * 8192 + i] = h;
        g_wB2l[tap * 8192 + i] = __float2bfloat16(v - __bfloat162float(h));
    }
}

// ---------- conv2 via bf16 split HMMA: 2 images/block, C[128row,128co], K=576 ----------
// dyn smem: sAh/sAl/sBh/sBl each [2buf][128][40] bf16 (pitch 40 el = 80B) = 20480B each; total 81920B
__global__ __launch_bounds__(512) void conv2_k(const float* __restrict__ bias) {
    extern __shared__ __nv_bfloat16 smem_bf[];
    __nv_bfloat16* base[4] = {smem_bf, smem_bf + 10240, smem_bf + 20480, smem_bf + 30720};
    int tid = threadIdx.x;
    int b0 = blockIdx.x * 2;
    int lane = tid & 31, wrp = tid >> 5;
    int g = lane >> 2, t = lane & 3;
    int mw = (wrp & 3) * 32, nw = (wrp >> 2) * 32;
    float acc[2][4][4];
#pragma unroll
    for (int mt = 0; mt < 2; mt++)
#pragma unroll
        for (int nt = 0; nt < 4; nt++)
#pragma unroll
            for (int i = 0; i < 4; i++) acc[mt][nt][i] = 0.f;

    // stage chunk ch (tap = ch>>1, ci0 = (ch&1)*32) into buffer buf
    auto stage = [&](int ch, int buf) {
        int tap = ch >> 1, ci0 = (ch & 1) * 32;
        int kh = tap / 3, kw = tap - kh * 3;
#pragma unroll
        for (int l = 0; l < 4; l++) {
            int gi = tid + 512 * l;               // 0..2047
            int arr = gi >> 9;                    // 0:Ah 1:Al 2:Bh 3:Bl
            int rem = gi & 511;
            int row = rem >> 2, q = rem & 3;      // row 0..127, q = 16B granule (8 bf16)
            __nv_bfloat16* dst = base[arr] + buf * 5120 + row * 40 + q * 8;
            if (arr < 2) {
                int img = row >> 6, pos = row & 63;
                int oh = pos >> 3, ow = pos & 7;
                int ih = oh * 2 + kh - 1, iw = ow * 2 + kw - 1;
                int ok = ((unsigned)ih < 16u && (unsigned)iw < 16u) ? 16 : 0;
                size_t si = ok ? ((((size_t)(b0 + img) * 256) + ih * 16 + iw) * 64 + ci0 + q * 8) : 0;
                const __nv_bfloat16* src = (arr ? g_a1l : g_a1h) + si;
                cpa16z(dst, src, ok);
            } else {
                const __nv_bfloat16* src = ((arr == 3) ? g_wB2l : g_wB2h)
                                           + (size_t)tap * 8192 + row * 64 + ci0 + q * 8;
                cpa16(dst, src);
            }
        }
        cpa_commit();
    };

    stage(0, 0);
    for (int ch = 0; ch < 18; ch++) {
        int cb = ch & 1;
        cpa_wait0();
        __syncthreads();
        if (ch + 1 < 18) stage(ch + 1, cb ^ 1);
#pragma unroll
        for (int ks = 0; ks < 2; ks++) {
            int kc = ks * 16 + t * 2;
            unsigned ah[2][4], al[2][4], bh[4][2], bl[4][2];
#pragma unroll
            for (int mt = 0; mt < 2; mt++) {
                int r = mw + mt * 16 + g;
                const __nv_bfloat16* ph = base[0] + cb * 5120 + r * 40;
                const __nv_bfloat16* pl = base[1] + cb * 5120 + r * 40;
                ah[mt][0] = *(const unsigned*)(ph + kc);
                ah[mt][1] = *(const unsigned*)(ph + 8 * 40 + kc);
                ah[mt][2] = *(const unsigned*)(ph + kc + 8);
                ah[mt][3] = *(const unsigned*)(ph + 8 * 40 + kc + 8);
                al[mt][0] = *(const unsigned*)(pl + kc);
                al[mt][1] = *(const unsigned*)(pl + 8 * 40 + kc);
                al[mt][2] = *(const unsigned*)(pl + kc + 8);
                al[mt][3] = *(const unsigned*)(pl + 8 * 40 + kc + 8);
            }
#pragma unroll
            for (int nt = 0; nt < 4; nt++) {
                int n = nw + nt * 8 + g;
                const __nv_bfloat16* ph = base[2] + cb * 5120 + n * 40;
                const __nv_bfloat16* pl = base[3] + cb * 5120 + n * 40;
                bh[nt][0] = *(const unsigned*)(ph + kc);
                bh[nt][1] = *(const unsigned*)(ph + kc + 8);
                bl[nt][0] = *(const unsigned*)(pl + kc);
                bl[nt][1] = *(const unsigned*)(pl + kc + 8);
            }
#pragma unroll
            for (int mt = 0; mt < 2; mt++)
#pragma unroll
                for (int nt = 0; nt < 4; nt++) {
                    hmma(acc[mt][nt], ah[mt], bh[nt]);
                    hmma(acc[mt][nt], ah[mt], bl[nt]);
                    hmma(acc[mt][nt], al[mt], bh[nt]);
                }
        }
    }
    // epilogue: bias + relu, direct stores
    float2 bb[4];
#pragma unroll
    for (int nt = 0; nt < 4; nt++) bb[nt] = *(const float2*)&bias[nw + nt * 8 + t * 2];
#pragma unroll
    for (int mt = 0; mt < 2; mt++) {
        int r0 = mw + mt * 16 + g;
        int img0 = r0 >> 6, pos0 = r0 & 63;
        int r1 = r0 + 8;
        int img1 = r1 >> 6, pos1 = r1 & 63;
        float* op0 = &g_a2[(((size_t)(b0 + img0) * 64) + pos0) * 128];
        float* op1 = &g_a2[(((size_t)(b0 + img1) * 64) + pos1) * 128];
#pragma unroll
        for (int nt = 0; nt < 4; nt++) {
            int c0 = nw + nt * 8 + t * 2;
            float2 v0, v1;
            v0.x = fmaxf(acc[mt][nt][0] + bb[nt].x, 0.f);
            v0.y = fmaxf(acc[mt][nt][1] + bb[nt].y, 0.f);
            v1.x = fmaxf(acc[mt][nt][2] + bb[nt].x, 0.f);
            v1.y = fmaxf(acc[mt][nt][3] + bb[nt].y, 0.f);
            *(float2*)&op0[c0] = v0;
            *(float2*)&op1[c0] = v1;
        }
    }
}

// ---------- weight/code transposes ----------
__global__ void wt3_k(const float* __restrict__ w) {
    int k = blockIdx.x, co = threadIdx.x;
    int tap = k / 128, ci = k % 128;
    g_wT3[k * 256 + co] = w[co * 1152 + ci * 9 + tap];
}
__global__ void ct_k(const float* __restrict__ c0, const float* __restrict__ c1) {
    int k = blockIdx.x;
    for (int c = threadIdx.x; c < 1024; c += 256)
        g_cT[k * 1024 + c] = (c < 512) ? c0[(size_t)c * 256 + k] : c1[(size_t)(c - 512) * 256 + k];
}
__global__ __launch_bounds__(256) void wtT_k(const float* __restrict__ w) {
    __shared__ float t[32][33];
    int bx = blockIdx.x, by = blockIdx.y;
    int tx = threadIdx.x & 31, ty = threadIdx.x >> 5;
#pragma unroll
    for (int i = 0; i < 4; i++)
        t[ty + 8 * i][tx] = w[(size_t)(by * 32 + ty + 8 * i) * 4096 + bx * 32 + tx];
    __syncthreads();
#pragma unroll
    for (int i = 0; i < 4; i++)
        g_wt[(size_t)(bx * 32 + ty + 8 * i) * 512 + by * 32 + tx] = t[tx][ty + 8 * i];
}

// ---- 16-k FFMA2 microkernel; A fragment = cols {px*4..+3, 64+px*4..+3} ----
#define MICRO16(SA, SB)                                                          \
    _Pragma("unroll")                                                            \
    for (int k = 0; k < 16; k++) {                                               \
        float4 a0 = *(float4*)&SA[k][px * 4];                                    \
        float4 a1 = *(float4*)&SA[k][64 + px * 4];                               \
        float4 w0 = *(float4*)&SB[k][cy * 8];                                    \
        float4 w1 = *(float4*)&SB[k][cy * 8 + 4];                                \
        u64 ap[4] = {pk2(a0.x, a0.y), pk2(a0.z, a0.w), pk2(a1.x, a1.y), pk2(a1.z, a1.w)}; \
        u64 bd[8] = {pk2(w0.x, w0.x), pk2(w0.y, w0.y), pk2(w0.z, w0.z), pk2(w0.w, w0.w),  \
                     pk2(w1.x, w1.x), pk2(w1.y, w1.y), pk2(w1.z, w1.z), pk2(w1.w, w1.w)}; \
        _Pragma("unroll")                                                        \
        for (int ip = 0; ip < 4; ip++)                                           \
            _Pragma("unroll")                                                    \
            for (int j = 0; j < 8; j++) ffma2(acc[ip][j], ap[ip], bd[j]);        \
    }
#define COL_OF(ip, e) (((ip) < 2) ? (px * 4 + 2 * (ip) + (e)) : (64 + px * 4 + 2 * ((ip) - 2) + (e)))

// ---------- conv3 GEMM: 8 images x 128 co, K=1152, inline im2col ----------
__global__ __launch_bounds__(256, 2) void conv3_k(const float* __restrict__ bias) {
    __shared__ float sA[2][16][132];
    __shared__ float sB[2][16][128];
    int tid = threadIdx.x;
    int b0 = blockIdx.x * 8;
    int cob = blockIdx.y * 128;
    int px = tid & 15, cy = tid >> 4;
    int qa = tid & 3, ca = tid >> 2;
    u64 acc[4][8];
#pragma unroll
    for (int i = 0; i < 4; i++)
#pragma unroll
        for (int j = 0; j < 8; j++) acc[i][j] = 0ull;
    float4 pva[2];

    auto fetchA = [&](int ch) {
        int tap = ch >> 3, ci0 = (ch & 7) * 16;
        int kh = tap / 3, kw = tap - kh * 3;
#pragma unroll
        for (int l = 0; l < 2; l++) {
            int c = ca + 64 * l; int img = c >> 4, pos = c & 15;
            int oh = pos >> 2, ow = pos & 3;
            int ih = oh * 2 + kh - 1, iw = ow * 2 + kw - 1;
            float4 v = make_float4(0.f, 0.f, 0.f, 0.f);
            if ((unsigned)ih < 8u && (unsigned)iw < 8u)
                v = *(const float4*)&g_a2[(((size_t)(b0 + img) * 64) + ih * 8 + iw) * 128 + ci0 + qa * 4];
            pva[l] = v;
        }
    };

    fetchA(0);
    {
#pragma unroll
        for (int l = 0; l < 2; l++) {
            int slot = tid + 256 * l;
            int k = slot >> 5, q = slot & 31;
            cpa16(&sB[0][k][q * 4], &g_wT3[(size_t)k * 256 + cob + q * 4]);
        }
        cpa_commit();
    }
    for (int ch = 0; ch < 72; ch++) {
        int cb = ch & 1;
#pragma unroll
        for (int l = 0; l < 2; l++) {
            int c = ca + 64 * l;
            sA[cb][qa * 4 + 0][c] = pva[l].x; sA[cb][qa * 4 + 1][c] = pva[l].y;
            sA[cb][qa * 4 + 2][c] = pva[l].z; sA[cb][qa * 4 + 3][c] = pva[l].w;
        }
        if (ch + 1 < 72) fetchA(ch + 1);
        cpa_wait0();
        __syncthreads();
        if (ch + 1 < 72) {
            int tap = (ch + 1) >> 3, ci0 = ((ch + 1) & 7) * 16;
            int nb = (ch + 1) & 1;
#pragma unroll
            for (int l = 0; l < 2; l++) {
                int slot = tid + 256 * l;
                int k = slot >> 5, q = slot & 31;
                cpa16(&sB[nb][k][q * 4], &g_wT3[(size_t)(tap * 128 + ci0 + k) * 256 + cob + q * 4]);
            }
            cpa_commit();
        }
        MICRO16(sA[cb], sB[cb])
    }
    float bb[8];
    *(float4*)&bb[0] = *(const float4*)&bias[cob + cy * 8];
    *(float4*)&bb[4] = *(const float4*)&bias[cob + cy * 8 + 4];
#pragma unroll
    for (int ip = 0; ip < 4; ip++) {
        float2 v[8];
#pragma unroll
        for (int j = 0; j < 8; j++) v[j] = upk(acc[ip][j]);
#pragma unroll
        for (int e = 0; e < 2; e++) {
            int col = COL_OF(ip, e);
            int img = col >> 4, pos = col & 15;
            float4 o0, o1;
            o0.x = fmaxf((e ? v[0].y : v[0].x) + bb[0], 0.f);
            o0.y = fmaxf((e ? v[1].y : v[1].x) + bb[1], 0.f);
            o0.z = fmaxf((e ? v[2].y : v[2].x) + bb[2], 0.f);
            o0.w = fmaxf((e ? v[3].y : v[3].x) + bb[3], 0.f);
            o1.x = fmaxf((e ? v[4].y : v[4].x) + bb[4], 0.f);
            o1.y = fmaxf((e ? v[5].y : v[5].x) + bb[5], 0.f);
            o1.z = fmaxf((e ? v[6].y : v[6].x) + bb[6], 0.f);
            o1.w = fmaxf((e ? v[7].y : v[7].x) + bb[7], 0.f);
            float* op = &g_fea[(((size_t)(b0 + img) * 16) + pos) * 256 + cob + cy * 8];
            *(float4*)&op[0] = o0;
            *(float4*)&op[4] = o1;
        }
    }
}

// ---------- code norms ----------
__global__ void codenorm_k(const float* __restrict__ c0, const float* __restrict__ c1) {
    int c = blockIdx.x * 256 + threadIdx.x;
    const float* cp = (c < 512) ? c0 + (size_t)c * 256 : c1 + (size_t)(c - 512) * 256;
    float s = 0.f;
    for (int k = 0; k < 256; k += 4) {
        float4 v = *(const float4*)&cp[k];
        s += v.x * v.x + v.y * v.y + v.z * v.z + v.w * v.w;
    }
    g_cn[c] = s;
}

// ---------- VQ: 128 rows/block x 128-code tiles, pipelined ----------
__global__ __launch_bounds__(256, 2) void vq_k(const int* __restrict__ idxp) {
    __shared__ float sA[2][16][132];
    __shared__ float sB[2][16][128];
    int tid = threadIdx.x;
    int rowbase = blockIdx.x * 128;
    int px = tid & 15, cy = tid >> 4;
    int qa = tid & 3, ca = tid >> 2;
    int Kc = (idxp[0] == 0) ? 512 : 1024;
    int total = (Kc >> 7) * 16;
    float bv[8]; int bi[8];
#pragma unroll
    for (int i = 0; i < 8; i++) { bv[i] = 1e30f; bi[i] = 0; }
    u64 acc[4][8];
#pragma unroll
    for (int i = 0; i < 4; i++)
#pragma unroll
        for (int j = 0; j < 8; j++) acc[i][j] = 0ull;
    float4 pva[2];

    auto fetchA = [&](int cc) {
        int kc = cc & 15;
#pragma unroll
        for (int l = 0; l < 2; l++) {
            int r = ca + 64 * l;
            pva[l] = *(const float4*)&g_fea[(size_t)(rowbase + r) * 256 + kc * 16 + qa * 4];
        }
    };

    fetchA(0);
    {
#pragma unroll
        for (int l = 0; l < 2; l++) {
            int slot = tid + 256 * l;
            int k = slot >> 5, q = slot & 31;
            cpa16(&sB[0][k][q * 4], &g_cT[(size_t)k * 1024 + q * 4]);
        }
        cpa_commit();
    }
    for (int cc = 0; cc < total; cc++) {
        int cb = cc & 1;
#pragma unroll
        for (int l = 0; l < 2; l++) {
            int r = ca + 64 * l;
            sA[cb][qa * 4 + 0][r] = pva[l].x; sA[cb][qa * 4 + 1][r] = pva[l].y;
            sA[cb][qa * 4 + 2][r] = pva[l].z; sA[cb][qa * 4 + 3][r] = pva[l].w;
        }
        if (cc + 1 < total) fetchA(cc + 1);
        cpa_wait0();
        __syncthreads();
        if (cc + 1 < total) {
            int t = (cc + 1) >> 4, kc = (cc + 1) & 15;
            int nb = (cc + 1) & 1;
#pragma unroll
            for (int l = 0; l < 2; l++) {
                int slot = tid + 256 * l;
                int k = slot >> 5, q = slot & 31;
                cpa16(&sB[nb][k][q * 4], &g_cT[(size_t)(kc * 16 + k) * 1024 + t * 128 + q * 4]);
            }
            cpa_commit();
        }
        MICRO16(sA[cb], sB[cb])
        if ((cc & 15) == 15) {
            int t = cc >> 4;
#pragma unroll
            for (int j = 0; j < 8; j++) {
                int c = t * 128 + cy * 8 + j;
                float cn = g_cn[c];
#pragma unroll
                for (int ip = 0; ip < 4; ip++) {
                    float2 v = upk(acc[ip][j]);
                    float d0 = cn - 2.f * v.x;
                    float d1 = cn - 2.f * v.y;
                    if (d0 < bv[2 * ip])     { bv[2 * ip] = d0;     bi[2 * ip] = c; }
                    if (d1 < bv[2 * ip + 1]) { bv[2 * ip + 1] = d1; bi[2 * ip + 1] = c; }
                }
            }
#pragma unroll
            for (int i = 0; i < 4; i++)
#pragma unroll
                for (int j = 0; j < 8; j++) acc[i][j] = 0ull;
        }
    }
    __syncthreads();
    float (*sbv)[16] = (float(*)[16])&sA[0][0][0];
    int   (*sbi)[16] = (int(*)[16])&sB[0][0][0];
#pragma unroll
    for (int ip = 0; ip < 4; ip++)
#pragma unroll
        for (int e = 0; e < 2; e++) {
            int row = COL_OF(ip, e);
            sbv[row][cy] = bv[2 * ip + e];
            sbi[row][cy] = bi[2 * ip + e];
        }
    __syncthreads();
    if (tid < 128) {
        float v = sbv[tid][0]; int ii = sbi[tid][0];
#pragma unroll
        for (int q = 1; q < 16; q++) {
            float v2 = sbv[tid][q]; int i2 = sbi[tid][q];
            if (v2 < v || (v2 == v && i2 < ii)) { v = v2; ii = i2; }
        }
        g_eidx[rowbase + tid] = ii;
    }
}

__global__ void zero_hist_k() { g_hist[threadIdx.x] = 0; }

// ---------- loss partials + histogram ----------
__global__ void loss_hist_k(const float* __restrict__ c0, const float* __restrict__ c1) {
    __shared__ float red[256];
    int row = blockIdx.x * 256 + threadIdx.x;
    int e = g_eidx[row];
    atomicAdd(&g_hist[e], 1);
    const float* cp = (e < 512) ? c0 + (size_t)e * 256 : c1 + (size_t)(e - 512) * 256;
    const float* f = g_fea + (size_t)row * 256;
    float s = 0.f;
    for (int k = 0; k < 256; k += 4) {
        float4 q = *(const float4*)&cp[k];
        float4 fv = *(const float4*)&f[k];
        float a = q.x - fv.x, b = q.y - fv.y, c = q.z - fv.z, d = q.w - fv.w;
        s += a * a + b * b + c * c + d * d;
    }
    red[threadIdx.x] = s;
    __syncthreads();
    for (int st = 128; st; st >>= 1) {
        if (threadIdx.x < st) red[threadIdx.x] += red[threadIdx.x + st];
        __syncthreads();
    }
    if (threadIdx.x == 0) g_losspart[blockIdx.x] = red[0];
}

// ---------- P[pos] = codes @ wt[pos] ----------
__global__ __launch_bounds__(256) void ptab_k(const float* __restrict__ c0,
                                              const float* __restrict__ c1) {
    __shared__ float sA[16][68];
    __shared__ float sB[16][68];
    int tid = threadIdx.x;
    int cb = blockIdx.x * 64, nb = blockIdx.y * 64, pos = blockIdx.z;
    int tx = tid & 15, ty = tid >> 4;
    float acc[4][4];
#pragma unroll
    for (int i = 0; i < 4; i++)
#pragma unroll
        for (int j = 0; j < 4; j++) acc[i][j] = 0.f;
    for (int kt = 0; kt < 16; kt++) {
        __syncthreads();
        for (int i = tid; i < 1024; i += 256) {
            int c = i >> 4, k = i & 15;
            int cg = cb + c;
            const float* cp = (cg < 512) ? c0 + (size_t)cg * 256 : c1 + (size_t)(cg - 512) * 256;
            sA[k][c] = cp[kt * 16 + k];
        }
        for (int i = tid; i < 1024; i += 256) {
            int k = i >> 6, n = i & 63;
            sB[k][n] = g_wt[(size_t)((kt * 16 + k) * 16 + pos) * 512 + nb + n];
        }
        __syncthreads();
#pragma unroll
        for (int kk = 0; kk < 16; kk++) {
            float a4[4], b4[4];
            *(float4*)a4 = *(float4*)&sA[kk][ty * 4];
            *(float4*)b4 = *(float4*)&sB[kk][tx * 4];
#pragma unroll
            for (int i = 0; i < 4; i++)
#pragma unroll
                for (int j = 0; j < 4; j++) acc[i][j] = fmaf(a4[i], b4[j], acc[i][j]);
        }
    }
#pragma unroll
    for (int i = 0; i < 4; i++) {
        float4 o = make_float4(acc[i][0], acc[i][1], acc[i][2], acc[i][3]);
        *(float4*)&g_P[((size_t)pos * 1024 + cb + ty * 4 + i) * 512 + nb + tx * 4] = o;
    }
}

// ---------- h = gelu(sum_pos P + b1) ----------
__global__ __launch_bounds__(512) void hgs_k(const float* __restrict__ fb) {
    __shared__ int se[16];
    int b = blockIdx.x, tid = threadIdx.x;
    if (tid < 16) se[tid] = g_eidx[b * 16 + tid];
    __syncthreads();
    float acc = fb[tid];
#pragma unroll
    for (int p = 0; p < 16; p++) acc += g_P[((size_t)p * 1024 + se[p]) * 512 + tid];
    g_h[(size_t)b * 512 + tid] = gelu_t(acc);
}

// ---------- fc2 ----------
__global__ __launch_bounds__(256) void fc2_k(const float* __restrict__ w,
                                             const float* __restrict__ bias,
                                             float* __restrict__ out) {
    __shared__ float sw[10][512];
    __shared__ float sb[10];
    int tid = threadIdx.x;
    for (int i = tid; i < 5120; i += 256) sw[i >> 9][i & 511] = w[i];
    if (tid < 10) sb[tid] = bias[tid];
    __syncthreads();
    int warp = tid >> 5, lane = tid & 31;
    int bimg = blockIdx.x * 8 + warp;
    const float* hr = g_h + (size_t)bimg * 512;
    float acc[10];
#pragma unroll
    for (int m = 0; m < 10; m++) acc[m] = 0.f;
    for (int k = 0; k < 16; k++) {
        float hv = hr[lane + 32 * k];
#pragma unroll
        for (int m = 0; m < 10; m++) acc[m] = fmaf(hv, sw[m][lane + 32 * k], acc[m]);
    }
#pragma unroll
    for (int off = 16; off; off >>= 1)
#pragma unroll
        for (int m = 0; m < 10; m++) acc[m] += __shfl_xor_sync(0xFFFFFFFFu, acc[m], off);
    if (lane < 10) out[(size_t)bimg * 10 + lane] = acc[lane] + sb[lane];
}

// ---------- loss + perplexity ----------
__global__ void losspp_k(float* __restrict__ dout, int osz) {
    __shared__ float red[256];
    int tid = threadIdx.x;
    red[tid] = g_losspart[tid];
    __syncthreads();
    for (int st = 128; st; st >>= 1) {
        if (tid < st) red[tid] += red[tid + st];
        __syncthreads();
    }
    float loss = 1.25f * red[0] / 16777216.0f;
    __syncthreads();
    float s = 0.f;
    for (int i = tid; i < 1024; i += 256) {
        float p = (float)g_hist[i] / 65536.0f;
        if (p > 0.f) s += p * logf(p + 1e-10f);
    }
    red[tid] = s;
    __syncthreads();
    for (int st = 128; st; st >>= 1) {
        if (tid < st) red[tid] += red[tid + st];
        __syncthreads();
    }
    if (tid == 0) { dout[osz - 2] = loss; dout[osz - 1] = expf(-red[0]); }
}

extern "C" void kernel_launch(void* const* d_in, const int* in_sizes, int n_in,
                              void* d_out, int out_size) {
    const float* x     = (const float*)d_in[0];
    const float* w1    = (const float*)d_in[1];
    const float* b1    = (const float*)d_in[2];
    const float* w2    = (const float*)d_in[3];
    const float* b2    = (const float*)d_in[4];
    const float* w3    = (const float*)d_in[5];
    const float* b3    = (const float*)d_in[6];
    const float* code0 = (const float*)d_in[7];
    const float* code1 = (const float*)d_in[8];
    const float* fc1w  = (const float*)d_in[9];
    const float* fc1b  = (const float*)d_in[10];
    const float* fc2w  = (const float*)d_in[11];
    const float* fc2b  = (const float*)d_in[12];
    const int*   idxp  = (const int*)d_in[13];
    float* out = (float*)d_out;

    cudaFuncSetAttribute(conv2_k, cudaFuncAttributeMaxDynamicSharedMemorySize, 81920);

    // conv2_k stays at our launch #3 (ncu -s 5 lands there after 2 harness launches).
    conv1_k<<<4096, 256>>>(x, w1, b1);                    // 0
    cvt_w2_k<<<9, 256>>>(w2);                             // 1
    cvt_a1_k<<<4096, 256>>>();                            // 2
    conv2_k<<<2048, 512, 81920>>>(b2);                    // 3  <-- profile target (HMMA)
    wt3_k<<<1152, 256>>>(w3);                             // 4
    conv3_k<<<dim3(512, 2), 256>>>(b3);                   // 5
    ct_k<<<256, 256>>>(code0, code1);                     // 6
    codenorm_k<<<4, 256>>>(code0, code1);                 // 7
    vq_k<<<512, 256>>>(idxp);                             // 8
    zero_hist_k<<<1, 1024>>>();                           // 9
    loss_hist_k<<<256, 256>>>(code0, code1);              // 10
    wtT_k<<<dim3(128, 16), 256>>>(fc1w);                  // 11
    ptab_k<<<dim3(16, 8, 16), 256>>>(code0, code1);       // 12
    hgs_k<<<4096, 512>>>(fc1b);                           // 13
    fc2_k<<<512, 256>>>(fc2w, fc2b, out);                 // 14
    losspp_k<<<1, 256>>>(out, out_size);                  // 15
}

// round 12
// speedup vs baseline: 29.5847x; 1.2786x over previous
#include <cuda_runtime.h>
#include <cuda_bf16.h>
#include <math.h>

typedef unsigned long long u64;

// ------------------ scratch (__device__ globals; no allocation) ------------------
__device__ float g_a1[4096 * 256 * 64];       // conv1 out NHWC [B,16x16,64]
__device__ __nv_bfloat16 g_a1h[4096 * 256 * 64];
__device__ __nv_bfloat16 g_a1l[4096 * 256 * 64];
__device__ __nv_bfloat16 g_wB2h[9 * 128 * 64];    // conv2 w [tap][co][ci]
__device__ __nv_bfloat16 g_wB2l[9 * 128 * 64];
__device__ float g_a2[4096 * 64 * 128];       // conv2 out NHWC [B,8x8,128]
__device__ __nv_bfloat16 g_a2h[4096 * 64 * 128];
__device__ __nv_bfloat16 g_a2l[4096 * 64 * 128];
__device__ __nv_bfloat16 g_wB3h[9 * 256 * 128];   // conv3 w [tap][co][ci]
__device__ __nv_bfloat16 g_wB3l[9 * 256 * 128];
__device__ float g_fea[4096 * 16 * 256];      // conv3 out NHWC rows (VQ input)
__device__ __nv_bfloat16 g_feah[4096 * 16 * 256];
__device__ __nv_bfloat16 g_feal[4096 * 16 * 256];
__device__ __nv_bfloat16 g_cdh[1024 * 256];       // codes bf16 hi [code][k]
__device__ __nv_bfloat16 g_cdl[1024 * 256];
__device__ float g_wt[4096 * 512];            // fc1_w transposed [c'][n], c' = c*16+pos
__device__ float g_P[16 * 1024 * 512];        // P[pos][code][n]
__device__ float g_h[4096 * 512];             // fc1+gelu output
__device__ int   g_eidx[65536];
__device__ float g_cn[1024];
__device__ int   g_hist[1024];
__device__ float g_losspart[256];

__device__ __forceinline__ float gelu_t(float x) {
    float x3 = x * x * x;
    float t = tanhf(0.7978845608028654f * (x + 0.044715f * x3));
    return 0.5f * x * (1.0f + t);
}

// ---- cp.async helpers ----
__device__ __forceinline__ void cpa16(void* smem_dst, const void* gmem_src) {
    unsigned d = (unsigned)__cvta_generic_to_shared(smem_dst);
    asm volatile("cp.async.ca.shared.global [%0], [%1], 16;" :: "r"(d), "l"(gmem_src));
}
__device__ __forceinline__ void cpa16z(void* smem_dst, const void* gmem_src, int srcbytes) {
    unsigned d = (unsigned)__cvta_generic_to_shared(smem_dst);
    asm volatile("cp.async.ca.shared.global [%0], [%1], 16, %2;" :: "r"(d), "l"(gmem_src), "r"(srcbytes));
}
__device__ __forceinline__ void cpa_commit() { asm volatile("cp.async.commit_group;"); }
__device__ __forceinline__ void cpa_wait0()  { asm volatile("cp.async.wait_group 0;" ::: "memory"); }

// ---- bf16 HMMA ----
__device__ __forceinline__ void hmma(float* c, const unsigned* a, const unsigned* b) {
    asm volatile(
        "mma.sync.aligned.m16n8k16.row.col.f32.bf16.bf16.f32 "
        "{%0,%1,%2,%3}, {%4,%5,%6,%7}, {%8,%9}, {%0,%1,%2,%3};\n"
        : "+f"(c[0]), "+f"(c[1]), "+f"(c[2]), "+f"(c[3])
        : "r"(a[0]), "r"(a[1]), "r"(a[2]), "r"(a[3]), "r"(b[0]), "r"(b[1]));
}

// ---------- conv1 ----------
__global__ __launch_bounds__(256) void conv1_k(const float* __restrict__ x,
                                               const float* __restrict__ w,
                                               const float* __restrict__ bias) {
    __shared__ float sw1[27][64];
    __shared__ float sb1[64];
    int tid = threadIdx.x, b = blockIdx.x;
    for (int i = tid; i < 1728; i += 256) { int co = i & 63, t = i >> 6; sw1[t][co] = w[co * 27 + t]; }
    if (tid < 64) sb1[tid] = bias[tid];
    __syncthreads();
    int oh = tid >> 4, ow = tid & 15;
    const float* xb = x + (size_t)b * 3072;
    float in[27];
#pragma unroll
    for (int c = 0; c < 3; c++)
#pragma unroll
        for (int kh = 0; kh < 3; kh++)
#pragma unroll
            for (int kw = 0; kw < 3; kw++) {
                int ih = oh * 2 + kh - 1, iw = ow * 2 + kw - 1;
                float v = 0.f;
                if ((unsigned)ih < 32u && (unsigned)iw < 32u) v = xb[(c * 32 + ih) * 32 + iw];
                in[(c * 3 + kh) * 3 + kw] = v;
            }
    float* ob = g_a1 + ((size_t)b * 256 + tid) * 64;
#pragma unroll
    for (int cq = 0; cq < 16; cq++) {
        float a0 = sb1[cq * 4], a1 = sb1[cq * 4 + 1], a2 = sb1[cq * 4 + 2], a3 = sb1[cq * 4 + 3];
#pragma unroll
        for (int t = 0; t < 27; t++) {
            float4 wv = *(float4*)&sw1[t][cq * 4];
            a0 = fmaf(in[t], wv.x, a0); a1 = fmaf(in[t], wv.y, a1);
            a2 = fmaf(in[t], wv.z, a2); a3 = fmaf(in[t], wv.w, a3);
        }
        float4 o; o.x = fmaxf(a0, 0.f); o.y = fmaxf(a1, 0.f); o.z = fmaxf(a2, 0.f); o.w = fmaxf(a3, 0.f);
        *(float4*)&ob[cq * 4] = o;
    }
}

// ---------- fp32 -> bf16 hi/lo converters ----------
__device__ __forceinline__ void cvt_block(const float* src, __nv_bfloat16* dh,
                                          __nv_bfloat16* dl, int nquads, int tid, int nthr) {
    for (int idx = tid; idx < nquads; idx += nthr) {
        float4 v = *(const float4*)&src[idx * 4];
        __nv_bfloat16 h[4], lo[4];
        float vv[4] = {v.x, v.y, v.z, v.w};
#pragma unroll
        for (int i = 0; i < 4; i++) {
            h[i] = __float2bfloat16(vv[i]);
            lo[i] = __float2bfloat16(vv[i] - __bfloat162float(h[i]));
        }
        *(uint2*)&dh[idx * 4] = *(uint2*)h;
        *(uint2*)&dl[idx * 4] = *(uint2*)lo;
    }
}
__global__ __launch_bounds__(256) void cvt_a1_k() {
    int b = blockIdx.x;
    cvt_block(g_a1 + (size_t)b * 16384, g_a1h + (size_t)b * 16384, g_a1l + (size_t)b * 16384,
              4096, threadIdx.x, 256);
}
__global__ __launch_bounds__(256) void cvt_a2_k() {
    int b = blockIdx.x;
    cvt_block(g_a2 + (size_t)b * 8192, g_a2h + (size_t)b * 8192, g_a2l + (size_t)b * 8192,
              2048, threadIdx.x, 256);
}
__global__ __launch_bounds__(256) void cvt_fea_k() {
    int b = blockIdx.x;
    cvt_block(g_fea + (size_t)b * 4096, g_feah + (size_t)b * 4096, g_feal + (size_t)b * 4096,
              1024, threadIdx.x, 256);
}
__global__ __launch_bounds__(256) void cvt_cd_k(const float* __restrict__ c0,
                                                const float* __restrict__ c1) {
    int c = blockIdx.x;
    const float* cp = (c < 512) ? c0 + (size_t)c * 256 : c1 + (size_t)(c - 512) * 256;
    cvt_block(cp, g_cdh + (size_t)c * 256, g_cdl + (size_t)c * 256, 64, threadIdx.x, 256);
}
__global__ __launch_bounds__(256) void cvt_w2_k(const float* __restrict__ w) {
    int tap = blockIdx.x, tid = threadIdx.x;
    for (int i = tid; i < 8192; i += 256) {
        int co = i >> 6, ci = i & 63;
        float v = w[(size_t)co * 576 + ci * 9 + tap];
        __nv_bfloat16 h = __float2bfloat16(v);
        g_wB2h[tap * 8192 + i] = h;
        g_wB2l[tap * 8192 + i] = __float2bfloat16(v - __bfloat162float(h));
    }
}
__global__ __launch_bounds__(256) void cvt_w3_k(const float* __restrict__ w) {
    int tap = blockIdx.x, tid = threadIdx.x;
    for (int i = tid; i < 32768; i += 256) {
        int co = i >> 7, ci = i & 127;
        float v = w[(size_t)co * 1152 + ci * 9 + tap];
        __nv_bfloat16 h = __float2bfloat16(v);
        g_wB3h[tap * 32768 + i] = h;
        g_wB3l[tap * 32768 + i] = __float2bfloat16(v - __bfloat162float(h));
    }
}

// ================= shared HMMA block machinery =================
// smem layout (dyn, 81920B): 4 tiles (Ah,Al,Bh,Bl), each [2buf][128 rows][40 bf16]

// frag loads for one k16 step: a-rows from tileA, b-rows from tileB
#define HMMA_STEP(cb, ks)                                                           \
    {                                                                               \
        int kc = (ks) * 16 + t2 * 2;                                                \
        unsigned ah[2][4], al[2][4], bh[4][2], bl[4][2];                            \
        _Pragma("unroll")                                                           \
        for (int mt = 0; mt < 2; mt++) {                                            \
            int r = mw + mt * 16 + g;                                               \
            const __nv_bfloat16* ph = base[0] + (cb) * 5120 + r * 40;               \
            const __nv_bfloat16* pl = base[1] + (cb) * 5120 + r * 40;               \
            ah[mt][0] = *(const unsigned*)(ph + kc);                                \
            ah[mt][1] = *(const unsigned*)(ph + 8 * 40 + kc);                       \
            ah[mt][2] = *(const unsigned*)(ph + kc + 8);                            \
            ah[mt][3] = *(const unsigned*)(ph + 8 * 40 + kc + 8);                   \
            al[mt][0] = *(const unsigned*)(pl + kc);                                \
            al[mt][1] = *(const unsigned*)(pl + 8 * 40 + kc);                       \
            al[mt][2] = *(const unsigned*)(pl + kc + 8);                            \
            al[mt][3] = *(const unsigned*)(pl + 8 * 40 + kc + 8);                   \
        }                                                                           \
        _Pragma("unroll")                                                           \
        for (int nt = 0; nt < 4; nt++) {                                            \
            int n = nw + nt * 8 + g;                                                \
            const __nv_bfloat16* ph = base[2] + (cb) * 5120 + n * 40;               \
            const __nv_bfloat16* pl = base[3] + (cb) * 5120 + n * 40;               \
            bh[nt][0] = *(const unsigned*)(ph + kc);                                \
            bh[nt][1] = *(const unsigned*)(ph + kc + 8);                            \
            bl[nt][0] = *(const unsigned*)(pl + kc);                                \
            bl[nt][1] = *(const unsigned*)(pl + kc + 8);                            \
        }                                                                           \
        _Pragma("unroll")                                                           \
        for (int mt = 0; mt < 2; mt++)                                              \
            _Pragma("unroll")                                                       \
            for (int nt = 0; nt < 4; nt++) {                                        \
                hmma(acc[mt][nt], ah[mt], bh[nt]);                                  \
                hmma(acc[mt][nt], ah[mt], bl[nt]);                                  \
                hmma(acc[mt][nt], al[mt], bh[nt]);                                  \
            }                                                                       \
    }

// ---------- conv2 via bf16 split HMMA: 2 images/block, C[128row,128co], K=576 ----------
__global__ __launch_bounds__(512) void conv2_k(const float* __restrict__ bias) {
    extern __shared__ __nv_bfloat16 smem_bf[];
    __nv_bfloat16* base[4] = {smem_bf, smem_bf + 10240, smem_bf + 20480, smem_bf + 30720};
    int tid = threadIdx.x;
    int b0 = blockIdx.x * 2;
    int lane = tid & 31, wrp = tid >> 5;
    int g = lane >> 2, t2 = lane & 3;
    int mw = (wrp & 3) * 32, nw = (wrp >> 2) * 32;
    float acc[2][4][4];
#pragma unroll
    for (int mt = 0; mt < 2; mt++)
#pragma unroll
        for (int nt = 0; nt < 4; nt++)
#pragma unroll
            for (int i = 0; i < 4; i++) acc[mt][nt][i] = 0.f;

    auto stage = [&](int ch, int buf) {
        int tap = ch >> 1, ci0 = (ch & 1) * 32;
        int kh = tap / 3, kw = tap - kh * 3;
#pragma unroll
        for (int l = 0; l < 4; l++) {
            int gi = tid + 512 * l;
            int arr = gi >> 9;
            int rem = gi & 511;
            int row = rem >> 2, q = rem & 3;
            __nv_bfloat16* dst = base[arr] + buf * 5120 + row * 40 + q * 8;
            if (arr < 2) {
                int img = row >> 6, pos = row & 63;
                int oh = pos >> 3, ow = pos & 7;
                int ih = oh * 2 + kh - 1, iw = ow * 2 + kw - 1;
                int ok = ((unsigned)ih < 16u && (unsigned)iw < 16u) ? 16 : 0;
                size_t si = ok ? ((((size_t)(b0 + img) * 256) + ih * 16 + iw) * 64 + ci0 + q * 8) : 0;
                cpa16z(dst, (arr ? g_a1l : g_a1h) + si, ok);
            } else {
                cpa16(dst, ((arr == 3) ? g_wB2l : g_wB2h) + (size_t)tap * 8192 + row * 64 + ci0 + q * 8);
            }
        }
        cpa_commit();
    };

    stage(0, 0);
    for (int ch = 0; ch < 18; ch++) {
        int cb = ch & 1;
        cpa_wait0();
        __syncthreads();
        if (ch + 1 < 18) stage(ch + 1, cb ^ 1);
        HMMA_STEP(cb, 0)
        HMMA_STEP(cb, 1)
    }
    float2 bb[4];
#pragma unroll
    for (int nt = 0; nt < 4; nt++) bb[nt] = *(const float2*)&bias[nw + nt * 8 + t2 * 2];
#pragma unroll
    for (int mt = 0; mt < 2; mt++) {
        int r0 = mw + mt * 16 + g, r1 = r0 + 8;
        float* op0 = &g_a2[(((size_t)(b0 + (r0 >> 6)) * 64) + (r0 & 63)) * 128];
        float* op1 = &g_a2[(((size_t)(b0 + (r1 >> 6)) * 64) + (r1 & 63)) * 128];
#pragma unroll
        for (int nt = 0; nt < 4; nt++) {
            int c0 = nw + nt * 8 + t2 * 2;
            float2 v0, v1;
            v0.x = fmaxf(acc[mt][nt][0] + bb[nt].x, 0.f);
            v0.y = fmaxf(acc[mt][nt][1] + bb[nt].y, 0.f);
            v1.x = fmaxf(acc[mt][nt][2] + bb[nt].x, 0.f);
            v1.y = fmaxf(acc[mt][nt][3] + bb[nt].y, 0.f);
            *(float2*)&op0[c0] = v0;
            *(float2*)&op1[c0] = v1;
        }
    }
}

// ---------- conv3 via bf16 split HMMA: 8 images/block x 128 co, K=1152 ----------
__global__ __launch_bounds__(512) void conv3_k(const float* __restrict__ bias) {
    extern __shared__ __nv_bfloat16 smem_bf[];
    __nv_bfloat16* base[4] = {smem_bf, smem_bf + 10240, smem_bf + 20480, smem_bf + 30720};
    int tid = threadIdx.x;
    int b0 = blockIdx.x * 8;
    int cob = blockIdx.y * 128;
    int lane = tid & 31, wrp = tid >> 5;
    int g = lane >> 2, t2 = lane & 3;
    int mw = (wrp & 3) * 32, nw = (wrp >> 2) * 32;
    float acc[2][4][4];
#pragma unroll
    for (int mt = 0; mt < 2; mt++)
#pragma unroll
        for (int nt = 0; nt < 4; nt++)
#pragma unroll
            for (int i = 0; i < 4; i++) acc[mt][nt][i] = 0.f;

    auto stage = [&](int ch, int buf) {
        int tap = ch >> 2, ci0 = (ch & 3) * 32;
        int kh = tap / 3, kw = tap - kh * 3;
#pragma unroll
        for (int l = 0; l < 4; l++) {
            int gi = tid + 512 * l;
            int arr = gi >> 9;
            int rem = gi & 511;
            int row = rem >> 2, q = rem & 3;
            __nv_bfloat16* dst = base[arr] + buf * 5120 + row * 40 + q * 8;
            if (arr < 2) {
                int img = row >> 4, pos = row & 15;
                int oh = pos >> 2, ow = pos & 3;
                int ih = oh * 2 + kh - 1, iw = ow * 2 + kw - 1;
                int ok = ((unsigned)ih < 8u && (unsigned)iw < 8u) ? 16 : 0;
                size_t si = ok ? ((((size_t)(b0 + img) * 64) + ih * 8 + iw) * 128 + ci0 + q * 8) : 0;
                cpa16z(dst, (arr ? g_a2l : g_a2h) + si, ok);
            } else {
                cpa16(dst, ((arr == 3) ? g_wB3l : g_wB3h)
                           + (size_t)tap * 32768 + (cob + row) * 128 + ci0 + q * 8);
            }
        }
        cpa_commit();
    };

    stage(0, 0);
    for (int ch = 0; ch < 36; ch++) {
        int cb = ch & 1;
        cpa_wait0();
        __syncthreads();
        if (ch + 1 < 36) stage(ch + 1, cb ^ 1);
        HMMA_STEP(cb, 0)
        HMMA_STEP(cb, 1)
    }
    float2 bb[4];
#pragma unroll
    for (int nt = 0; nt < 4; nt++) bb[nt] = *(const float2*)&bias[cob + nw + nt * 8 + t2 * 2];
#pragma unroll
    for (int mt = 0; mt < 2; mt++) {
        int r0 = mw + mt * 16 + g, r1 = r0 + 8;
        float* op0 = &g_fea[(((size_t)(b0 + (r0 >> 4)) * 16) + (r0 & 15)) * 256 + cob];
        float* op1 = &g_fea[(((size_t)(b0 + (r1 >> 4)) * 16) + (r1 & 15)) * 256 + cob];
#pragma unroll
        for (int nt = 0; nt < 4; nt++) {
            int c0 = nw + nt * 8 + t2 * 2;
            float2 v0, v1;
            v0.x = fmaxf(acc[mt][nt][0] + bb[nt].x, 0.f);
            v0.y = fmaxf(acc[mt][nt][1] + bb[nt].y, 0.f);
            v1.x = fmaxf(acc[mt][nt][2] + bb[nt].x, 0.f);
            v1.y = fmaxf(acc[mt][nt][3] + bb[nt].y, 0.f);
            *(float2*)&op0[c0] = v0;
            *(float2*)&op1[c0] = v1;
        }
    }
}

// ---------- code norms ----------
__global__ void codenorm_k(const float* __restrict__ c0, const float* __restrict__ c1) {
    int c = blockIdx.x * 256 + threadIdx.x;
    const float* cp = (c < 512) ? c0 + (size_t)c * 256 : c1 + (size_t)(c - 512) * 256;
    float s = 0.f;
    for (int k = 0; k < 256; k += 4) {
        float4 v = *(const float4*)&cp[k];
        s += v.x * v.x + v.y * v.y + v.z * v.z + v.w * v.w;
    }
    g_cn[c] = s;
}

// ---------- VQ via bf16 split HMMA: 128 rows/block x 128-code tiles, K=256 ----------
__global__ __launch_bounds__(512) void vq_k(const int* __restrict__ idxp) {
    extern __shared__ __nv_bfloat16 smem_bf[];
    __nv_bfloat16* base[4] = {smem_bf, smem_bf + 10240, smem_bf + 20480, smem_bf + 30720};
    int tid = threadIdx.x;
    int rowbase = blockIdx.x * 128;
    int lane = tid & 31, wrp = tid >> 5;
    int g = lane >> 2, t2 = lane & 3;
    int mw = (wrp & 3) * 32, nw = (wrp >> 2) * 32;
    int Kc = (idxp[0] == 0) ? 512 : 1024;
    int ntiles = Kc >> 7;
    int total = ntiles * 8;                  // cc: tile = cc>>3, kc = cc&7
    float bv[4]; int bi[4];
#pragma unroll
    for (int i = 0; i < 4; i++) { bv[i] = 1e30f; bi[i] = 0; }
    float acc[2][4][4];
#pragma unroll
    for (int mt = 0; mt < 2; mt++)
#pragma unroll
        for (int nt = 0; nt < 4; nt++)
#pragma unroll
            for (int i = 0; i < 4; i++) acc[mt][nt][i] = 0.f;

    auto stage = [&](int cc, int buf) {
        int tile = cc >> 3, kc = cc & 7;
#pragma unroll
        for (int l = 0; l < 4; l++) {
            int gi = tid + 512 * l;
            int arr = gi >> 9;
            int rem = gi & 511;
            int row = rem >> 2, q = rem & 3;
            __nv_bfloat16* dst = base[arr] + buf * 5120 + row * 40 + q * 8;
            const __nv_bfloat16* src;
            if (arr < 2)
                src = (arr ? g_feal : g_feah) + (size_t)(rowbase + row) * 256 + kc * 32 + q * 8;
            else
                src = ((arr == 3) ? g_cdl : g_cdh) + (size_t)(tile * 128 + row) * 256 + kc * 32 + q * 8;
            cpa16(dst, src);
        }
        cpa_commit();
    };

    stage(0, 0);
    for (int cc = 0; cc < total; cc++) {
        int cb = cc & 1;
        cpa_wait0();
        __syncthreads();
        if (cc + 1 < total) stage(cc + 1, cb ^ 1);
        HMMA_STEP(cb, 0)
        HMMA_STEP(cb, 1)
        if ((cc & 7) == 7) {
            int tile = cc >> 3;
#pragma unroll
            for (int nt = 0; nt < 4; nt++) {
                int c0 = tile * 128 + nw + nt * 8 + t2 * 2;
                float cn0 = g_cn[c0], cn1 = g_cn[c0 + 1];
#pragma unroll
                for (int mt = 0; mt < 2; mt++) {
                    float d00 = cn0 - 2.f * acc[mt][nt][0];
                    float d01 = cn1 - 2.f * acc[mt][nt][1];
                    float d10 = cn0 - 2.f * acc[mt][nt][2];
                    float d11 = cn1 - 2.f * acc[mt][nt][3];
                    int bidx0 = mt * 2, bidx1 = mt * 2 + 1;
                    if (d00 < bv[bidx0]) { bv[bidx0] = d00; bi[bidx0] = c0; }
                    if (d01 < bv[bidx0]) { bv[bidx0] = d01; bi[bidx0] = c0 + 1; }
                    if (d10 < bv[bidx1]) { bv[bidx1] = d10; bi[bidx1] = c0; }
                    if (d11 < bv[bidx1]) { bv[bidx1] = d11; bi[bidx1] = c0 + 1; }
                }
            }
#pragma unroll
            for (int mt = 0; mt < 2; mt++)
#pragma unroll
                for (int nt = 0; nt < 4; nt++)
#pragma unroll
                    for (int i = 0; i < 4; i++) acc[mt][nt][i] = 0.f;
        }
    }
    // cross-thread reduction: row r held by 16 threads (4 nw-warps x 4 t2)
    __syncthreads();
    float (*sbv)[16] = (float(*)[16])smem_bf;                    // 8KB
    int   (*sbi)[16] = (int(*)[16])(smem_bf + 4096);             // next 8KB
    int qidx = (wrp >> 2) * 4 + t2;
#pragma unroll
    for (int mt = 0; mt < 2; mt++) {
        int r0 = mw + mt * 16 + g, r1 = r0 + 8;
        sbv[r0][qidx] = bv[mt * 2];     sbi[r0][qidx] = bi[mt * 2];
        sbv[r1][qidx] = bv[mt * 2 + 1]; sbi[r1][qidx] = bi[mt * 2 + 1];
    }
    __syncthreads();
    if (tid < 128) {
        float v = sbv[tid][0]; int ii = sbi[tid][0];
#pragma unroll
        for (int q = 1; q < 16; q++) {
            float v2 = sbv[tid][q]; int i2 = sbi[tid][q];
            if (v2 < v || (v2 == v && i2 < ii)) { v = v2; ii = i2; }
        }
        g_eidx[rowbase + tid] = ii;
    }
}

__global__ void zero_hist_k() { g_hist[threadIdx.x] = 0; }

// ---------- loss partials + histogram ----------
__global__ void loss_hist_k(const float* __restrict__ c0, const float* __restrict__ c1) {
    __shared__ float red[256];
    int row = blockIdx.x * 256 + threadIdx.x;
    int e = g_eidx[row];
    atomicAdd(&g_hist[e], 1);
    const float* cp = (e < 512) ? c0 + (size_t)e * 256 : c1 + (size_t)(e - 512) * 256;
    const float* f = g_fea + (size_t)row * 256;
    float s = 0.f;
    for (int k = 0; k < 256; k += 4) {
        float4 q = *(const float4*)&cp[k];
        float4 fv = *(const float4*)&f[k];
        float a = q.x - fv.x, b = q.y - fv.y, c = q.z - fv.z, d = q.w - fv.w;
        s += a * a + b * b + c * c + d * d;
    }
    red[threadIdx.x] = s;
    __syncthreads();
    for (int st = 128; st; st >>= 1) {
        if (threadIdx.x < st) red[threadIdx.x] += red[threadIdx.x + st];
        __syncthreads();
    }
    if (threadIdx.x == 0) g_losspart[blockIdx.x] = red[0];
}

// ---------- fc1_w transpose ----------
__global__ __launch_bounds__(256) void wtT_k(const float* __restrict__ w) {
    __shared__ float t[32][33];
    int bx = blockIdx.x, by = blockIdx.y;
    int tx = threadIdx.x & 31, ty = threadIdx.x >> 5;
#pragma unroll
    for (int i = 0; i < 4; i++)
        t[ty + 8 * i][tx] = w[(size_t)(by * 32 + ty + 8 * i) * 4096 + bx * 32 + tx];
    __syncthreads();
#pragma unroll
    for (int i = 0; i < 4; i++)
        g_wt[(size_t)(bx * 32 + ty + 8 * i) * 512 + by * 32 + tx] = t[tx][ty + 8 * i];
}

// ---------- P[pos] = codes @ wt[pos] ----------
__global__ __launch_bounds__(256) void ptab_k(const float* __restrict__ c0,
                                              const float* __restrict__ c1) {
    __shared__ float sA[16][68];
    __shared__ float sB[16][68];
    int tid = threadIdx.x;
    int cb = blockIdx.x * 64, nb = blockIdx.y * 64, pos = blockIdx.z;
    int tx = tid & 15, ty = tid >> 4;
    float acc[4][4];
#pragma unroll
    for (int i = 0; i < 4; i++)
#pragma unroll
        for (int j = 0; j < 4; j++) acc[i][j] = 0.f;
    for (int kt = 0; kt < 16; kt++) {
        __syncthreads();
        for (int i = tid; i < 1024; i += 256) {
            int c = i >> 4, k = i & 15;
            int cg = cb + c;
            const float* cp = (cg < 512) ? c0 + (size_t)cg * 256 : c1 + (size_t)(cg - 512) * 256;
            sA[k][c] = cp[kt * 16 + k];
        }
        for (int i = tid; i < 1024; i += 256) {
            int k = i >> 6, n = i & 63;
            sB[k][n] = g_wt[(size_t)((kt * 16 + k) * 16 + pos) * 512 + nb + n];
        }
        __syncthreads();
#pragma unroll
        for (int kk = 0; kk < 16; kk++) {
            float a4[4], b4[4];
            *(float4*)a4 = *(float4*)&sA[kk][ty * 4];
            *(float4*)b4 = *(float4*)&sB[kk][tx * 4];
#pragma unroll
            for (int i = 0; i < 4; i++)
#pragma unroll
                for (int j = 0; j < 4; j++) acc[i][j] = fmaf(a4[i], b4[j], acc[i][j]);
        }
    }
#pragma unroll
    for (int i = 0; i < 4; i++) {
        float4 o = make_float4(acc[i][0], acc[i][1], acc[i][2], acc[i][3]);
        *(float4*)&g_P[((size_t)pos * 1024 + cb + ty * 4 + i) * 512 + nb + tx * 4] = o;
    }
}

// ---------- h = gelu(sum_pos P + b1) ----------
__global__ __launch_bounds__(512) void hgs_k(const float* __restrict__ fb) {
    __shared__ int se[16];
    int b = blockIdx.x, tid = threadIdx.x;
    if (tid < 16) se[tid] = g_eidx[b * 16 + tid];
    __syncthreads();
    float acc = fb[tid];
#pragma unroll
    for (int p = 0; p < 16; p++) acc += g_P[((size_t)p * 1024 + se[p]) * 512 + tid];
    g_h[(size_t)b * 512 + tid] = gelu_t(acc);
}

// ---------- fc2 ----------
__global__ __launch_bounds__(256) void fc2_k(const float* __restrict__ w,
                                             const float* __restrict__ bias,
                                             float* __restrict__ out) {
    __shared__ float sw[10][512];
    __shared__ float sb[10];
    int tid = threadIdx.x;
    for (int i = tid; i < 5120; i += 256) sw[i >> 9][i & 511] = w[i];
    if (tid < 10) sb[tid] = bias[tid];
    __syncthreads();
    int warp = tid >> 5, lane = tid & 31;
    int bimg = blockIdx.x * 8 + warp;
    const float* hr = g_h + (size_t)bimg * 512;
    float acc[10];
#pragma unroll
    for (int m = 0; m < 10; m++) acc[m] = 0.f;
    for (int k = 0; k < 16; k++) {
        float hv = hr[lane + 32 * k];
#pragma unroll
        for (int m = 0; m < 10; m++) acc[m] = fmaf(hv, sw[m][lane + 32 * k], acc[m]);
    }
#pragma unroll
    for (int off = 16; off; off >>= 1)
#pragma unroll
        for (int m = 0; m < 10; m++) acc[m] += __shfl_xor_sync(0xFFFFFFFFu, acc[m], off);
    if (lane < 10) out[(size_t)bimg * 10 + lane] = acc[lane] + sb[lane];
}

// ---------- loss + perplexity ----------
__global__ void losspp_k(float* __restrict__ dout, int osz) {
    __shared__ float red[256];
    int tid = threadIdx.x;
    red[tid] = g_losspart[tid];
    __syncthreads();
    for (int st = 128; st; st >>= 1) {
        if (tid < st) red[tid] += red[tid + st];
        __syncthreads();
    }
    float loss = 1.25f * red[0] / 16777216.0f;
    __syncthreads();
    float s = 0.f;
    for (int i = tid; i < 1024; i += 256) {
        float p = (float)g_hist[i] / 65536.0f;
        if (p > 0.f) s += p * logf(p + 1e-10f);
    }
    red[tid] = s;
    __syncthreads();
    for (int st = 128; st; st >>= 1) {
        if (tid < st) red[tid] += red[tid + st];
        __syncthreads();
    }
    if (tid == 0) { dout[osz - 2] = loss; dout[osz - 1] = expf(-red[0]); }
}

extern "C" void kernel_launch(void* const* d_in, const int* in_sizes, int n_in,
                              void* d_out, int out_size) {
    const float* x     = (const float*)d_in[0];
    const float* w1    = (const float*)d_in[1];
    const float* b1    = (const float*)d_in[2];
    const float* w2    = (const float*)d_in[3];
    const float* b2    = (const float*)d_in[4];
    const float* w3    = (const float*)d_in[5];
    const float* b3    = (const float*)d_in[6];
    const float* code0 = (const float*)d_in[7];
    const float* code1 = (const float*)d_in[8];
    const float* fc1w  = (const float*)d_in[9];
    const float* fc1b  = (const float*)d_in[10];
    const float* fc2w  = (const float*)d_in[11];
    const float* fc2b  = (const float*)d_in[12];
    const int*   idxp  = (const int*)d_in[13];
    float* out = (float*)d_out;

    cudaFuncSetAttribute(conv2_k, cudaFuncAttributeMaxDynamicSharedMemorySize, 81920);
    cudaFuncSetAttribute(conv3_k, cudaFuncAttributeMaxDynamicSharedMemorySize, 81920);
    cudaFuncSetAttribute(vq_k,    cudaFuncAttributeMaxDynamicSharedMemorySize, 81920);

    // conv2_k stays at our launch #3 (ncu -s 5 lands there after 2 harness launches).
    conv1_k<<<4096, 256>>>(x, w1, b1);                    // 0
    cvt_w2_k<<<9, 256>>>(w2);                             // 1
    cvt_a1_k<<<4096, 256>>>();                            // 2
    conv2_k<<<2048, 512, 81920>>>(b2);                    // 3
    cvt_w3_k<<<9, 256>>>(w3);                             // 4
    cvt_a2_k<<<4096, 256>>>();                            // 5
    conv3_k<<<dim3(512, 2), 512, 81920>>>(b3);            // 6
    cvt_fea_k<<<4096, 256>>>();                           // 7
    cvt_cd_k<<<1024, 256>>>(code0, code1);                // 8
    codenorm_k<<<4, 256>>>(code0, code1);                 // 9
    vq_k<<<512, 512, 81920>>>(idxp);                      // 10
    zero_hist_k<<<1, 1024>>>();                           // 11
    loss_hist_k<<<256, 256>>>(code0, code1);              // 12
    wtT_k<<<dim3(128, 16), 256>>>(fc1w);                  // 13
    ptab_k<<<dim3(16, 8, 16), 256>>>(code0, code1);       // 14
    hgs_k<<<4096, 512>>>(fc1b);                           // 15
    fc2_k<<<512, 256>>>(fc2w, fc2b, out);                 // 16
    losspp_k<<<1, 256>>>(out, out_size);                  // 17
}

// round 13
// speedup vs baseline: 30.9172x; 1.0450x over previous
#include <cuda_runtime.h>
#include <cuda_bf16.h>
#include <math.h>

typedef unsigned long long u64;

// ------------------ scratch (__device__ globals; no allocation) ------------------
__device__ __nv_bfloat16 g_a1h[4096 * 256 * 64];
__device__ __nv_bfloat16 g_a1l[4096 * 256 * 64];
__device__ __nv_bfloat16 g_wB2h[9 * 128 * 64];    // conv2 w [tap][co][ci]
__device__ __nv_bfloat16 g_wB2l[9 * 128 * 64];
__device__ __nv_bfloat16 g_a2h[4096 * 64 * 128];
__device__ __nv_bfloat16 g_a2l[4096 * 64 * 128];
__device__ __nv_bfloat16 g_wB3h[9 * 256 * 128];   // conv3 w [tap][co][ci]
__device__ __nv_bfloat16 g_wB3l[9 * 256 * 128];
__device__ float g_fea[4096 * 16 * 256];          // conv3 out fp32 (loss input)
__device__ __nv_bfloat16 g_feah[4096 * 16 * 256];
__device__ __nv_bfloat16 g_feal[4096 * 16 * 256];
__device__ __nv_bfloat16 g_cdh[1024 * 256];       // codes bf16 hi [code][k]
__device__ __nv_bfloat16 g_cdl[1024 * 256];
__device__ float g_wt[4096 * 512];                // fc1_w transposed [c'][n]
__device__ float g_P[16 * 1024 * 512];            // P[pos][code][n]
__device__ float g_h[4096 * 512];
__device__ int   g_eidx[65536];
__device__ float g_cn[1024];
__device__ int   g_hist[1024];
__device__ float g_losspart[256];

__device__ __forceinline__ float gelu_t(float x) {
    float x3 = x * x * x;
    float t = tanhf(0.7978845608028654f * (x + 0.044715f * x3));
    return 0.5f * x * (1.0f + t);
}

// ---- cp.async helpers ----
__device__ __forceinline__ void cpa16(void* smem_dst, const void* gmem_src) {
    unsigned d = (unsigned)__cvta_generic_to_shared(smem_dst);
    asm volatile("cp.async.ca.shared.global [%0], [%1], 16;" :: "r"(d), "l"(gmem_src));
}
__device__ __forceinline__ void cpa16z(void* smem_dst, const void* gmem_src, int srcbytes) {
    unsigned d = (unsigned)__cvta_generic_to_shared(smem_dst);
    asm volatile("cp.async.ca.shared.global [%0], [%1], 16, %2;" :: "r"(d), "l"(gmem_src), "r"(srcbytes));
}
__device__ __forceinline__ void cpa_commit() { asm volatile("cp.async.commit_group;"); }
__device__ __forceinline__ void cpa_wait0()  { asm volatile("cp.async.wait_group 0;" ::: "memory"); }

// ---- bf16 HMMA + ldmatrix ----
__device__ __forceinline__ void hmma(float* c, const unsigned* a, const unsigned* b) {
    asm volatile(
        "mma.sync.aligned.m16n8k16.row.col.f32.bf16.bf16.f32 "
        "{%0,%1,%2,%3}, {%4,%5,%6,%7}, {%8,%9}, {%0,%1,%2,%3};\n"
        : "+f"(c[0]), "+f"(c[1]), "+f"(c[2]), "+f"(c[3])
        : "r"(a[0]), "r"(a[1]), "r"(a[2]), "r"(a[3]), "r"(b[0]), "r"(b[1]));
}
__device__ __forceinline__ void ldm_x4(unsigned* r, const void* p) {
    unsigned a = (unsigned)__cvta_generic_to_shared(p);
    asm volatile("ldmatrix.sync.aligned.m8n8.x4.shared.b16 {%0,%1,%2,%3}, [%4];"
        : "=r"(r[0]), "=r"(r[1]), "=r"(r[2]), "=r"(r[3]) : "r"(a));
}
__device__ __forceinline__ void split_bf(float v, __nv_bfloat16& h, __nv_bfloat16& l) {
    h = __float2bfloat16(v);
    l = __float2bfloat16(v - __bfloat162float(h));
}

// ---------- conv1: writes bf16 hi/lo directly ----------
__global__ __launch_bounds__(256) void conv1_k(const float* __restrict__ x,
                                               const float* __restrict__ w,
                                               const float* __restrict__ bias) {
    __shared__ float sw1[27][64];
    __shared__ float sb1[64];
    int tid = threadIdx.x, b = blockIdx.x;
    for (int i = tid; i < 1728; i += 256) { int co = i & 63, t = i >> 6; sw1[t][co] = w[co * 27 + t]; }
    if (tid < 64) sb1[tid] = bias[tid];
    __syncthreads();
    int oh = tid >> 4, ow = tid & 15;
    const float* xb = x + (size_t)b * 3072;
    float in[27];
#pragma unroll
    for (int c = 0; c < 3; c++)
#pragma unroll
        for (int kh = 0; kh < 3; kh++)
#pragma unroll
            for (int kw = 0; kw < 3; kw++) {
                int ih = oh * 2 + kh - 1, iw = ow * 2 + kw - 1;
                float v = 0.f;
                if ((unsigned)ih < 32u && (unsigned)iw < 32u) v = xb[(c * 32 + ih) * 32 + iw];
                in[(c * 3 + kh) * 3 + kw] = v;
            }
    size_t ob = ((size_t)b * 256 + tid) * 64;
#pragma unroll
    for (int cq = 0; cq < 16; cq++) {
        float a0 = sb1[cq * 4], a1 = sb1[cq * 4 + 1], a2 = sb1[cq * 4 + 2], a3 = sb1[cq * 4 + 3];
#pragma unroll
        for (int t = 0; t < 27; t++) {
            float4 wv = *(float4*)&sw1[t][cq * 4];
            a0 = fmaf(in[t], wv.x, a0); a1 = fmaf(in[t], wv.y, a1);
            a2 = fmaf(in[t], wv.z, a2); a3 = fmaf(in[t], wv.w, a3);
        }
        float vv[4] = {fmaxf(a0, 0.f), fmaxf(a1, 0.f), fmaxf(a2, 0.f), fmaxf(a3, 0.f)};
        __nv_bfloat16 h[4], lo[4];
#pragma unroll
        for (int i = 0; i < 4; i++) split_bf(vv[i], h[i], lo[i]);
        *(uint2*)&g_a1h[ob + cq * 4] = *(uint2*)h;
        *(uint2*)&g_a1l[ob + cq * 4] = *(uint2*)lo;
    }
}

// ---------- weight/code converters ----------
__global__ __launch_bounds__(256) void cvt_w2_k(const float* __restrict__ w) {
    int tap = blockIdx.x, tid = threadIdx.x;
    for (int i = tid; i < 8192; i += 256) {
        int co = i >> 6, ci = i & 63;
        float v = w[(size_t)co * 576 + ci * 9 + tap];
        __nv_bfloat16 h, l; split_bf(v, h, l);
        g_wB2h[tap * 8192 + i] = h;
        g_wB2l[tap * 8192 + i] = l;
    }
}
__global__ __launch_bounds__(256) void cvt_w3_k(const float* __restrict__ w) {
    int tap = blockIdx.x, tid = threadIdx.x;
    for (int i = tid; i < 32768; i += 256) {
        int co = i >> 7, ci = i & 127;
        float v = w[(size_t)co * 1152 + ci * 9 + tap];
        __nv_bfloat16 h, l; split_bf(v, h, l);
        g_wB3h[tap * 32768 + i] = h;
        g_wB3l[tap * 32768 + i] = l;
    }
}
__global__ __launch_bounds__(256) void cvt_cd_k(const float* __restrict__ c0,
                                                const float* __restrict__ c1) {
    int c = blockIdx.x;
    const float* cp = (c < 512) ? c0 + (size_t)c * 256 : c1 + (size_t)(c - 512) * 256;
    for (int k = threadIdx.x; k < 256; k += 256) {
        __nv_bfloat16 h, l; split_bf(cp[k], h, l);
        g_cdh[(size_t)c * 256 + k] = h;
        g_cdl[(size_t)c * 256 + k] = l;
    }
}

// ================= HMMA machinery =================
// smem: 4 tiles (Ah,Al,Bh,Bl), each [2buf][128 rows][40 bf16]; 81920B total
// per-thread ldmatrix address components (defined per kernel):
//   rA=(lane&7)+((lane>>3)&1)*8, kA=(lane>>4)*8  (A tiles)
//   nB=(lane>>4)*8+(lane&7),     kB=((lane>>3)&1)*8 (B tiles, 2 nt per x4)
#define HMMA_STEP(cb, ks)                                                            \
    {                                                                                \
        unsigned ah[2][4], al[2][4], bh4[2][4], bl4[2][4];                           \
        _Pragma("unroll")                                                            \
        for (int mt = 0; mt < 2; mt++) {                                             \
            int roff = (mw + mt * 16 + rA) * 40 + (ks) * 16 + kA;                    \
            ldm_x4(ah[mt], base[0] + (cb) * 5120 + roff);                            \
            ldm_x4(al[mt], base[1] + (cb) * 5120 + roff);                            \
        }                                                                            \
        _Pragma("unroll")                                                            \
        for (int p = 0; p < 2; p++) {                                                \
            int noff = (nw + p * 16 + nB) * 40 + (ks) * 16 + kB;                     \
            ldm_x4(bh4[p], base[2] + (cb) * 5120 + noff);                            \
            ldm_x4(bl4[p], base[3] + (cb) * 5120 + noff);                            \
        }                                                                            \
        _Pragma("unroll")                                                            \
        for (int mt = 0; mt < 2; mt++)                                               \
            _Pragma("unroll")                                                        \
            for (int p = 0; p < 2; p++)                                              \
                _Pragma("unroll")                                                    \
                for (int hh = 0; hh < 2; hh++) {                                     \
                    hmma(acc[mt][p * 2 + hh], ah[mt], &bh4[p][hh * 2]);              \
                    hmma(acc[mt][p * 2 + hh], ah[mt], &bl4[p][hh * 2]);              \
                    hmma(acc[mt][p * 2 + hh], al[mt], &bh4[p][hh * 2]);              \
                }                                                                    \
    }

// ---------- conv2: 2 images/block, C[128row,128co], K=576 ----------
__global__ __launch_bounds__(512) void conv2_k(const float* __restrict__ bias) {
    extern __shared__ __nv_bfloat16 smem_bf[];
    __nv_bfloat16* base[4] = {smem_bf, smem_bf + 10240, smem_bf + 20480, smem_bf + 30720};
    int tid = threadIdx.x;
    int b0 = blockIdx.x * 2;
    int lane = tid & 31, wrp = tid >> 5;
    int g = lane >> 2, t2 = lane & 3;
    int mw = (wrp & 3) * 32, nw = (wrp >> 2) * 32;
    int rA = (lane & 7) + ((lane >> 3) & 1) * 8, kA = (lane >> 4) * 8;
    int nB = (lane >> 4) * 8 + (lane & 7), kB = ((lane >> 3) & 1) * 8;
    float acc[2][4][4];
#pragma unroll
    for (int mt = 0; mt < 2; mt++)
#pragma unroll
        for (int nt = 0; nt < 4; nt++)
#pragma unroll
            for (int i = 0; i < 4; i++) acc[mt][nt][i] = 0.f;

    auto stage = [&](int ch, int buf) {
        int tap = ch >> 1, ci0 = (ch & 1) * 32;
        int kh = tap / 3, kw = tap - kh * 3;
#pragma unroll
        for (int l = 0; l < 4; l++) {
            int gi = tid + 512 * l;
            int arr = gi >> 9;
            int rem = gi & 511;
            int row = rem >> 2, q = rem & 3;
            __nv_bfloat16* dst = base[arr] + buf * 5120 + row * 40 + q * 8;
            if (arr < 2) {
                int img = row >> 6, pos = row & 63;
                int oh = pos >> 3, ow = pos & 7;
                int ih = oh * 2 + kh - 1, iw = ow * 2 + kw - 1;
                int ok = ((unsigned)ih < 16u && (unsigned)iw < 16u) ? 16 : 0;
                size_t si = ok ? ((((size_t)(b0 + img) * 256) + ih * 16 + iw) * 64 + ci0 + q * 8) : 0;
                cpa16z(dst, (arr ? g_a1l : g_a1h) + si, ok);
            } else {
                cpa16(dst, ((arr == 3) ? g_wB2l : g_wB2h) + (size_t)tap * 8192 + row * 64 + ci0 + q * 8);
            }
        }
        cpa_commit();
    };

    stage(0, 0);
    for (int ch = 0; ch < 18; ch++) {
        int cb = ch & 1;
        cpa_wait0();
        __syncthreads();
        if (ch + 1 < 18) stage(ch + 1, cb ^ 1);
        HMMA_STEP(cb, 0)
        HMMA_STEP(cb, 1)
    }
    float2 bb[4];
#pragma unroll
    for (int nt = 0; nt < 4; nt++) bb[nt] = *(const float2*)&bias[nw + nt * 8 + t2 * 2];
#pragma unroll
    for (int mt = 0; mt < 2; mt++) {
        int r0 = mw + mt * 16 + g, r1 = r0 + 8;
        size_t o0 = (((size_t)(b0 + (r0 >> 6)) * 64) + (r0 & 63)) * 128;
        size_t o1 = (((size_t)(b0 + (r1 >> 6)) * 64) + (r1 & 63)) * 128;
#pragma unroll
        for (int nt = 0; nt < 4; nt++) {
            int c0 = nw + nt * 8 + t2 * 2;
            float v00 = fmaxf(acc[mt][nt][0] + bb[nt].x, 0.f);
            float v01 = fmaxf(acc[mt][nt][1] + bb[nt].y, 0.f);
            float v10 = fmaxf(acc[mt][nt][2] + bb[nt].x, 0.f);
            float v11 = fmaxf(acc[mt][nt][3] + bb[nt].y, 0.f);
            __nv_bfloat162 h0, l0, h1, l1;
            split_bf(v00, h0.x, l0.x); split_bf(v01, h0.y, l0.y);
            split_bf(v10, h1.x, l1.x); split_bf(v11, h1.y, l1.y);
            *(__nv_bfloat162*)&g_a2h[o0 + c0] = h0;
            *(__nv_bfloat162*)&g_a2l[o0 + c0] = l0;
            *(__nv_bfloat162*)&g_a2h[o1 + c0] = h1;
            *(__nv_bfloat162*)&g_a2l[o1 + c0] = l1;
        }
    }
}

// ---------- conv3: 8 images/block x 128 co, K=1152 ----------
__global__ __launch_bounds__(512) void conv3_k(const float* __restrict__ bias) {
    extern __shared__ __nv_bfloat16 smem_bf[];
    __nv_bfloat16* base[4] = {smem_bf, smem_bf + 10240, smem_bf + 20480, smem_bf + 30720};
    int tid = threadIdx.x;
    int b0 = blockIdx.x * 8;
    int cob = blockIdx.y * 128;
    int lane = tid & 31, wrp = tid >> 5;
    int g = lane >> 2, t2 = lane & 3;
    int mw = (wrp & 3) * 32, nw = (wrp >> 2) * 32;
    int rA = (lane & 7) + ((lane >> 3) & 1) * 8, kA = (lane >> 4) * 8;
    int nB = (lane >> 4) * 8 + (lane & 7), kB = ((lane >> 3) & 1) * 8;
    float acc[2][4][4];
#pragma unroll
    for (int mt = 0; mt < 2; mt++)
#pragma unroll
        for (int nt = 0; nt < 4; nt++)
#pragma unroll
            for (int i = 0; i < 4; i++) acc[mt][nt][i] = 0.f;

    auto stage = [&](int ch, int buf) {
        int tap = ch >> 2, ci0 = (ch & 3) * 32;
        int kh = tap / 3, kw = tap - kh * 3;
#pragma unroll
        for (int l = 0; l < 4; l++) {
            int gi = tid + 512 * l;
            int arr = gi >> 9;
            int rem = gi & 511;
            int row = rem >> 2, q = rem & 3;
            __nv_bfloat16* dst = base[arr] + buf * 5120 + row * 40 + q * 8;
            if (arr < 2) {
                int img = row >> 4, pos = row & 15;
                int oh = pos >> 2, ow = pos & 3;
                int ih = oh * 2 + kh - 1, iw = ow * 2 + kw - 1;
                int ok = ((unsigned)ih < 8u && (unsigned)iw < 8u) ? 16 : 0;
                size_t si = ok ? ((((size_t)(b0 + img) * 64) + ih * 8 + iw) * 128 + ci0 + q * 8) : 0;
                cpa16z(dst, (arr ? g_a2l : g_a2h) + si, ok);
            } else {
                cpa16(dst, ((arr == 3) ? g_wB3l : g_wB3h)
                           + (size_t)tap * 32768 + (cob + row) * 128 + ci0 + q * 8);
            }
        }
        cpa_commit();
    };

    stage(0, 0);
    for (int ch = 0; ch < 36; ch++) {
        int cb = ch & 1;
        cpa_wait0();
        __syncthreads();
        if (ch + 1 < 36) stage(ch + 1, cb ^ 1);
        HMMA_STEP(cb, 0)
        HMMA_STEP(cb, 1)
    }
    float2 bb[4];
#pragma unroll
    for (int nt = 0; nt < 4; nt++) bb[nt] = *(const float2*)&bias[cob + nw + nt * 8 + t2 * 2];
#pragma unroll
    for (int mt = 0; mt < 2; mt++) {
        int r0 = mw + mt * 16 + g, r1 = r0 + 8;
        size_t o0 = (((size_t)(b0 + (r0 >> 4)) * 16) + (r0 & 15)) * 256 + cob;
        size_t o1 = (((size_t)(b0 + (r1 >> 4)) * 16) + (r1 & 15)) * 256 + cob;
#pragma unroll
        for (int nt = 0; nt < 4; nt++) {
            int c0 = nw + nt * 8 + t2 * 2;
            float v00 = fmaxf(acc[mt][nt][0] + bb[nt].x, 0.f);
            float v01 = fmaxf(acc[mt][nt][1] + bb[nt].y, 0.f);
            float v10 = fmaxf(acc[mt][nt][2] + bb[nt].x, 0.f);
            float v11 = fmaxf(acc[mt][nt][3] + bb[nt].y, 0.f);
            *(float2*)&g_fea[o0 + c0] = make_float2(v00, v01);
            *(float2*)&g_fea[o1 + c0] = make_float2(v10, v11);
            __nv_bfloat162 h0, l0, h1, l1;
            split_bf(v00, h0.x, l0.x); split_bf(v01, h0.y, l0.y);
            split_bf(v10, h1.x, l1.x); split_bf(v11, h1.y, l1.y);
            *(__nv_bfloat162*)&g_feah[o0 + c0] = h0;
            *(__nv_bfloat162*)&g_feal[o0 + c0] = l0;
            *(__nv_bfloat162*)&g_feah[o1 + c0] = h1;
            *(__nv_bfloat162*)&g_feal[o1 + c0] = l1;
        }
    }
}

// ---------- code norms ----------
__global__ void codenorm_k(const float* __restrict__ c0, const float* __restrict__ c1) {
    int c = blockIdx.x * 256 + threadIdx.x;
    const float* cp = (c < 512) ? c0 + (size_t)c * 256 : c1 + (size_t)(c - 512) * 256;
    float s = 0.f;
    for (int k = 0; k < 256; k += 4) {
        float4 v = *(const float4*)&cp[k];
        s += v.x * v.x + v.y * v.y + v.z * v.z + v.w * v.w;
    }
    g_cn[c] = s;
}

// ---------- VQ: 128 rows/block x 128-code tiles, K=256 ----------
__global__ __launch_bounds__(512) void vq_k(const int* __restrict__ idxp) {
    extern __shared__ __nv_bfloat16 smem_bf[];
    __nv_bfloat16* base[4] = {smem_bf, smem_bf + 10240, smem_bf + 20480, smem_bf + 30720};
    int tid = threadIdx.x;
    int rowbase = blockIdx.x * 128;
    int lane = tid & 31, wrp = tid >> 5;
    int g = lane >> 2, t2 = lane & 3;
    int mw = (wrp & 3) * 32, nw = (wrp >> 2) * 32;
    int rA = (lane & 7) + ((lane >> 3) & 1) * 8, kA = (lane >> 4) * 8;
    int nB = (lane >> 4) * 8 + (lane & 7), kB = ((lane >> 3) & 1) * 8;
    int Kc = (idxp[0] == 0) ? 512 : 1024;
    int total = (Kc >> 7) * 8;               // tile = cc>>3, kc = cc&7
    float bv[4]; int bi[4];
#pragma unroll
    for (int i = 0; i < 4; i++) { bv[i] = 1e30f; bi[i] = 0; }
    float acc[2][4][4];
#pragma unroll
    for (int mt = 0; mt < 2; mt++)
#pragma unroll
        for (int nt = 0; nt < 4; nt++)
#pragma unroll
            for (int i = 0; i < 4; i++) acc[mt][nt][i] = 0.f;

    auto stage = [&](int cc, int buf) {
        int tile = cc >> 3, kc = cc & 7;
#pragma unroll
        for (int l = 0; l < 4; l++) {
            int gi = tid + 512 * l;
            int arr = gi >> 9;
            int rem = gi & 511;
            int row = rem >> 2, q = rem & 3;
            __nv_bfloat16* dst = base[arr] + buf * 5120 + row * 40 + q * 8;
            const __nv_bfloat16* src;
            if (arr < 2)
                src = (arr ? g_feal : g_feah) + (size_t)(rowbase + row) * 256 + kc * 32 + q * 8;
            else
                src = ((arr == 3) ? g_cdl : g_cdh) + (size_t)(tile * 128 + row) * 256 + kc * 32 + q * 8;
            cpa16(dst, src);
        }
        cpa_commit();
    };

    stage(0, 0);
    for (int cc = 0; cc < total; cc++) {
        int cb = cc & 1;
        cpa_wait0();
        __syncthreads();
        if (cc + 1 < total) stage(cc + 1, cb ^ 1);
        HMMA_STEP(cb, 0)
        HMMA_STEP(cb, 1)
        if ((cc & 7) == 7) {
            int tile = cc >> 3;
#pragma unroll
            for (int nt = 0; nt < 4; nt++) {
                int c0 = tile * 128 + nw + nt * 8 + t2 * 2;
                float cn0 = g_cn[c0], cn1 = g_cn[c0 + 1];
#pragma unroll
                for (int mt = 0; mt < 2; mt++) {
                    float d00 = cn0 - 2.f * acc[mt][nt][0];
                    float d01 = cn1 - 2.f * acc[mt][nt][1];
                    float d10 = cn0 - 2.f * acc[mt][nt][2];
                    float d11 = cn1 - 2.f * acc[mt][nt][3];
                    int b0i = mt * 2, b1i = mt * 2 + 1;
                    if (d00 < bv[b0i]) { bv[b0i] = d00; bi[b0i] = c0; }
                    if (d01 < bv[b0i]) { bv[b0i] = d01; bi[b0i] = c0 + 1; }
                    if (d10 < bv[b1i]) { bv[b1i] = d10; bi[b1i] = c0; }
                    if (d11 < bv[b1i]) { bv[b1i] = d11; bi[b1i] = c0 + 1; }
                }
            }
#pragma unroll
            for (int mt = 0; mt < 2; mt++)
#pragma unroll
                for (int nt = 0; nt < 4; nt++)
#pragma unroll
                    for (int i = 0; i < 4; i++) acc[mt][nt][i] = 0.f;
        }
    }
    __syncthreads();
    float (*sbv)[16] = (float(*)[16])smem_bf;
    int   (*sbi)[16] = (int(*)[16])(smem_bf + 4096);
    int qidx = (wrp >> 2) * 4 + t2;
#pragma unroll
    for (int mt = 0; mt < 2; mt++) {
        int r0 = mw + mt * 16 + g, r1 = r0 + 8;
        sbv[r0][qidx] = bv[mt * 2];     sbi[r0][qidx] = bi[mt * 2];
        sbv[r1][qidx] = bv[mt * 2 + 1]; sbi[r1][qidx] = bi[mt * 2 + 1];
    }
    __syncthreads();
    if (tid < 128) {
        float v = sbv[tid][0]; int ii = sbi[tid][0];
#pragma unroll
        for (int q = 1; q < 16; q++) {
            float v2 = sbv[tid][q]; int i2 = sbi[tid][q];
            if (v2 < v || (v2 == v && i2 < ii)) { v = v2; ii = i2; }
        }
        g_eidx[rowbase + tid] = ii;
    }
}

__global__ void zero_hist_k() { g_hist[threadIdx.x] = 0; }

// ---------- loss partials + histogram ----------
__global__ void loss_hist_k(const float* __restrict__ c0, const float* __restrict__ c1) {
    __shared__ float red[256];
    int row = blockIdx.x * 256 + threadIdx.x;
    int e = g_eidx[row];
    atomicAdd(&g_hist[e], 1);
    const float* cp = (e < 512) ? c0 + (size_t)e * 256 : c1 + (size_t)(e - 512) * 256;
    const float* f = g_fea + (size_t)row * 256;
    float s = 0.f;
    for (int k = 0; k < 256; k += 4) {
        float4 q = *(const float4*)&cp[k];
        float4 fv = *(const float4*)&f[k];
        float a = q.x - fv.x, b = q.y - fv.y, c = q.z - fv.z, d = q.w - fv.w;
        s += a * a + b * b + c * c + d * d;
    }
    red[threadIdx.x] = s;
    __syncthreads();
    for (int st = 128; st; st >>= 1) {
        if (threadIdx.x < st) red[threadIdx.x] += red[threadIdx.x + st];
        __syncthreads();
    }
    if (threadIdx.x == 0) g_losspart[blockIdx.x] = red[0];
}

// ---------- fc1_w transpose ----------
__global__ __launch_bounds__(256) void wtT_k(const float* __restrict__ w) {
    __shared__ float t[32][33];
    int bx = blockIdx.x, by = blockIdx.y;
    int tx = threadIdx.x & 31, ty = threadIdx.x >> 5;
#pragma unroll
    for (int i = 0; i < 4; i++)
        t[ty + 8 * i][tx] = w[(size_t)(by * 32 + ty + 8 * i) * 4096 + bx * 32 + tx];
    __syncthreads();
#pragma unroll
    for (int i = 0; i < 4; i++)
        g_wt[(size_t)(bx * 32 + ty + 8 * i) * 512 + by * 32 + tx] = t[tx][ty + 8 * i];
}

// ---------- P[pos] = codes @ wt[pos] ----------
__global__ __launch_bounds__(256) void ptab_k(const float* __restrict__ c0,
                                              const float* __restrict__ c1) {
    __shared__ float sA[16][68];
    __shared__ float sB[16][68];
    int tid = threadIdx.x;
    int cb = blockIdx.x * 64, nb = blockIdx.y * 64, pos = blockIdx.z;
    int tx = tid & 15, ty = tid >> 4;
    float acc[4][4];
#pragma unroll
    for (int i = 0; i < 4; i++)
#pragma unroll
        for (int j = 0; j < 4; j++) acc[i][j] = 0.f;
    for (int kt = 0; kt < 16; kt++) {
        __syncthreads();
        for (int i = tid; i < 1024; i += 256) {
            int c = i >> 4, k = i & 15;
            int cg = cb + c;
            const float* cp = (cg < 512) ? c0 + (size_t)cg * 256 : c1 + (size_t)(cg - 512) * 256;
            sA[k][c] = cp[kt * 16 + k];
        }
        for (int i = tid; i < 1024; i += 256) {
            int k = i >> 6, n = i & 63;
            sB[k][n] = g_wt[(size_t)((kt * 16 + k) * 16 + pos) * 512 + nb + n];
        }
        __syncthreads();
#pragma unroll
        for (int kk = 0; kk < 16; kk++) {
            float a4[4], b4[4];
            *(float4*)a4 = *(float4*)&sA[kk][ty * 4];
            *(float4*)b4 = *(float4*)&sB[kk][tx * 4];
#pragma unroll
            for (int i = 0; i < 4; i++)
#pragma unroll
                for (int j = 0; j < 4; j++) acc[i][j] = fmaf(a4[i], b4[j], acc[i][j]);
        }
    }
#pragma unroll
    for (int i = 0; i < 4; i++) {
        float4 o = make_float4(acc[i][0], acc[i][1], acc[i][2], acc[i][3]);
        *(float4*)&g_P[((size_t)pos * 1024 + cb + ty * 4 + i) * 512 + nb + tx * 4] = o;
    }
}

// ---------- h = gelu(sum_pos P + b1) ----------
__global__ __launch_bounds__(512) void hgs_k(const float* __restrict__ fb) {
    __shared__ int se[16];
    int b = blockIdx.x, tid = threadIdx.x;
    if (tid < 16) se[tid] = g_eidx[b * 16 + tid];
    __syncthreads();
    float acc = fb[tid];
#pragma unroll
    for (int p = 0; p < 16; p++) acc += g_P[((size_t)p * 1024 + se[p]) * 512 + tid];
    g_h[(size_t)b * 512 + tid] = gelu_t(acc);
}

// ---------- fc2 ----------
__global__ __launch_bounds__(256) void fc2_k(const float* __restrict__ w,
                                             const float* __restrict__ bias,
                                             float* __restrict__ out) {
    __shared__ float sw[10][512];
    __shared__ float sb[10];
    int tid = threadIdx.x;
    for (int i = tid; i < 5120; i += 256) sw[i >> 9][i & 511] = w[i];
    if (tid < 10) sb[tid] = bias[tid];
    __syncthreads();
    int warp = tid >> 5, lane = tid & 31;
    int bimg = blockIdx.x * 8 + warp;
    const float* hr = g_h + (size_t)bimg * 512;
    float acc[10];
#pragma unroll
    for (int m = 0; m < 10; m++) acc[m] = 0.f;
    for (int k = 0; k < 16; k++) {
        float hv = hr[lane + 32 * k];
#pragma unroll
        for (int m = 0; m < 10; m++) acc[m] = fmaf(hv, sw[m][lane + 32 * k], acc[m]);
    }
#pragma unroll
    for (int off = 16; off; off >>= 1)
#pragma unroll
        for (int m = 0; m < 10; m++) acc[m] += __shfl_xor_sync(0xFFFFFFFFu, acc[m], off);
    if (lane < 10) out[(size_t)bimg * 10 + lane] = acc[lane] + sb[lane];
}

// ---------- loss + perplexity ----------
__global__ void losspp_k(float* __restrict__ dout, int osz) {
    __shared__ float red[256];
    int tid = threadIdx.x;
    red[tid] = g_losspart[tid];
    __syncthreads();
    for (int st = 128; st; st >>= 1) {
        if (tid < st) red[tid] += red[tid + st];
        __syncthreads();
    }
    float loss = 1.25f * red[0] / 16777216.0f;
    __syncthreads();
    float s = 0.f;
    for (int i = tid; i < 1024; i += 256) {
        float p = (float)g_hist[i] / 65536.0f;
        if (p > 0.f) s += p * logf(p + 1e-10f);
    }
    red[tid] = s;
    __syncthreads();
    for (int st = 128; st; st >>= 1) {
        if (tid < st) red[tid] += red[tid + st];
        __syncthreads();
    }
    if (tid == 0) { dout[osz - 2] = loss; dout[osz - 1] = expf(-red[0]); }
}

extern "C" void kernel_launch(void* const* d_in, const int* in_sizes, int n_in,
                              void* d_out, int out_size) {
    const float* x     = (const float*)d_in[0];
    const float* w1    = (const float*)d_in[1];
    const float* b1    = (const float*)d_in[2];
    const float* w2    = (const float*)d_in[3];
    const float* b2    = (const float*)d_in[4];
    const float* w3    = (const float*)d_in[5];
    const float* b3    = (const float*)d_in[6];
    const float* code0 = (const float*)d_in[7];
    const float* code1 = (const float*)d_in[8];
    const float* fc1w  = (const float*)d_in[9];
    const float* fc1b  = (const float*)d_in[10];
    const float* fc2w  = (const float*)d_in[11];
    const float* fc2b  = (const float*)d_in[12];
    const int*   idxp  = (const int*)d_in[13];
    float* out = (float*)d_out;

    cudaFuncSetAttribute(conv2_k, cudaFuncAttributeMaxDynamicSharedMemorySize, 81920);
    cudaFuncSetAttribute(conv3_k, cudaFuncAttributeMaxDynamicSharedMemorySize, 81920);
    cudaFuncSetAttribute(vq_k,    cudaFuncAttributeMaxDynamicSharedMemorySize, 81920);

    // conv2_k stays at our launch #3 (ncu -s 5 lands there after 2 harness launches).
    conv1_k<<<4096, 256>>>(x, w1, b1);                    // 0
    cvt_w2_k<<<9, 256>>>(w2);                             // 1
    cvt_w3_k<<<9, 256>>>(w3);                             // 2
    conv2_k<<<2048, 512, 81920>>>(b2);                    // 3
    conv3_k<<<dim3(512, 2), 512, 81920>>>(b3);            // 4
    cvt_cd_k<<<1024, 256>>>(code0, code1);                // 5
    codenorm_k<<<4, 256>>>(code0, code1);                 // 6
    vq_k<<<512, 512, 81920>>>(idxp);                      // 7
    zero_hist_k<<<1, 1024>>>();                           // 8
    loss_hist_k<<<256, 256>>>(code0, code1);              // 9
    wtT_k<<<dim3(128, 16), 256>>>(fc1w);                  // 10
    ptab_k<<<dim3(16, 8, 16), 256>>>(code0, code1);       // 11
    hgs_k<<<4096, 512>>>(fc1b);                           // 12
    fc2_k<<<512, 256>>>(fc2w, fc2b, out);                 // 13
    losspp_k<<<1, 256>>>(out, out_size);                  // 14
}

// round 14
// speedup vs baseline: 33.9497x; 1.0981x over previous
#include <cuda_runtime.h>
#include <cuda_bf16.h>
#include <math.h>

typedef unsigned long long u64;

// ------------------ scratch (__device__ globals; no allocation) ------------------
__device__ __nv_bfloat16 g_a1h[4096 * 256 * 64];
__device__ __nv_bfloat16 g_a1l[4096 * 256 * 64];
__device__ __nv_bfloat16 g_wB2h[9 * 128 * 64];    // conv2 w [tap][co][ci]
__device__ __nv_bfloat16 g_wB2l[9 * 128 * 64];
__device__ __nv_bfloat16 g_a2h[4096 * 64 * 128];
__device__ __nv_bfloat16 g_a2l[4096 * 64 * 128];
__device__ __nv_bfloat16 g_wB3h[9 * 256 * 128];   // conv3 w [tap][co][ci]
__device__ __nv_bfloat16 g_wB3l[9 * 256 * 128];
__device__ float g_fea[4096 * 16 * 256];          // conv3 out fp32 (loss input)
__device__ __nv_bfloat16 g_feah[4096 * 16 * 256];
__device__ __nv_bfloat16 g_feal[4096 * 16 * 256];
__device__ __nv_bfloat16 g_cdh[1024 * 256];       // codes bf16 hi [code][k]
__device__ __nv_bfloat16 g_cdl[1024 * 256];
__device__ float g_wt[4096 * 512];                // fc1_w transposed [c'][n]
__device__ float g_P[16 * 1024 * 512];            // P[pos][code][n]
__device__ float g_h[4096 * 512];
__device__ int   g_eidx[65536];
__device__ float g_cn[1024];
__device__ int   g_hist[1024];
__device__ float g_losspart[256];

__device__ __forceinline__ float gelu_t(float x) {
    float x3 = x * x * x;
    float t = tanhf(0.7978845608028654f * (x + 0.044715f * x3));
    return 0.5f * x * (1.0f + t);
}

// ---- cp.async helpers ----
__device__ __forceinline__ void cpa16(void* smem_dst, const void* gmem_src) {
    unsigned d = (unsigned)__cvta_generic_to_shared(smem_dst);
    asm volatile("cp.async.ca.shared.global [%0], [%1], 16;" :: "r"(d), "l"(gmem_src));
}
__device__ __forceinline__ void cpa16z(void* smem_dst, const void* gmem_src, int srcbytes) {
    unsigned d = (unsigned)__cvta_generic_to_shared(smem_dst);
    asm volatile("cp.async.ca.shared.global [%0], [%1], 16, %2;" :: "r"(d), "l"(gmem_src), "r"(srcbytes));
}
__device__ __forceinline__ void cpa_commit() { asm volatile("cp.async.commit_group;"); }
__device__ __forceinline__ void cpa_wait0()  { asm volatile("cp.async.wait_group 0;" ::: "memory"); }

// ---- bf16 HMMA + ldmatrix ----
__device__ __forceinline__ void hmma(float* c, const unsigned* a, const unsigned* b) {
    asm volatile(
        "mma.sync.aligned.m16n8k16.row.col.f32.bf16.bf16.f32 "
        "{%0,%1,%2,%3}, {%4,%5,%6,%7}, {%8,%9}, {%0,%1,%2,%3};\n"
        : "+f"(c[0]), "+f"(c[1]), "+f"(c[2]), "+f"(c[3])
        : "r"(a[0]), "r"(a[1]), "r"(a[2]), "r"(a[3]), "r"(b[0]), "r"(b[1]));
}
__device__ __forceinline__ void ldm_x4(unsigned* r, const void* p) {
    unsigned a = (unsigned)__cvta_generic_to_shared(p);
    asm volatile("ldmatrix.sync.aligned.m8n8.x4.shared.b16 {%0,%1,%2,%3}, [%4];"
        : "=r"(r[0]), "=r"(r[1]), "=r"(r[2]), "=r"(r[3]) : "r"(a));
}
__device__ __forceinline__ void split_bf(float v, __nv_bfloat16& h, __nv_bfloat16& l) {
    h = __float2bfloat16(v);
    l = __float2bfloat16(v - __bfloat162float(h));
}

// ---------- conv1: writes bf16 hi/lo directly ----------
__global__ __launch_bounds__(256) void conv1_k(const float* __restrict__ x,
                                               const float* __restrict__ w,
                                               const float* __restrict__ bias) {
    __shared__ float sw1[27][64];
    __shared__ float sb1[64];
    int tid = threadIdx.x, b = blockIdx.x;
    for (int i = tid; i < 1728; i += 256) { int co = i & 63, t = i >> 6; sw1[t][co] = w[co * 27 + t]; }
    if (tid < 64) sb1[tid] = bias[tid];
    __syncthreads();
    int oh = tid >> 4, ow = tid & 15;
    const float* xb = x + (size_t)b * 3072;
    float in[27];
#pragma unroll
    for (int c = 0; c < 3; c++)
#pragma unroll
        for (int kh = 0; kh < 3; kh++)
#pragma unroll
            for (int kw = 0; kw < 3; kw++) {
                int ih = oh * 2 + kh - 1, iw = ow * 2 + kw - 1;
                float v = 0.f;
                if ((unsigned)ih < 32u && (unsigned)iw < 32u) v = xb[(c * 32 + ih) * 32 + iw];
                in[(c * 3 + kh) * 3 + kw] = v;
            }
    size_t ob = ((size_t)b * 256 + tid) * 64;
#pragma unroll
    for (int cq = 0; cq < 16; cq++) {
        float a0 = sb1[cq * 4], a1 = sb1[cq * 4 + 1], a2 = sb1[cq * 4 + 2], a3 = sb1[cq * 4 + 3];
#pragma unroll
        for (int t = 0; t < 27; t++) {
            float4 wv = *(float4*)&sw1[t][cq * 4];
            a0 = fmaf(in[t], wv.x, a0); a1 = fmaf(in[t], wv.y, a1);
            a2 = fmaf(in[t], wv.z, a2); a3 = fmaf(in[t], wv.w, a3);
        }
        float vv[4] = {fmaxf(a0, 0.f), fmaxf(a1, 0.f), fmaxf(a2, 0.f), fmaxf(a3, 0.f)};
        __nv_bfloat16 h[4], lo[4];
#pragma unroll
        for (int i = 0; i < 4; i++) split_bf(vv[i], h[i], lo[i]);
        *(uint2*)&g_a1h[ob + cq * 4] = *(uint2*)h;
        *(uint2*)&g_a1l[ob + cq * 4] = *(uint2*)lo;
    }
}

// ---------- weight/code converters ----------
__global__ __launch_bounds__(256) void cvt_w2_k(const float* __restrict__ w) {
    int tap = blockIdx.x, tid = threadIdx.x;
    for (int i = tid; i < 8192; i += 256) {
        int co = i >> 6, ci = i & 63;
        float v = w[(size_t)co * 576 + ci * 9 + tap];
        __nv_bfloat16 h, l; split_bf(v, h, l);
        g_wB2h[tap * 8192 + i] = h;
        g_wB2l[tap * 8192 + i] = l;
    }
}
__global__ __launch_bounds__(256) void cvt_w3_k(const float* __restrict__ w) {
    int tap = blockIdx.x, tid = threadIdx.x;
    for (int i = tid; i < 32768; i += 256) {
        int co = i >> 7, ci = i & 127;
        float v = w[(size_t)co * 1152 + ci * 9 + tap];
        __nv_bfloat16 h, l; split_bf(v, h, l);
        g_wB3h[tap * 32768 + i] = h;
        g_wB3l[tap * 32768 + i] = l;
    }
}
__global__ __launch_bounds__(256) void cvt_cd_k(const float* __restrict__ c0,
                                                const float* __restrict__ c1) {
    int c = blockIdx.x;
    const float* cp = (c < 512) ? c0 + (size_t)c * 256 : c1 + (size_t)(c - 512) * 256;
    for (int k = threadIdx.x; k < 256; k += 256) {
        __nv_bfloat16 h, l; split_bf(cp[k], h, l);
        g_cdh[(size_t)c * 256 + k] = h;
        g_cdl[(size_t)c * 256 + k] = l;
    }
}

// ================= HMMA machinery =================
// smem: 4 tiles (Ah,Al,Bh,Bl), each [2buf][128 rows][40 bf16]; 81920B total
#define HMMA_STEP(cb, ks)                                                            \
    {                                                                                \
        unsigned ah[2][4], al[2][4], bh4[2][4], bl4[2][4];                           \
        _Pragma("unroll")                                                            \
        for (int mt = 0; mt < 2; mt++) {                                             \
            int roff = (mw + mt * 16 + rA) * 40 + (ks) * 16 + kA;                    \
            ldm_x4(ah[mt], base[0] + (cb) * 5120 + roff);                            \
            ldm_x4(al[mt], base[1] + (cb) * 5120 + roff);                            \
        }                                                                            \
        _Pragma("unroll")                                                            \
        for (int p = 0; p < 2; p++) {                                                \
            int noff = (nw + p * 16 + nB) * 40 + (ks) * 16 + kB;                     \
            ldm_x4(bh4[p], base[2] + (cb) * 5120 + noff);                            \
            ldm_x4(bl4[p], base[3] + (cb) * 5120 + noff);                            \
        }                                                                            \
        _Pragma("unroll")                                                            \
        for (int mt = 0; mt < 2; mt++)                                               \
            _Pragma("unroll")                                                        \
            for (int p = 0; p < 2; p++)                                              \
                _Pragma("unroll")                                                    \
                for (int hh = 0; hh < 2; hh++) {                                     \
                    hmma(acc[mt][p * 2 + hh], ah[mt], &bh4[p][hh * 2]);              \
                    hmma(acc[mt][p * 2 + hh], ah[mt], &bl4[p][hh * 2]);              \
                    hmma(acc[mt][p * 2 + hh], al[mt], &bh4[p][hh * 2]);              \
                }                                                                    \
    }

// ---------- conv2: 2 images/block, C[128row,128co], K=576 ----------
__global__ __launch_bounds__(512, 2) void conv2_k(const float* __restrict__ bias) {
    extern __shared__ __nv_bfloat16 smem_bf[];
    __nv_bfloat16* base[4] = {smem_bf, smem_bf + 10240, smem_bf + 20480, smem_bf + 30720};
    int tid = threadIdx.x;
    int b0 = blockIdx.x * 2;
    int lane = tid & 31, wrp = tid >> 5;
    int g = lane >> 2, t2 = lane & 3;
    int mw = (wrp & 3) * 32, nw = (wrp >> 2) * 32;
    int rA = (lane & 7) + ((lane >> 3) & 1) * 8, kA = (lane >> 4) * 8;
    int nB = (lane >> 4) * 8 + (lane & 7), kB = ((lane >> 3) & 1) * 8;
    float acc[2][4][4];
#pragma unroll
    for (int mt = 0; mt < 2; mt++)
#pragma unroll
        for (int nt = 0; nt < 4; nt++)
#pragma unroll
            for (int i = 0; i < 4; i++) acc[mt][nt][i] = 0.f;

    auto stage = [&](int ch, int buf) {
        int tap = ch >> 1, ci0 = (ch & 1) * 32;
        int kh = tap / 3, kw = tap - kh * 3;
#pragma unroll
        for (int l = 0; l < 4; l++) {
            int gi = tid + 512 * l;
            int arr = gi >> 9;
            int rem = gi & 511;
            int row = rem >> 2, q = rem & 3;
            __nv_bfloat16* dst = base[arr] + buf * 5120 + row * 40 + q * 8;
            if (arr < 2) {
                int img = row >> 6, pos = row & 63;
                int oh = pos >> 3, ow = pos & 7;
                int ih = oh * 2 + kh - 1, iw = ow * 2 + kw - 1;
                int ok = ((unsigned)ih < 16u && (unsigned)iw < 16u) ? 16 : 0;
                size_t si = ok ? ((((size_t)(b0 + img) * 256) + ih * 16 + iw) * 64 + ci0 + q * 8) : 0;
                cpa16z(dst, (arr ? g_a1l : g_a1h) + si, ok);
            } else {
                cpa16(dst, ((arr == 3) ? g_wB2l : g_wB2h) + (size_t)tap * 8192 + row * 64 + ci0 + q * 8);
            }
        }
        cpa_commit();
    };

    stage(0, 0);
    for (int ch = 0; ch < 18; ch++) {
        int cb = ch & 1;
        cpa_wait0();
        __syncthreads();
        if (ch + 1 < 18) stage(ch + 1, cb ^ 1);
        HMMA_STEP(cb, 0)
        HMMA_STEP(cb, 1)
    }
    float2 bb[4];
#pragma unroll
    for (int nt = 0; nt < 4; nt++) bb[nt] = *(const float2*)&bias[nw + nt * 8 + t2 * 2];
#pragma unroll
    for (int mt = 0; mt < 2; mt++) {
        int r0 = mw + mt * 16 + g, r1 = r0 + 8;
        size_t o0 = (((size_t)(b0 + (r0 >> 6)) * 64) + (r0 & 63)) * 128;
        size_t o1 = (((size_t)(b0 + (r1 >> 6)) * 64) + (r1 & 63)) * 128;
#pragma unroll
        for (int nt = 0; nt < 4; nt++) {
            int c0 = nw + nt * 8 + t2 * 2;
            float v00 = fmaxf(acc[mt][nt][0] + bb[nt].x, 0.f);
            float v01 = fmaxf(acc[mt][nt][1] + bb[nt].y, 0.f);
            float v10 = fmaxf(acc[mt][nt][2] + bb[nt].x, 0.f);
            float v11 = fmaxf(acc[mt][nt][3] + bb[nt].y, 0.f);
            __nv_bfloat162 h0, l0, h1, l1;
            split_bf(v00, h0.x, l0.x); split_bf(v01, h0.y, l0.y);
            split_bf(v10, h1.x, l1.x); split_bf(v11, h1.y, l1.y);
            *(__nv_bfloat162*)&g_a2h[o0 + c0] = h0;
            *(__nv_bfloat162*)&g_a2l[o0 + c0] = l0;
            *(__nv_bfloat162*)&g_a2h[o1 + c0] = h1;
            *(__nv_bfloat162*)&g_a2l[o1 + c0] = l1;
        }
    }
}

// ---------- conv3: 8 images/block x 128 co, K=1152 ----------
__global__ __launch_bounds__(512, 2) void conv3_k(const float* __restrict__ bias) {
    extern __shared__ __nv_bfloat16 smem_bf[];
    __nv_bfloat16* base[4] = {smem_bf, smem_bf + 10240, smem_bf + 20480, smem_bf + 30720};
    int tid = threadIdx.x;
    int b0 = blockIdx.x * 8;
    int cob = blockIdx.y * 128;
    int lane = tid & 31, wrp = tid >> 5;
    int g = lane >> 2, t2 = lane & 3;
    int mw = (wrp & 3) * 32, nw = (wrp >> 2) * 32;
    int rA = (lane & 7) + ((lane >> 3) & 1) * 8, kA = (lane >> 4) * 8;
    int nB = (lane >> 4) * 8 + (lane & 7), kB = ((lane >> 3) & 1) * 8;
    float acc[2][4][4];
#pragma unroll
    for (int mt = 0; mt < 2; mt++)
#pragma unroll
        for (int nt = 0; nt < 4; nt++)
#pragma unroll
            for (int i = 0; i < 4; i++) acc[mt][nt][i] = 0.f;

    auto stage = [&](int ch, int buf) {
        int tap = ch >> 2, ci0 = (ch & 3) * 32;
        int kh = tap / 3, kw = tap - kh * 3;
#pragma unroll
        for (int l = 0; l < 4; l++) {
            int gi = tid + 512 * l;
            int arr = gi >> 9;
            int rem = gi & 511;
            int row = rem >> 2, q = rem & 3;
            __nv_bfloat16* dst = base[arr] + buf * 5120 + row * 40 + q * 8;
            if (arr < 2) {
                int img = row >> 4, pos = row & 15;
                int oh = pos >> 2, ow = pos & 3;
                int ih = oh * 2 + kh - 1, iw = ow * 2 + kw - 1;
                int ok = ((unsigned)ih < 8u && (unsigned)iw < 8u) ? 16 : 0;
                size_t si = ok ? ((((size_t)(b0 + img) * 64) + ih * 8 + iw) * 128 + ci0 + q * 8) : 0;
                cpa16z(dst, (arr ? g_a2l : g_a2h) + si, ok);
            } else {
                cpa16(dst, ((arr == 3) ? g_wB3l : g_wB3h)
                           + (size_t)tap * 32768 + (cob + row) * 128 + ci0 + q * 8);
            }
        }
        cpa_commit();
    };

    stage(0, 0);
    for (int ch = 0; ch < 36; ch++) {
        int cb = ch & 1;
        cpa_wait0();
        __syncthreads();
        if (ch + 1 < 36) stage(ch + 1, cb ^ 1);
        HMMA_STEP(cb, 0)
        HMMA_STEP(cb, 1)
    }
    float2 bb[4];
#pragma unroll
    for (int nt = 0; nt < 4; nt++) bb[nt] = *(const float2*)&bias[cob + nw + nt * 8 + t2 * 2];
#pragma unroll
    for (int mt = 0; mt < 2; mt++) {
        int r0 = mw + mt * 16 + g, r1 = r0 + 8;
        size_t o0 = (((size_t)(b0 + (r0 >> 4)) * 16) + (r0 & 15)) * 256 + cob;
        size_t o1 = (((size_t)(b0 + (r1 >> 4)) * 16) + (r1 & 15)) * 256 + cob;
#pragma unroll
        for (int nt = 0; nt < 4; nt++) {
            int c0 = nw + nt * 8 + t2 * 2;
            float v00 = fmaxf(acc[mt][nt][0] + bb[nt].x, 0.f);
            float v01 = fmaxf(acc[mt][nt][1] + bb[nt].y, 0.f);
            float v10 = fmaxf(acc[mt][nt][2] + bb[nt].x, 0.f);
            float v11 = fmaxf(acc[mt][nt][3] + bb[nt].y, 0.f);
            *(float2*)&g_fea[o0 + c0] = make_float2(v00, v01);
            *(float2*)&g_fea[o1 + c0] = make_float2(v10, v11);
            __nv_bfloat162 h0, l0, h1, l1;
            split_bf(v00, h0.x, l0.x); split_bf(v01, h0.y, l0.y);
            split_bf(v10, h1.x, l1.x); split_bf(v11, h1.y, l1.y);
            *(__nv_bfloat162*)&g_feah[o0 + c0] = h0;
            *(__nv_bfloat162*)&g_feal[o0 + c0] = l0;
            *(__nv_bfloat162*)&g_feah[o1 + c0] = h1;
            *(__nv_bfloat162*)&g_feal[o1 + c0] = l1;
        }
    }
}

// ---------- code norms ----------
__global__ void codenorm_k(const float* __restrict__ c0, const float* __restrict__ c1) {
    int c = blockIdx.x * 256 + threadIdx.x;
    const float* cp = (c < 512) ? c0 + (size_t)c * 256 : c1 + (size_t)(c - 512) * 256;
    float s = 0.f;
    for (int k = 0; k < 256; k += 4) {
        float4 v = *(const float4*)&cp[k];
        s += v.x * v.x + v.y * v.y + v.z * v.z + v.w * v.w;
    }
    g_cn[c] = s;
}

// ---------- VQ: 128 rows/block x 128-code tiles, K=256 ----------
__global__ __launch_bounds__(512, 2) void vq_k(const int* __restrict__ idxp) {
    extern __shared__ __nv_bfloat16 smem_bf[];
    __nv_bfloat16* base[4] = {smem_bf, smem_bf + 10240, smem_bf + 20480, smem_bf + 30720};
    int tid = threadIdx.x;
    int rowbase = blockIdx.x * 128;
    int lane = tid & 31, wrp = tid >> 5;
    int g = lane >> 2, t2 = lane & 3;
    int mw = (wrp & 3) * 32, nw = (wrp >> 2) * 32;
    int rA = (lane & 7) + ((lane >> 3) & 1) * 8, kA = (lane >> 4) * 8;
    int nB = (lane >> 4) * 8 + (lane & 7), kB = ((lane >> 3) & 1) * 8;
    int Kc = (idxp[0] == 0) ? 512 : 1024;
    int total = (Kc >> 7) * 8;               // tile = cc>>3, kc = cc&7
    float bv[4]; int bi[4];
#pragma unroll
    for (int i = 0; i < 4; i++) { bv[i] = 1e30f; bi[i] = 0; }
    float acc[2][4][4];
#pragma unroll
    for (int mt = 0; mt < 2; mt++)
#pragma unroll
        for (int nt = 0; nt < 4; nt++)
#pragma unroll
            for (int i = 0; i < 4; i++) acc[mt][nt][i] = 0.f;

    auto stage = [&](int cc, int buf) {
        int tile = cc >> 3, kc = cc & 7;
#pragma unroll
        for (int l = 0; l < 4; l++) {
            int gi = tid + 512 * l;
            int arr = gi >> 9;
            int rem = gi & 511;
            int row = rem >> 2, q = rem & 3;
            __nv_bfloat16* dst = base[arr] + buf * 5120 + row * 40 + q * 8;
            const __nv_bfloat16* src;
            if (arr < 2)
                src = (arr ? g_feal : g_feah) + (size_t)(rowbase + row) * 256 + kc * 32 + q * 8;
            else
                src = ((arr == 3) ? g_cdl : g_cdh) + (size_t)(tile * 128 + row) * 256 + kc * 32 + q * 8;
            cpa16(dst, src);
        }
        cpa_commit();
    };

    stage(0, 0);
    for (int cc = 0; cc < total; cc++) {
        int cb = cc & 1;
        cpa_wait0();
        __syncthreads();
        if (cc + 1 < total) stage(cc + 1, cb ^ 1);
        HMMA_STEP(cb, 0)
        HMMA_STEP(cb, 1)
        if ((cc & 7) == 7) {
            int tile = cc >> 3;
#pragma unroll
            for (int nt = 0; nt < 4; nt++) {
                int c0 = tile * 128 + nw + nt * 8 + t2 * 2;
                float cn0 = g_cn[c0], cn1 = g_cn[c0 + 1];
#pragma unroll
                for (int mt = 0; mt < 2; mt++) {
                    float d00 = cn0 - 2.f * acc[mt][nt][0];
                    float d01 = cn1 - 2.f * acc[mt][nt][1];
                    float d10 = cn0 - 2.f * acc[mt][nt][2];
                    float d11 = cn1 - 2.f * acc[mt][nt][3];
                    int b0i = mt * 2, b1i = mt * 2 + 1;
                    if (d00 < bv[b0i]) { bv[b0i] = d00; bi[b0i] = c0; }
                    if (d01 < bv[b0i]) { bv[b0i] = d01; bi[b0i] = c0 + 1; }
                    if (d10 < bv[b1i]) { bv[b1i] = d10; bi[b1i] = c0; }
                    if (d11 < bv[b1i]) { bv[b1i] = d11; bi[b1i] = c0 + 1; }
                }
            }
#pragma unroll
            for (int mt = 0; mt < 2; mt++)
#pragma unroll
                for (int nt = 0; nt < 4; nt++)
#pragma unroll
                    for (int i = 0; i < 4; i++) acc[mt][nt][i] = 0.f;
        }
    }
    __syncthreads();
    float (*sbv)[16] = (float(*)[16])smem_bf;
    int   (*sbi)[16] = (int(*)[16])(smem_bf + 4096);
    int qidx = (wrp >> 2) * 4 + t2;
#pragma unroll
    for (int mt = 0; mt < 2; mt++) {
        int r0 = mw + mt * 16 + g, r1 = r0 + 8;
        sbv[r0][qidx] = bv[mt * 2];     sbi[r0][qidx] = bi[mt * 2];
        sbv[r1][qidx] = bv[mt * 2 + 1]; sbi[r1][qidx] = bi[mt * 2 + 1];
    }
    __syncthreads();
    if (tid < 128) {
        float v = sbv[tid][0]; int ii = sbi[tid][0];
#pragma unroll
        for (int q = 1; q < 16; q++) {
            float v2 = sbv[tid][q]; int i2 = sbi[tid][q];
            if (v2 < v || (v2 == v && i2 < ii)) { v = v2; ii = i2; }
        }
        g_eidx[rowbase + tid] = ii;
    }
}

__global__ void zero_hist_k() { g_hist[threadIdx.x] = 0; }

// ---------- loss partials + histogram ----------
__global__ void loss_hist_k(const float* __restrict__ c0, const float* __restrict__ c1) {
    __shared__ float red[256];
    int row = blockIdx.x * 256 + threadIdx.x;
    int e = g_eidx[row];
    atomicAdd(&g_hist[e], 1);
    const float* cp = (e < 512) ? c0 + (size_t)e * 256 : c1 + (size_t)(e - 512) * 256;
    const float* f = g_fea + (size_t)row * 256;
    float s = 0.f;
    for (int k = 0; k < 256; k += 4) {
        float4 q = *(const float4*)&cp[k];
        float4 fv = *(const float4*)&f[k];
        float a = q.x - fv.x, b = q.y - fv.y, c = q.z - fv.z, d = q.w - fv.w;
        s += a * a + b * b + c * c + d * d;
    }
    red[threadIdx.x] = s;
    __syncthreads();
    for (int st = 128; st; st >>= 1) {
        if (threadIdx.x < st) red[threadIdx.x] += red[threadIdx.x + st];
        __syncthreads();
    }
    if (threadIdx.x == 0) g_losspart[blockIdx.x] = red[0];
}

// ---------- fc1_w transpose ----------
__global__ __launch_bounds__(256) void wtT_k(const float* __restrict__ w) {
    __shared__ float t[32][33];
    int bx = blockIdx.x, by = blockIdx.y;
    int tx = threadIdx.x & 31, ty = threadIdx.x >> 5;
#pragma unroll
    for (int i = 0; i < 4; i++)
        t[ty + 8 * i][tx] = w[(size_t)(by * 32 + ty + 8 * i) * 4096 + bx * 32 + tx];
    __syncthreads();
#pragma unroll
    for (int i = 0; i < 4; i++)
        g_wt[(size_t)(bx * 32 + ty + 8 * i) * 512 + by * 32 + tx] = t[tx][ty + 8 * i];
}

// ---------- P[pos] = codes @ wt[pos] ----------
__global__ __launch_bounds__(256) void ptab_k(const float* __restrict__ c0,
                                              const float* __restrict__ c1) {
    __shared__ float sA[16][68];
    __shared__ float sB[16][68];
    int tid = threadIdx.x;
    int cb = blockIdx.x * 64, nb = blockIdx.y * 64, pos = blockIdx.z;
    int tx = tid & 15, ty = tid >> 4;
    float acc[4][4];
#pragma unroll
    for (int i = 0; i < 4; i++)
#pragma unroll
        for (int j = 0; j < 4; j++) acc[i][j] = 0.f;
    for (int kt = 0; kt < 16; kt++) {
        __syncthreads();
        for (int i = tid; i < 1024; i += 256) {
            int c = i >> 4, k = i & 15;
            int cg = cb + c;
            const float* cp = (cg < 512) ? c0 + (size_t)cg * 256 : c1 + (size_t)(cg - 512) * 256;
            sA[k][c] = cp[kt * 16 + k];
        }
        for (int i = tid; i < 1024; i += 256) {
            int k = i >> 6, n = i & 63;
            sB[k][n] = g_wt[(size_t)((kt * 16 + k) * 16 + pos) * 512 + nb + n];
        }
        __syncthreads();
#pragma unroll
        for (int kk = 0; kk < 16; kk++) {
            float a4[4], b4[4];
            *(float4*)a4 = *(float4*)&sA[kk][ty * 4];
            *(float4*)b4 = *(float4*)&sB[kk][tx * 4];
#pragma unroll
            for (int i = 0; i < 4; i++)
#pragma unroll
                for (int j = 0; j < 4; j++) acc[i][j] = fmaf(a4[i], b4[j], acc[i][j]);
        }
    }
#pragma unroll
    for (int i = 0; i < 4; i++) {
        float4 o = make_float4(acc[i][0], acc[i][1], acc[i][2], acc[i][3]);
        *(float4*)&g_P[((size_t)pos * 1024 + cb + ty * 4 + i) * 512 + nb + tx * 4] = o;
    }
}

// ---------- h = gelu(sum_pos P + b1) ----------
__global__ __launch_bounds__(512) void hgs_k(const float* __restrict__ fb) {
    __shared__ int se[16];
    int b = blockIdx.x, tid = threadIdx.x;
    if (tid < 16) se[tid] = g_eidx[b * 16 + tid];
    __syncthreads();
    float acc = fb[tid];
#pragma unroll
    for (int p = 0; p < 16; p++) acc += g_P[((size_t)p * 1024 + se[p]) * 512 + tid];
    g_h[(size_t)b * 512 + tid] = gelu_t(acc);
}

// ---------- fc2 ----------
__global__ __launch_bounds__(256) void fc2_k(const float* __restrict__ w,
                                             const float* __restrict__ bias,
                                             float* __restrict__ out) {
    __shared__ float sw[10][512];
    __shared__ float sb[10];
    int tid = threadIdx.x;
    for (int i = tid; i < 5120; i += 256) sw[i >> 9][i & 511] = w[i];
    if (tid < 10) sb[tid] = bias[tid];
    __syncthreads();
    int warp = tid >> 5, lane = tid & 31;
    int bimg = blockIdx.x * 8 + warp;
    const float* hr = g_h + (size_t)bimg * 512;
    float acc[10];
#pragma unroll
    for (int m = 0; m < 10; m++) acc[m] = 0.f;
    for (int k = 0; k < 16; k++) {
        float hv = hr[lane + 32 * k];
#pragma unroll
        for (int m = 0; m < 10; m++) acc[m] = fmaf(hv, sw[m][lane + 32 * k], acc[m]);
    }
#pragma unroll
    for (int off = 16; off; off >>= 1)
#pragma unroll
        for (int m = 0; m < 10; m++) acc[m] += __shfl_xor_sync(0xFFFFFFFFu, acc[m], off);
    if (lane < 10) out[(size_t)bimg * 10 + lane] = acc[lane] + sb[lane];
}

// ---------- loss + perplexity ----------
__global__ void losspp_k(float* __restrict__ dout, int osz) {
    __shared__ float red[256];
    int tid = threadIdx.x;
    red[tid] = g_losspart[tid];
    __syncthreads();
    for (int st = 128; st; st >>= 1) {
        if (tid < st) red[tid] += red[tid + st];
        __syncthreads();
    }
    float loss = 1.25f * red[0] / 16777216.0f;
    __syncthreads();
    float s = 0.f;
    for (int i = tid; i < 1024; i += 256) {
        float p = (float)g_hist[i] / 65536.0f;
        if (p > 0.f) s += p * logf(p + 1e-10f);
    }
    red[tid] = s;
    __syncthreads();
    for (int st = 128; st; st >>= 1) {
        if (tid < st) red[tid] += red[tid + st];
        __syncthreads();
    }
    if (tid == 0) { dout[osz - 2] = loss; dout[osz - 1] = expf(-red[0]); }
}

extern "C" void kernel_launch(void* const* d_in, const int* in_sizes, int n_in,
                              void* d_out, int out_size) {
    const float* x     = (const float*)d_in[0];
    const float* w1    = (const float*)d_in[1];
    const float* b1    = (const float*)d_in[2];
    const float* w2    = (const float*)d_in[3];
    const float* b2    = (const float*)d_in[4];
    const float* w3    = (const float*)d_in[5];
    const float* b3    = (const float*)d_in[6];
    const float* code0 = (const float*)d_in[7];
    const float* code1 = (const float*)d_in[8];
    const float* fc1w  = (const float*)d_in[9];
    const float* fc1b  = (const float*)d_in[10];
    const float* fc2w  = (const float*)d_in[11];
    const float* fc2b  = (const float*)d_in[12];
    const int*   idxp  = (const int*)d_in[13];
    float* out = (float*)d_out;

    cudaFuncSetAttribute(conv2_k, cudaFuncAttributeMaxDynamicSharedMemorySize, 81920);
    cudaFuncSetAttribute(conv3_k, cudaFuncAttributeMaxDynamicSharedMemorySize, 81920);
    cudaFuncSetAttribute(vq_k,    cudaFuncAttributeMaxDynamicSharedMemorySize, 81920);

    // conv2_k stays at our launch #3 (ncu -s 5 lands there after 2 harness launches).
    conv1_k<<<4096, 256>>>(x, w1, b1);                    // 0
    cvt_w2_k<<<9, 256>>>(w2);                             // 1
    cvt_w3_k<<<9, 256>>>(w3);                             // 2
    conv2_k<<<2048, 512, 81920>>>(b2);                    // 3
    conv3_k<<<dim3(512, 2), 512, 81920>>>(b3);            // 4
    cvt_cd_k<<<1024, 256>>>(code0, code1);                // 5
    codenorm_k<<<4, 256>>>(code0, code1);                 // 6
    vq_k<<<512, 512, 81920>>>(idxp);                      // 7
    zero_hist_k<<<1, 1024>>>();                           // 8
    loss_hist_k<<<256, 256>>>(code0, code1);              // 9
    wtT_k<<<dim3(128, 16), 256>>>(fc1w);                  // 10
    ptab_k<<<dim3(16, 8, 16), 256>>>(code0, code1);       // 11
    hgs_k<<<4096, 512>>>(fc1b);                           // 12
    fc2_k<<<512, 256>>>(fc2w, fc2b, out);                 // 13
    losspp_k<<<1, 256>>>(out, out_size);                  // 14
}

// round 15
// speedup vs baseline: 36.4045x; 1.0723x over previous
#include <cuda_runtime.h>
#include <cuda_bf16.h>
#include <math.h>

typedef unsigned long long u64;

// ------------------ scratch (__device__ globals; no allocation) ------------------
__device__ __nv_bfloat16 g_a1h[4096 * 256 * 64];
__device__ __nv_bfloat16 g_a1l[4096 * 256 * 64];
__device__ __nv_bfloat16 g_wB2h[9 * 128 * 64];    // conv2 w [tap][co][ci]
__device__ __nv_bfloat16 g_wB2l[9 * 128 * 64];
__device__ __nv_bfloat16 g_a2h[4096 * 64 * 128];
__device__ __nv_bfloat16 g_a2l[4096 * 64 * 128];
__device__ __nv_bfloat16 g_wB3h[9 * 256 * 128];   // conv3 w [tap][co][ci]
__device__ __nv_bfloat16 g_wB3l[9 * 256 * 128];
__device__ float g_fea[4096 * 16 * 256];          // conv3 out fp32 (loss input)
__device__ __nv_bfloat16 g_feah[4096 * 16 * 256];
__device__ __nv_bfloat16 g_feal[4096 * 16 * 256];
__device__ __nv_bfloat16 g_cdh[1024 * 256];       // codes bf16 hi [code][k]
__device__ __nv_bfloat16 g_cdl[1024 * 256];
__device__ __nv_bfloat16 g_wbh[16 * 512 * 256];   // fc1w bf16 hi [pos][n][c]
__device__ __nv_bfloat16 g_wbl[16 * 512 * 256];
__device__ float g_P[16 * 1024 * 512];            // P[pos][code][n]
__device__ float g_h[4096 * 512];
__device__ int   g_eidx[65536];
__device__ float g_cn[1024];
__device__ int   g_hist[1024];
__device__ float g_losspart[256];

__device__ __forceinline__ float gelu_t(float x) {
    float x3 = x * x * x;
    float t = tanhf(0.7978845608028654f * (x + 0.044715f * x3));
    return 0.5f * x * (1.0f + t);
}

// ---- cp.async helpers ----
__device__ __forceinline__ void cpa16(void* smem_dst, const void* gmem_src) {
    unsigned d = (unsigned)__cvta_generic_to_shared(smem_dst);
    asm volatile("cp.async.ca.shared.global [%0], [%1], 16;" :: "r"(d), "l"(gmem_src));
}
__device__ __forceinline__ void cpa16z(void* smem_dst, const void* gmem_src, int srcbytes) {
    unsigned d = (unsigned)__cvta_generic_to_shared(smem_dst);
    asm volatile("cp.async.ca.shared.global [%0], [%1], 16, %2;" :: "r"(d), "l"(gmem_src), "r"(srcbytes));
}
__device__ __forceinline__ void cpa_commit() { asm volatile("cp.async.commit_group;"); }
__device__ __forceinline__ void cpa_wait0()  { asm volatile("cp.async.wait_group 0;" ::: "memory"); }

// ---- bf16 HMMA + ldmatrix ----
__device__ __forceinline__ void hmma(float* c, const unsigned* a, const unsigned* b) {
    asm volatile(
        "mma.sync.aligned.m16n8k16.row.col.f32.bf16.bf16.f32 "
        "{%0,%1,%2,%3}, {%4,%5,%6,%7}, {%8,%9}, {%0,%1,%2,%3};\n"
        : "+f"(c[0]), "+f"(c[1]), "+f"(c[2]), "+f"(c[3])
        : "r"(a[0]), "r"(a[1]), "r"(a[2]), "r"(a[3]), "r"(b[0]), "r"(b[1]));
}
__device__ __forceinline__ void ldm_x4(unsigned* r, const void* p) {
    unsigned a = (unsigned)__cvta_generic_to_shared(p);
    asm volatile("ldmatrix.sync.aligned.m8n8.x4.shared.b16 {%0,%1,%2,%3}, [%4];"
        : "=r"(r[0]), "=r"(r[1]), "=r"(r[2]), "=r"(r[3]) : "r"(a));
}
__device__ __forceinline__ void split_bf(float v, __nv_bfloat16& h, __nv_bfloat16& l) {
    h = __float2bfloat16(v);
    l = __float2bfloat16(v - __bfloat162float(h));
}

// ---------- conv1: writes bf16 hi/lo directly ----------
__global__ __launch_bounds__(256) void conv1_k(const float* __restrict__ x,
                                               const float* __restrict__ w,
                                               const float* __restrict__ bias) {
    __shared__ float sw1[27][64];
    __shared__ float sb1[64];
    int tid = threadIdx.x, b = blockIdx.x;
    for (int i = tid; i < 1728; i += 256) { int co = i & 63, t = i >> 6; sw1[t][co] = w[co * 27 + t]; }
    if (tid < 64) sb1[tid] = bias[tid];
    __syncthreads();
    int oh = tid >> 4, ow = tid & 15;
    const float* xb = x + (size_t)b * 3072;
    float in[27];
#pragma unroll
    for (int c = 0; c < 3; c++)
#pragma unroll
        for (int kh = 0; kh < 3; kh++)
#pragma unroll
            for (int kw = 0; kw < 3; kw++) {
                int ih = oh * 2 + kh - 1, iw = ow * 2 + kw - 1;
                float v = 0.f;
                if ((unsigned)ih < 32u && (unsigned)iw < 32u) v = xb[(c * 32 + ih) * 32 + iw];
                in[(c * 3 + kh) * 3 + kw] = v;
            }
    size_t ob = ((size_t)b * 256 + tid) * 64;
#pragma unroll
    for (int cq = 0; cq < 16; cq++) {
        float a0 = sb1[cq * 4], a1 = sb1[cq * 4 + 1], a2 = sb1[cq * 4 + 2], a3 = sb1[cq * 4 + 3];
#pragma unroll
        for (int t = 0; t < 27; t++) {
            float4 wv = *(float4*)&sw1[t][cq * 4];
            a0 = fmaf(in[t], wv.x, a0); a1 = fmaf(in[t], wv.y, a1);
            a2 = fmaf(in[t], wv.z, a2); a3 = fmaf(in[t], wv.w, a3);
        }
        float vv[4] = {fmaxf(a0, 0.f), fmaxf(a1, 0.f), fmaxf(a2, 0.f), fmaxf(a3, 0.f)};
        __nv_bfloat16 h[4], lo[4];
#pragma unroll
        for (int i = 0; i < 4; i++) split_bf(vv[i], h[i], lo[i]);
        *(uint2*)&g_a1h[ob + cq * 4] = *(uint2*)h;
        *(uint2*)&g_a1l[ob + cq * 4] = *(uint2*)lo;
    }
}

// ---------- weight/code converters ----------
__global__ __launch_bounds__(256) void cvt_w2_k(const float* __restrict__ w) {
    int tap = blockIdx.x, tid = threadIdx.x;
    for (int i = tid; i < 8192; i += 256) {
        int co = i >> 6, ci = i & 63;
        float v = w[(size_t)co * 576 + ci * 9 + tap];
        __nv_bfloat16 h, l; split_bf(v, h, l);
        g_wB2h[tap * 8192 + i] = h;
        g_wB2l[tap * 8192 + i] = l;
    }
}
__global__ __launch_bounds__(256) void cvt_w3_k(const float* __restrict__ w) {
    int tap = blockIdx.x, tid = threadIdx.x;
    for (int i = tid; i < 32768; i += 256) {
        int co = i >> 7, ci = i & 127;
        float v = w[(size_t)co * 1152 + ci * 9 + tap];
        __nv_bfloat16 h, l; split_bf(v, h, l);
        g_wB3h[tap * 32768 + i] = h;
        g_wB3l[tap * 32768 + i] = l;
    }
}
__global__ __launch_bounds__(256) void cvt_cd_k(const float* __restrict__ c0,
                                                const float* __restrict__ c1) {
    int c = blockIdx.x;
    const float* cp = (c < 512) ? c0 + (size_t)c * 256 : c1 + (size_t)(c - 512) * 256;
    for (int k = threadIdx.x; k < 256; k += 256) {
        __nv_bfloat16 h, l; split_bf(cp[k], h, l);
        g_cdh[(size_t)c * 256 + k] = h;
        g_cdl[(size_t)c * 256 + k] = l;
    }
}
// fc1w [512n][4096c'] -> g_wbh/g_wbl [pos][n][256c] bf16 (c' = c*16+pos)
__global__ __launch_bounds__(256) void cvt_wb_k(const float* __restrict__ w) {
    __shared__ __nv_bfloat16 shh[4096], shl[4096];
    int n = blockIdx.x, tid = threadIdx.x;
    for (int i = tid; i < 4096; i += 256) {
        float v = w[(size_t)n * 4096 + i];
        __nv_bfloat16 h, l; split_bf(v, h, l);
        shh[i] = h; shl[i] = l;
    }
    __syncthreads();
    for (int i = tid; i < 4096; i += 256) {
        int pos = i >> 8, c = i & 255;
        size_t o = ((size_t)pos * 512 + n) * 256 + c;
        g_wbh[o] = shh[c * 16 + pos];
        g_wbl[o] = shl[c * 16 + pos];
    }
}

// ================= HMMA machinery =================
// smem: 4 tiles (Ah,Al,Bh,Bl), each [2buf][128 rows][40 bf16]; 81920B total
#define HMMA_STEP(cb, ks)                                                            \
    {                                                                                \
        unsigned ah[2][4], al[2][4], bh4[2][4], bl4[2][4];                           \
        _Pragma("unroll")                                                            \
        for (int mt = 0; mt < 2; mt++) {                                             \
            int roff = (mw + mt * 16 + rA) * 40 + (ks) * 16 + kA;                    \
            ldm_x4(ah[mt], base[0] + (cb) * 5120 + roff);                            \
            ldm_x4(al[mt], base[1] + (cb) * 5120 + roff);                            \
        }                                                                            \
        _Pragma("unroll")                                                            \
        for (int p = 0; p < 2; p++) {                                                \
            int noff = (nw + p * 16 + nB) * 40 + (ks) * 16 + kB;                     \
            ldm_x4(bh4[p], base[2] + (cb) * 5120 + noff);                            \
            ldm_x4(bl4[p], base[3] + (cb) * 5120 + noff);                            \
        }                                                                            \
        _Pragma("unroll")                                                            \
        for (int mt = 0; mt < 2; mt++)                                               \
            _Pragma("unroll")                                                        \
            for (int p = 0; p < 2; p++)                                              \
                _Pragma("unroll")                                                    \
                for (int hh = 0; hh < 2; hh++) {                                     \
                    hmma(acc[mt][p * 2 + hh], ah[mt], &bh4[p][hh * 2]);              \
                    hmma(acc[mt][p * 2 + hh], ah[mt], &bl4[p][hh * 2]);              \
                    hmma(acc[mt][p * 2 + hh], al[mt], &bh4[p][hh * 2]);              \
                }                                                                    \
    }

// ---------- conv2: 2 images/block, C[128row,128co], K=576 ----------
__global__ __launch_bounds__(512, 2) void conv2_k(const float* __restrict__ bias) {
    extern __shared__ __nv_bfloat16 smem_bf[];
    __nv_bfloat16* base[4] = {smem_bf, smem_bf + 10240, smem_bf + 20480, smem_bf + 30720};
    int tid = threadIdx.x;
    int b0 = blockIdx.x * 2;
    int lane = tid & 31, wrp = tid >> 5;
    int g = lane >> 2, t2 = lane & 3;
    int mw = (wrp & 3) * 32, nw = (wrp >> 2) * 32;
    int rA = (lane & 7) + ((lane >> 3) & 1) * 8, kA = (lane >> 4) * 8;
    int nB = (lane >> 4) * 8 + (lane & 7), kB = ((lane >> 3) & 1) * 8;
    float acc[2][4][4];
#pragma unroll
    for (int mt = 0; mt < 2; mt++)
#pragma unroll
        for (int nt = 0; nt < 4; nt++)
#pragma unroll
            for (int i = 0; i < 4; i++) acc[mt][nt][i] = 0.f;

    auto stage = [&](int ch, int buf) {
        int tap = ch >> 1, ci0 = (ch & 1) * 32;
        int kh = tap / 3, kw = tap - kh * 3;
#pragma unroll
        for (int l = 0; l < 4; l++) {
            int gi = tid + 512 * l;
            int arr = gi >> 9;
            int rem = gi & 511;
            int row = rem >> 2, q = rem & 3;
            __nv_bfloat16* dst = base[arr] + buf * 5120 + row * 40 + q * 8;
            if (arr < 2) {
                int img = row >> 6, pos = row & 63;
                int oh = pos >> 3, ow = pos & 7;
                int ih = oh * 2 + kh - 1, iw = ow * 2 + kw - 1;
                int ok = ((unsigned)ih < 16u && (unsigned)iw < 16u) ? 16 : 0;
                size_t si = ok ? ((((size_t)(b0 + img) * 256) + ih * 16 + iw) * 64 + ci0 + q * 8) : 0;
                cpa16z(dst, (arr ? g_a1l : g_a1h) + si, ok);
            } else {
                cpa16(dst, ((arr == 3) ? g_wB2l : g_wB2h) + (size_t)tap * 8192 + row * 64 + ci0 + q * 8);
            }
        }
        cpa_commit();
    };

    stage(0, 0);
    for (int ch = 0; ch < 18; ch++) {
        int cb = ch & 1;
        cpa_wait0();
        __syncthreads();
        if (ch + 1 < 18) stage(ch + 1, cb ^ 1);
        HMMA_STEP(cb, 0)
        HMMA_STEP(cb, 1)
    }
    float2 bb[4];
#pragma unroll
    for (int nt = 0; nt < 4; nt++) bb[nt] = *(const float2*)&bias[nw + nt * 8 + t2 * 2];
#pragma unroll
    for (int mt = 0; mt < 2; mt++) {
        int r0 = mw + mt * 16 + g, r1 = r0 + 8;
        size_t o0 = (((size_t)(b0 + (r0 >> 6)) * 64) + (r0 & 63)) * 128;
        size_t o1 = (((size_t)(b0 + (r1 >> 6)) * 64) + (r1 & 63)) * 128;
#pragma unroll
        for (int nt = 0; nt < 4; nt++) {
            int c0 = nw + nt * 8 + t2 * 2;
            float v00 = fmaxf(acc[mt][nt][0] + bb[nt].x, 0.f);
            float v01 = fmaxf(acc[mt][nt][1] + bb[nt].y, 0.f);
            float v10 = fmaxf(acc[mt][nt][2] + bb[nt].x, 0.f);
            float v11 = fmaxf(acc[mt][nt][3] + bb[nt].y, 0.f);
            __nv_bfloat162 h0, l0, h1, l1;
            split_bf(v00, h0.x, l0.x); split_bf(v01, h0.y, l0.y);
            split_bf(v10, h1.x, l1.x); split_bf(v11, h1.y, l1.y);
            *(__nv_bfloat162*)&g_a2h[o0 + c0] = h0;
            *(__nv_bfloat162*)&g_a2l[o0 + c0] = l0;
            *(__nv_bfloat162*)&g_a2h[o1 + c0] = h1;
            *(__nv_bfloat162*)&g_a2l[o1 + c0] = l1;
        }
    }
}

// ---------- conv3: 8 images/block x 128 co, K=1152 ----------
__global__ __launch_bounds__(512, 2) void conv3_k(const float* __restrict__ bias) {
    extern __shared__ __nv_bfloat16 smem_bf[];
    __nv_bfloat16* base[4] = {smem_bf, smem_bf + 10240, smem_bf + 20480, smem_bf + 30720};
    int tid = threadIdx.x;
    int b0 = blockIdx.x * 8;
    int cob = blockIdx.y * 128;
    int lane = tid & 31, wrp = tid >> 5;
    int g = lane >> 2, t2 = lane & 3;
    int mw = (wrp & 3) * 32, nw = (wrp >> 2) * 32;
    int rA = (lane & 7) + ((lane >> 3) & 1) * 8, kA = (lane >> 4) * 8;
    int nB = (lane >> 4) * 8 + (lane & 7), kB = ((lane >> 3) & 1) * 8;
    float acc[2][4][4];
#pragma unroll
    for (int mt = 0; mt < 2; mt++)
#pragma unroll
        for (int nt = 0; nt < 4; nt++)
#pragma unroll
            for (int i = 0; i < 4; i++) acc[mt][nt][i] = 0.f;

    auto stage = [&](int ch, int buf) {
        int tap = ch >> 2, ci0 = (ch & 3) * 32;
        int kh = tap / 3, kw = tap - kh * 3;
#pragma unroll
        for (int l = 0; l < 4; l++) {
            int gi = tid + 512 * l;
            int arr = gi >> 9;
            int rem = gi & 511;
            int row = rem >> 2, q = rem & 3;
            __nv_bfloat16* dst = base[arr] + buf * 5120 + row * 40 + q * 8;
            if (arr < 2) {
                int img = row >> 4, pos = row & 15;
                int oh = pos >> 2, ow = pos & 3;
                int ih = oh * 2 + kh - 1, iw = ow * 2 + kw - 1;
                int ok = ((unsigned)ih < 8u && (unsigned)iw < 8u) ? 16 : 0;
                size_t si = ok ? ((((size_t)(b0 + img) * 64) + ih * 8 + iw) * 128 + ci0 + q * 8) : 0;
                cpa16z(dst, (arr ? g_a2l : g_a2h) + si, ok);
            } else {
                cpa16(dst, ((arr == 3) ? g_wB3l : g_wB3h)
                           + (size_t)tap * 32768 + (cob + row) * 128 + ci0 + q * 8);
            }
        }
        cpa_commit();
    };

    stage(0, 0);
    for (int ch = 0; ch < 36; ch++) {
        int cb = ch & 1;
        cpa_wait0();
        __syncthreads();
        if (ch + 1 < 36) stage(ch + 1, cb ^ 1);
        HMMA_STEP(cb, 0)
        HMMA_STEP(cb, 1)
    }
    float2 bb[4];
#pragma unroll
    for (int nt = 0; nt < 4; nt++) bb[nt] = *(const float2*)&bias[cob + nw + nt * 8 + t2 * 2];
#pragma unroll
    for (int mt = 0; mt < 2; mt++) {
        int r0 = mw + mt * 16 + g, r1 = r0 + 8;
        size_t o0 = (((size_t)(b0 + (r0 >> 4)) * 16) + (r0 & 15)) * 256 + cob;
        size_t o1 = (((size_t)(b0 + (r1 >> 4)) * 16) + (r1 & 15)) * 256 + cob;
#pragma unroll
        for (int nt = 0; nt < 4; nt++) {
            int c0 = nw + nt * 8 + t2 * 2;
            float v00 = fmaxf(acc[mt][nt][0] + bb[nt].x, 0.f);
            float v01 = fmaxf(acc[mt][nt][1] + bb[nt].y, 0.f);
            float v10 = fmaxf(acc[mt][nt][2] + bb[nt].x, 0.f);
            float v11 = fmaxf(acc[mt][nt][3] + bb[nt].y, 0.f);
            *(float2*)&g_fea[o0 + c0] = make_float2(v00, v01);
            *(float2*)&g_fea[o1 + c0] = make_float2(v10, v11);
            __nv_bfloat162 h0, l0, h1, l1;
            split_bf(v00, h0.x, l0.x); split_bf(v01, h0.y, l0.y);
            split_bf(v10, h1.x, l1.x); split_bf(v11, h1.y, l1.y);
            *(__nv_bfloat162*)&g_feah[o0 + c0] = h0;
            *(__nv_bfloat162*)&g_feal[o0 + c0] = l0;
            *(__nv_bfloat162*)&g_feah[o1 + c0] = h1;
            *(__nv_bfloat162*)&g_feal[o1 + c0] = l1;
        }
    }
}

// ---------- code norms ----------
__global__ void codenorm_k(const float* __restrict__ c0, const float* __restrict__ c1) {
    int c = blockIdx.x * 256 + threadIdx.x;
    const float* cp = (c < 512) ? c0 + (size_t)c * 256 : c1 + (size_t)(c - 512) * 256;
    float s = 0.f;
    for (int k = 0; k < 256; k += 4) {
        float4 v = *(const float4*)&cp[k];
        s += v.x * v.x + v.y * v.y + v.z * v.z + v.w * v.w;
    }
    g_cn[c] = s;
}

// ---------- VQ: 128 rows/block x 128-code tiles, K=256 ----------
__global__ __launch_bounds__(512, 2) void vq_k(const int* __restrict__ idxp) {
    extern __shared__ __nv_bfloat16 smem_bf[];
    __nv_bfloat16* base[4] = {smem_bf, smem_bf + 10240, smem_bf + 20480, smem_bf + 30720};
    int tid = threadIdx.x;
    int rowbase = blockIdx.x * 128;
    int lane = tid & 31, wrp = tid >> 5;
    int g = lane >> 2, t2 = lane & 3;
    int mw = (wrp & 3) * 32, nw = (wrp >> 2) * 32;
    int rA = (lane & 7) + ((lane >> 3) & 1) * 8, kA = (lane >> 4) * 8;
    int nB = (lane >> 4) * 8 + (lane & 7), kB = ((lane >> 3) & 1) * 8;
    int Kc = (idxp[0] == 0) ? 512 : 1024;
    int total = (Kc >> 7) * 8;               // tile = cc>>3, kc = cc&7
    float bv[4]; int bi[4];
#pragma unroll
    for (int i = 0; i < 4; i++) { bv[i] = 1e30f; bi[i] = 0; }
    float acc[2][4][4];
#pragma unroll
    for (int mt = 0; mt < 2; mt++)
#pragma unroll
        for (int nt = 0; nt < 4; nt++)
#pragma unroll
            for (int i = 0; i < 4; i++) acc[mt][nt][i] = 0.f;

    auto stage = [&](int cc, int buf) {
        int tile = cc >> 3, kc = cc & 7;
#pragma unroll
        for (int l = 0; l < 4; l++) {
            int gi = tid + 512 * l;
            int arr = gi >> 9;
            int rem = gi & 511;
            int row = rem >> 2, q = rem & 3;
            __nv_bfloat16* dst = base[arr] + buf * 5120 + row * 40 + q * 8;
            const __nv_bfloat16* src;
            if (arr < 2)
                src = (arr ? g_feal : g_feah) + (size_t)(rowbase + row) * 256 + kc * 32 + q * 8;
            else
                src = ((arr == 3) ? g_cdl : g_cdh) + (size_t)(tile * 128 + row) * 256 + kc * 32 + q * 8;
            cpa16(dst, src);
        }
        cpa_commit();
    };

    stage(0, 0);
    for (int cc = 0; cc < total; cc++) {
        int cb = cc & 1;
        cpa_wait0();
        __syncthreads();
        if (cc + 1 < total) stage(cc + 1, cb ^ 1);
        HMMA_STEP(cb, 0)
        HMMA_STEP(cb, 1)
        if ((cc & 7) == 7) {
            int tile = cc >> 3;
#pragma unroll
            for (int nt = 0; nt < 4; nt++) {
                int c0 = tile * 128 + nw + nt * 8 + t2 * 2;
                float cn0 = g_cn[c0], cn1 = g_cn[c0 + 1];
#pragma unroll
                for (int mt = 0; mt < 2; mt++) {
                    float d00 = cn0 - 2.f * acc[mt][nt][0];
                    float d01 = cn1 - 2.f * acc[mt][nt][1];
                    float d10 = cn0 - 2.f * acc[mt][nt][2];
                    float d11 = cn1 - 2.f * acc[mt][nt][3];
                    int b0i = mt * 2, b1i = mt * 2 + 1;
                    if (d00 < bv[b0i]) { bv[b0i] = d00; bi[b0i] = c0; }
                    if (d01 < bv[b0i]) { bv[b0i] = d01; bi[b0i] = c0 + 1; }
                    if (d10 < bv[b1i]) { bv[b1i] = d10; bi[b1i] = c0; }
                    if (d11 < bv[b1i]) { bv[b1i] = d11; bi[b1i] = c0 + 1; }
                }
            }
#pragma unroll
            for (int mt = 0; mt < 2; mt++)
#pragma unroll
                for (int nt = 0; nt < 4; nt++)
#pragma unroll
                    for (int i = 0; i < 4; i++) acc[mt][nt][i] = 0.f;
        }
    }
    __syncthreads();
    float (*sbv)[16] = (float(*)[16])smem_bf;
    int   (*sbi)[16] = (int(*)[16])(smem_bf + 4096);
    int qidx = (wrp >> 2) * 4 + t2;
#pragma unroll
    for (int mt = 0; mt < 2; mt++) {
        int r0 = mw + mt * 16 + g, r1 = r0 + 8;
        sbv[r0][qidx] = bv[mt * 2];     sbi[r0][qidx] = bi[mt * 2];
        sbv[r1][qidx] = bv[mt * 2 + 1]; sbi[r1][qidx] = bi[mt * 2 + 1];
    }
    __syncthreads();
    if (tid < 128) {
        float v = sbv[tid][0]; int ii = sbi[tid][0];
#pragma unroll
        for (int q = 1; q < 16; q++) {
            float v2 = sbv[tid][q]; int i2 = sbi[tid][q];
            if (v2 < v || (v2 == v && i2 < ii)) { v = v2; ii = i2; }
        }
        g_eidx[rowbase + tid] = ii;
    }
}

// ---------- ptab via HMMA: P[pos] = codes @ fc1w_pos^T ----------
__global__ __launch_bounds__(512, 2) void ptab_k() {
    extern __shared__ __nv_bfloat16 smem_bf[];
    __nv_bfloat16* base[4] = {smem_bf, smem_bf + 10240, smem_bf + 20480, smem_bf + 30720};
    int tid = threadIdx.x;
    int cbb = blockIdx.x * 128;      // code base
    int nbb = blockIdx.y * 128;      // n base (within 512)
    int pos = blockIdx.z;
    int lane = tid & 31, wrp = tid >> 5;
    int g = lane >> 2, t2 = lane & 3;
    int mw = (wrp & 3) * 32, nw = (wrp >> 2) * 32;
    int rA = (lane & 7) + ((lane >> 3) & 1) * 8, kA = (lane >> 4) * 8;
    int nB = (lane >> 4) * 8 + (lane & 7), kB = ((lane >> 3) & 1) * 8;
    float acc[2][4][4];
#pragma unroll
    for (int mt = 0; mt < 2; mt++)
#pragma unroll
        for (int nt = 0; nt < 4; nt++)
#pragma unroll
            for (int i = 0; i < 4; i++) acc[mt][nt][i] = 0.f;

    auto stage = [&](int kc, int buf) {
#pragma unroll
        for (int l = 0; l < 4; l++) {
            int gi = tid + 512 * l;
            int arr = gi >> 9;
            int rem = gi & 511;
            int row = rem >> 2, q = rem & 3;
            __nv_bfloat16* dst = base[arr] + buf * 5120 + row * 40 + q * 8;
            const __nv_bfloat16* src;
            if (arr < 2)
                src = (arr ? g_cdl : g_cdh) + (size_t)(cbb + row) * 256 + kc * 32 + q * 8;
            else
                src = ((arr == 3) ? g_wbl : g_wbh)
                      + ((size_t)pos * 512 + nbb + row) * 256 + kc * 32 + q * 8;
            cpa16(dst, src);
        }
        cpa_commit();
    };

    stage(0, 0);
    for (int kc = 0; kc < 8; kc++) {
        int cb = kc & 1;
        cpa_wait0();
        __syncthreads();
        if (kc + 1 < 8) stage(kc + 1, cb ^ 1);
        HMMA_STEP(cb, 0)
        HMMA_STEP(cb, 1)
    }
#pragma unroll
    for (int mt = 0; mt < 2; mt++) {
        int r0 = mw + mt * 16 + g, r1 = r0 + 8;
        size_t o0 = ((size_t)pos * 1024 + cbb + r0) * 512 + nbb;
        size_t o1 = ((size_t)pos * 1024 + cbb + r1) * 512 + nbb;
#pragma unroll
        for (int nt = 0; nt < 4; nt++) {
            int c0 = nw + nt * 8 + t2 * 2;
            *(float2*)&g_P[o0 + c0] = make_float2(acc[mt][nt][0], acc[mt][nt][1]);
            *(float2*)&g_P[o1 + c0] = make_float2(acc[mt][nt][2], acc[mt][nt][3]);
        }
    }
}

__global__ void zero_hist_k() { g_hist[threadIdx.x] = 0; }

// ---------- loss partials + histogram ----------
__global__ void loss_hist_k(const float* __restrict__ c0, const float* __restrict__ c1) {
    __shared__ float red[256];
    int row = blockIdx.x * 256 + threadIdx.x;
    int e = g_eidx[row];
    atomicAdd(&g_hist[e], 1);
    const float* cp = (e < 512) ? c0 + (size_t)e * 256 : c1 + (size_t)(e - 512) * 256;
    const float* f = g_fea + (size_t)row * 256;
    float s = 0.f;
    for (int k = 0; k < 256; k += 4) {
        float4 q = *(const float4*)&cp[k];
        float4 fv = *(const float4*)&f[k];
        float a = q.x - fv.x, b = q.y - fv.y, c = q.z - fv.z, d = q.w - fv.w;
        s += a * a + b * b + c * c + d * d;
    }
    red[threadIdx.x] = s;
    __syncthreads();
    for (int st = 128; st; st >>= 1) {
        if (threadIdx.x < st) red[threadIdx.x] += red[threadIdx.x + st];
        __syncthreads();
    }
    if (threadIdx.x == 0) g_losspart[blockIdx.x] = red[0];
}

// ---------- h = gelu(sum_pos P + b1) ----------
__global__ __launch_bounds__(512) void hgs_k(const float* __restrict__ fb) {
    __shared__ int se[16];
    int b = blockIdx.x, tid = threadIdx.x;
    if (tid < 16) se[tid] = g_eidx[b * 16 + tid];
    __syncthreads();
    float acc = fb[tid];
#pragma unroll
    for (int p = 0; p < 16; p++) acc += g_P[((size_t)p * 1024 + se[p]) * 512 + tid];
    g_h[(size_t)b * 512 + tid] = gelu_t(acc);
}

// ---------- fc2 ----------
__global__ __launch_bounds__(256) void fc2_k(const float* __restrict__ w,
                                             const float* __restrict__ bias,
                                             float* __restrict__ out) {
    __shared__ float sw[10][512];
    __shared__ float sb[10];
    int tid = threadIdx.x;
    for (int i = tid; i < 5120; i += 256) sw[i >> 9][i & 511] = w[i];
    if (tid < 10) sb[tid] = bias[tid];
    __syncthreads();
    int warp = tid >> 5, lane = tid & 31;
    int bimg = blockIdx.x * 8 + warp;
    const float* hr = g_h + (size_t)bimg * 512;
    float acc[10];
#pragma unroll
    for (int m = 0; m < 10; m++) acc[m] = 0.f;
    for (int k = 0; k < 16; k++) {
        float hv = hr[lane + 32 * k];
#pragma unroll
        for (int m = 0; m < 10; m++) acc[m] = fmaf(hv, sw[m][lane + 32 * k], acc[m]);
    }
#pragma unroll
    for (int off = 16; off; off >>= 1)
#pragma unroll
        for (int m = 0; m < 10; m++) acc[m] += __shfl_xor_sync(0xFFFFFFFFu, acc[m], off);
    if (lane < 10) out[(size_t)bimg * 10 + lane] = acc[lane] + sb[lane];
}

// ---------- loss + perplexity ----------
__global__ void losspp_k(float* __restrict__ dout, int osz) {
    __shared__ float red[256];
    int tid = threadIdx.x;
    red[tid] = g_losspart[tid];
    __syncthreads();
    for (int st = 128; st; st >>= 1) {
        if (tid < st) red[tid] += red[tid + st];
        __syncthreads();
    }
    float loss = 1.25f * red[0] / 16777216.0f;
    __syncthreads();
    float s = 0.f;
    for (int i = tid; i < 1024; i += 256) {
        float p = (float)g_hist[i] / 65536.0f;
        if (p > 0.f) s += p * logf(p + 1e-10f);
    }
    red[tid] = s;
    __syncthreads();
    for (int st = 128; st; st >>= 1) {
        if (tid < st) red[tid] += red[tid + st];
        __syncthreads();
    }
    if (tid == 0) { dout[osz - 2] = loss; dout[osz - 1] = expf(-red[0]); }
}

extern "C" void kernel_launch(void* const* d_in, const int* in_sizes, int n_in,
                              void* d_out, int out_size) {
    const float* x     = (const float*)d_in[0];
    const float* w1    = (const float*)d_in[1];
    const float* b1    = (const float*)d_in[2];
    const float* w2    = (const float*)d_in[3];
    const float* b2    = (const float*)d_in[4];
    const float* w3    = (const float*)d_in[5];
    const float* b3    = (const float*)d_in[6];
    const float* code0 = (const float*)d_in[7];
    const float* code1 = (const float*)d_in[8];
    const float* fc1w  = (const float*)d_in[9];
    const float* fc1b  = (const float*)d_in[10];
    const float* fc2w  = (const float*)d_in[11];
    const float* fc2b  = (const float*)d_in[12];
    const int*   idxp  = (const int*)d_in[13];
    float* out = (float*)d_out;

    cudaFuncSetAttribute(conv2_k, cudaFuncAttributeMaxDynamicSharedMemorySize, 81920);
    cudaFuncSetAttribute(conv3_k, cudaFuncAttributeMaxDynamicSharedMemorySize, 81920);
    cudaFuncSetAttribute(vq_k,    cudaFuncAttributeMaxDynamicSharedMemorySize, 81920);
    cudaFuncSetAttribute(ptab_k,  cudaFuncAttributeMaxDynamicSharedMemorySize, 81920);

    // conv2_k stays at our launch #3 (ncu -s 5 lands there after 2 harness launches).
    conv1_k<<<4096, 256>>>(x, w1, b1);                    // 0
    cvt_w2_k<<<9, 256>>>(w2);                             // 1
    cvt_w3_k<<<9, 256>>>(w3);                             // 2
    conv2_k<<<2048, 512, 81920>>>(b2);                    // 3
    conv3_k<<<dim3(512, 2), 512, 81920>>>(b3);            // 4
    cvt_cd_k<<<1024, 256>>>(code0, code1);                // 5
    codenorm_k<<<4, 256>>>(code0, code1);                 // 6
    vq_k<<<512, 512, 81920>>>(idxp);                      // 7
    zero_hist_k<<<1, 1024>>>();                           // 8
    loss_hist_k<<<256, 256>>>(code0, code1);              // 9
    cvt_wb_k<<<512, 256>>>(fc1w);                         // 10
    ptab_k<<<dim3(8, 4, 16), 512, 81920>>>();             // 11
    hgs_k<<<4096, 512>>>(fc1b);                           // 12
    fc2_k<<<512, 256>>>(fc2w, fc2b, out);                 // 13
    losspp_k<<<1, 256>>>(out, out_size);                  // 14
}